// round 3
// baseline (speedup 1.0000x reference)
#include <cuda_runtime.h>
#include <math.h>

#define NN 131072

// ---------------- scratch (static device arrays; no allocations) ----------------
__device__ __align__(16) float g_edges[NN * 4 * 64];   // stacked edges, rows (n*4+s)
__device__ __align__(16) float g_ao[NN * 4 * 64];      // attention output (pre out-proj)
__device__ __align__(16) float g_attln[NN * 4 * 64];   // post residual+LN
__device__ __align__(16) float g_h1[NN * 128];         // interaction hidden
__device__ __align__(16) float g_ci1[NN * 64];         // ci hidden
__device__ __align__(16) float g_iemb[NN * 64];
__device__ __align__(16) float g_cemb[NN * 64];
__device__ __align__(16) float g_merged[NN * 64];

__device__ __forceinline__ float gelu_f(float x) {
    return 0.5f * x * (1.0f + erff(x * 0.70710678118654752f));
}

// source / residual / destination selectors for the generic linear kernel
#define SRC_AO    0
#define SRC_H1    1
#define SRC_CI1   2
#define SRC_MERGE 3
#define RES_NONE  -1
#define RES_EDGES 0
#define DST_ATTLN 0
#define DST_IEMB  1
#define DST_CEMB  2
#define DST_MERGED 3

__device__ __forceinline__ float loadA(int id, int row, int col) {
    switch (id) {
        case SRC_AO:  return g_ao[row * 64 + col];
        case SRC_H1:  return g_h1[row * 128 + col];
        case SRC_CI1: return g_ci1[row * 64 + col];
        default: {  // SRC_MERGE: [pooled(64) | iemb(64) | cemb(64)]
            if (col < 64) {
                int b = row * 256 + col;
                return 0.25f * (g_attln[b] + g_attln[b + 64] + g_attln[b + 128] + g_attln[b + 192]);
            } else if (col < 128) {
                return g_iemb[row * 64 + (col - 64)];
            } else {
                return g_cemb[row * 64 + (col - 128)];
            }
        }
    }
}

__device__ __forceinline__ float* dstPtr(int id) {
    switch (id) {
        case DST_ATTLN: return g_attln;
        case DST_IEMB:  return g_iemb;
        case DST_CEMB:  return g_cemb;
        default:        return g_merged;
    }
}

// =====================================================================
// Kernel 1: QKV GEMM (8 nodes = 32 rows; W in three 64-col chunks)
//           + fused per-node attention core -> g_ao, also writes g_edges
// static smem: sW 64*65 | sA 32*65 (edges, reused for V) | sQK 32*129 | sb 192
// =====================================================================
__global__ void k_qkv_attn(const float* __restrict__ evx, const float* __restrict__ evy,
                           const float* __restrict__ exv, const float* __restrict__ eyv,
                           const float* __restrict__ Win, const float* __restrict__ bin)
{
    __shared__ float sW[64 * 65];
    __shared__ float sA[32 * 65];     // edge rows (stride 65); later reused for V output
    __shared__ float sQK[32 * 129];   // Q cols 0..63, K cols 64..127 (stride 129)
    __shared__ float sb[192];

    const int tid = threadIdx.x;
    const int node0 = blockIdx.x * 8;

    if (tid < 192) sb[tid] = bin[tid];
    for (int i = tid; i < 32 * 64; i += 256) {
        int r = i >> 6, k = i & 63;
        int node = node0 + (r >> 2), s = r & 3;
        const float* base = (s == 0) ? evx : (s == 1) ? evy : (s == 2) ? exv : eyv;
        float v = base[node * 64 + k];
        sA[r * 65 + k] = v;
        g_edges[(node0 * 4 + r) * 64 + k] = v;
    }

    const int ty = tid >> 5, tx = tid & 31;
    const int r0 = ty * 4;
    float acc[4][2];

    for (int wc = 0; wc < 3; wc++) {
        __syncthreads();   // sA ready (wc=0) / prev-iter reads of sW complete
        for (int i = tid; i < 64 * 64; i += 256) {
            int c = i >> 6, k = i & 63;
            sW[c * 65 + k] = Win[(wc * 64 + c) * 64 + k];
        }
        __syncthreads();

#pragma unroll
        for (int j = 0; j < 4; j++) { acc[j][0] = 0.0f; acc[j][1] = 0.0f; }
#pragma unroll 8
        for (int k = 0; k < 64; k++) {
            float a0 = sA[(r0 + 0) * 65 + k];
            float a1 = sA[(r0 + 1) * 65 + k];
            float a2 = sA[(r0 + 2) * 65 + k];
            float a3 = sA[(r0 + 3) * 65 + k];
            float w0 = sW[tx * 65 + k];
            float w1 = sW[(tx + 32) * 65 + k];
            acc[0][0] += a0 * w0; acc[0][1] += a0 * w1;
            acc[1][0] += a1 * w0; acc[1][1] += a1 * w1;
            acc[2][0] += a2 * w0; acc[2][1] += a2 * w1;
            acc[3][0] += a3 * w0; acc[3][1] += a3 * w1;
        }
        if (wc < 2) {
#pragma unroll
            for (int j = 0; j < 4; j++) {
                sQK[(r0 + j) * 129 + wc * 64 + tx]      = acc[j][0] + sb[wc * 64 + tx];
                sQK[(r0 + j) * 129 + wc * 64 + tx + 32] = acc[j][1] + sb[wc * 64 + tx + 32];
            }
        }
    }

    __syncthreads();   // all V-GEMM reads of sA complete
#pragma unroll
    for (int j = 0; j < 4; j++) {        // V output into sA (stride 65)
        sA[(r0 + j) * 65 + tx]      = acc[j][0] + sb[128 + tx];
        sA[(r0 + j) * 65 + tx + 32] = acc[j][1] + sb[128 + tx + 32];
    }
    __syncthreads();

    // attention core: warp ty handles node (node0+ty); lanes 0..15 = (head h, query qs)
    if (tx < 16) {
        int h = tx >> 2, qs = tx & 3;
        const float* qrow = &sQK[(ty * 4 + qs) * 129 + h * 16];
        float sc[4];
#pragma unroll
        for (int ks = 0; ks < 4; ks++) {
            const float* krow = &sQK[(ty * 4 + ks) * 129 + 64 + h * 16];
            float d = 0.0f;
#pragma unroll
            for (int e = 0; e < 16; e++) d += qrow[e] * krow[e];
            sc[ks] = d * 0.25f;   // 1/sqrt(16)
        }
        float m = fmaxf(fmaxf(sc[0], sc[1]), fmaxf(sc[2], sc[3]));
        float ssum = 0.0f;
#pragma unroll
        for (int ks = 0; ks < 4; ks++) { sc[ks] = expf(sc[ks] - m); ssum += sc[ks]; }
        float inv = 1.0f / ssum;

        int obase = ((node0 + ty) * 4 + qs) * 64 + h * 16;
#pragma unroll
        for (int e = 0; e < 16; e++) {
            float o = 0.0f;
#pragma unroll
            for (int ks = 0; ks < 4; ks++)
                o += sc[ks] * sA[(ty * 4 + ks) * 65 + h * 16 + e];
            g_ao[obase + e] = o * inv;
        }
    }
}

// =====================================================================
// Generic: dst(M,64) = LN( A(M,K) @ W(64,K)^T + b (+ res) ) * gamma + beta, opt GELU
// 64 rows per block, 256 threads, thread tile 4x4, K in 64-chunks
// =====================================================================
__global__ void k_lin64_ln(int srcId, int K,
                           const float* __restrict__ W, const float* __restrict__ b,
                           int resId,
                           const float* __restrict__ gamma, const float* __restrict__ beta,
                           int dstId, int doGelu)
{
    __shared__ float sA[64 * 65];
    __shared__ float sW[64 * 65];
    const int tid = threadIdx.x;
    const int row0 = blockIdx.x * 64;
    const int rty = tid >> 4, rtx = tid & 15;

    float acc[4][4];
#pragma unroll
    for (int j = 0; j < 4; j++)
#pragma unroll
        for (int i = 0; i < 4; i++) acc[j][i] = 0.0f;

    for (int kc = 0; kc < K; kc += 64) {
        __syncthreads();
        for (int i = tid; i < 64 * 64; i += 256) {
            int r = i >> 6, k = i & 63;
            sA[r * 65 + k] = loadA(srcId, row0 + r, kc + k);
            sW[r * 65 + k] = W[r * K + kc + k];   // r = output channel
        }
        __syncthreads();
#pragma unroll 8
        for (int k = 0; k < 64; k++) {
            float a[4], w[4];
#pragma unroll
            for (int j = 0; j < 4; j++) a[j] = sA[(rty * 4 + j) * 65 + k];
#pragma unroll
            for (int i = 0; i < 4; i++) w[i] = sW[(rtx + 16 * i) * 65 + k];
#pragma unroll
            for (int j = 0; j < 4; j++)
#pragma unroll
                for (int i = 0; i < 4; i++) acc[j][i] += a[j] * w[i];
        }
    }
    __syncthreads();

    // C (+bias, +residual) back into sA
#pragma unroll
    for (int j = 0; j < 4; j++)
#pragma unroll
        for (int i = 0; i < 4; i++) {
            int r = rty * 4 + j, c = rtx + 16 * i;
            float v = acc[j][i] + b[c];
            if (resId == RES_EDGES) v += g_edges[(row0 + r) * 64 + c];
            sA[r * 65 + c] = v;
        }
    __syncthreads();

    // LayerNorm per row: warp handles 8 rows, 4 lanes per row
    float* out = dstPtr(dstId);
    const int wid = tid >> 5, lane = tid & 31;
    const int row = wid * 8 + (lane >> 2), part = lane & 3;
    float x[16];
    float s = 0.0f, ss = 0.0f;
#pragma unroll
    for (int e = 0; e < 16; e++) {
        x[e] = sA[row * 65 + part * 16 + e];
        s += x[e]; ss += x[e] * x[e];
    }
    s += __shfl_xor_sync(0xffffffffu, s, 1, 4);
    s += __shfl_xor_sync(0xffffffffu, s, 2, 4);
    ss += __shfl_xor_sync(0xffffffffu, ss, 1, 4);
    ss += __shfl_xor_sync(0xffffffffu, ss, 2, 4);
    float mean = s * (1.0f / 64.0f);
    float var = ss * (1.0f / 64.0f) - mean * mean;
    float rstd = rsqrtf(var + 1e-5f);
#pragma unroll
    for (int e = 0; e < 16; e++) {
        int c = part * 16 + e;
        float y = (x[e] - mean) * rstd * gamma[c] + beta[c];
        if (doGelu) y = gelu_f(y);
        out[(row0 + row) * 64 + c] = y;
    }
}

// =====================================================================
// Interaction GEMM: g_h1(N,128) = GELU( inter(N,384) @ Wi1^T + bi1 )
// 64 rows x 64 cols per block (gridDim.y selects col half); K = 6 chunks of 64
// built on the fly from pairwise edge products. static smem 33.3KB
// =====================================================================
__global__ void k_inter(const float* __restrict__ evx, const float* __restrict__ evy,
                        const float* __restrict__ exv, const float* __restrict__ eyv,
                        const float* __restrict__ Wi1, const float* __restrict__ bi1)
{
    __shared__ float sA[64 * 65];
    __shared__ float sW[64 * 65];
    const int tid = threadIdx.x;
    const int n0 = blockIdx.x * 64;
    const int c0 = blockIdx.y * 64;
    const int rty = tid >> 4, rtx = tid & 15;

    float acc[4][4];
#pragma unroll
    for (int j = 0; j < 4; j++)
#pragma unroll
        for (int i = 0; i < 4; i++) acc[j][i] = 0.0f;

#pragma unroll 1
    for (int p = 0; p < 6; p++) {
        const float* Ea; const float* Eb;
        switch (p) {
            case 0: Ea = evx; Eb = evy; break;
            case 1: Ea = evx; Eb = exv; break;
            case 2: Ea = evx; Eb = eyv; break;
            case 3: Ea = evy; Eb = exv; break;
            case 4: Ea = evy; Eb = eyv; break;
            default: Ea = exv; Eb = eyv; break;
        }
        __syncthreads();
        for (int i = tid; i < 64 * 64; i += 256) {
            int r = i >> 6, k = i & 63;
            int g = (n0 + r) * 64 + k;
            sA[r * 65 + k] = Ea[g] * Eb[g];
        }
        for (int i = tid; i < 64 * 64; i += 256) {
            int c = i >> 6, k = i & 63;
            sW[c * 65 + k] = Wi1[(c0 + c) * 384 + p * 64 + k];
        }
        __syncthreads();
#pragma unroll 8
        for (int k = 0; k < 64; k++) {
            float a[4], w[4];
#pragma unroll
            for (int j = 0; j < 4; j++) a[j] = sA[(rty * 4 + j) * 65 + k];
#pragma unroll
            for (int i = 0; i < 4; i++) w[i] = sW[(rtx + 16 * i) * 65 + k];
#pragma unroll
            for (int j = 0; j < 4; j++)
#pragma unroll
                for (int i = 0; i < 4; i++) acc[j][i] += a[j] * w[i];
        }
    }
#pragma unroll
    for (int j = 0; j < 4; j++)
#pragma unroll
        for (int i = 0; i < 4; i++) {
            int r = rty * 4 + j, c = rtx + 16 * i;
            g_h1[(n0 + r) * 128 + c0 + c] = gelu_f(acc[j][i] + bi1[c0 + c]);
        }
}

// =====================================================================
// ci stage 1: g_ci1(N,64) = GELU( ci(N,10) @ Wc1^T + bc1 ), 16 nodes/block
// =====================================================================
__global__ void k_ci1(const float* __restrict__ ci, const float* __restrict__ Wc1,
                      const float* __restrict__ bc1)
{
    __shared__ float sW[64 * 10];
    __shared__ float sC[16 * 10];
    const int tid = threadIdx.x;
    const int n0 = blockIdx.x * 16;
    for (int i = tid; i < 640; i += 256) sW[i] = Wc1[i];      // FIXED: was if(tid<640)
    if (tid < 160) sC[tid] = ci[n0 * 10 + tid];
    __syncthreads();
    for (int o = tid; o < 1024; o += 256) {
        int nl = o >> 6, c = o & 63;
        float a = bc1[c];
#pragma unroll
        for (int k = 0; k < 10; k++) a += sC[nl * 10 + k] * sW[c * 10 + k];
        g_ci1[(n0 + nl) * 64 + c] = gelu_f(a);
    }
}

// =====================================================================
// classifier: out(N,8) = GELU(merged @ Wk1^T + bk1) @ Wk2^T + bk2 ; 64 nodes/block
// =====================================================================
__global__ void k_cls(const float* __restrict__ Wk1, const float* __restrict__ bk1,
                      const float* __restrict__ Wk2, const float* __restrict__ bk2,
                      float* __restrict__ out)
{
    __shared__ float sA[64 * 65];
    __shared__ float sW[64 * 65];
    __shared__ float sW2[8 * 65];
    const int tid = threadIdx.x;
    const int n0 = blockIdx.x * 64;
    const int rty = tid >> 4, rtx = tid & 15;

    for (int i = tid; i < 64 * 64; i += 256) {
        int r = i >> 6, k = i & 63;
        sA[r * 65 + k] = g_merged[(n0 + r) * 64 + k];
        sW[r * 65 + k] = Wk1[i];
    }
    for (int i = tid; i < 512; i += 256) {                    // FIXED: was if(tid<512)
        int c = i >> 6, k = i & 63;
        sW2[c * 65 + k] = Wk2[i];
    }
    __syncthreads();

    float acc[4][4];
#pragma unroll
    for (int j = 0; j < 4; j++)
#pragma unroll
        for (int i = 0; i < 4; i++) acc[j][i] = 0.0f;
#pragma unroll 8
    for (int k = 0; k < 64; k++) {
        float a[4], w[4];
#pragma unroll
        for (int j = 0; j < 4; j++) a[j] = sA[(rty * 4 + j) * 65 + k];
#pragma unroll
        for (int i = 0; i < 4; i++) w[i] = sW[(rtx + 16 * i) * 65 + k];
#pragma unroll
        for (int j = 0; j < 4; j++)
#pragma unroll
            for (int i = 0; i < 4; i++) acc[j][i] += a[j] * w[i];
    }
    __syncthreads();
#pragma unroll
    for (int j = 0; j < 4; j++)
#pragma unroll
        for (int i = 0; i < 4; i++) {
            int r = rty * 4 + j, c = rtx + 16 * i;
            sA[r * 65 + c] = gelu_f(acc[j][i] + bk1[c]);
        }
    __syncthreads();

    // stage 2: 64x8 out, 2 outputs per thread
    int r = tid & 63, oc0 = (tid >> 6) * 2;
    float o0 = bk2[oc0], o1 = bk2[oc0 + 1];
#pragma unroll 8
    for (int k = 0; k < 64; k++) {
        float h = sA[r * 65 + k];
        o0 += h * sW2[oc0 * 65 + k];
        o1 += h * sW2[(oc0 + 1) * 65 + k];
    }
    out[(n0 + r) * 8 + oc0] = o0;
    out[(n0 + r) * 8 + oc0 + 1] = o1;
}

// =====================================================================
extern "C" void kernel_launch(void* const* d_in, const int* in_sizes, int n_in,
                              void* d_out, int out_size)
{
    const float* evx  = (const float*)d_in[0];
    const float* evy  = (const float*)d_in[1];
    const float* exv  = (const float*)d_in[2];
    const float* eyv  = (const float*)d_in[3];
    const float* cif  = (const float*)d_in[4];
    const float* W_in = (const float*)d_in[5];
    const float* b_in = (const float*)d_in[6];
    const float* W_out= (const float*)d_in[7];
    const float* b_out= (const float*)d_in[8];
    const float* g_at = (const float*)d_in[9];
    const float* b_at = (const float*)d_in[10];
    const float* Wi1  = (const float*)d_in[11];
    const float* bi1  = (const float*)d_in[12];
    const float* Wi2  = (const float*)d_in[13];
    const float* bi2  = (const float*)d_in[14];
    const float* gi   = (const float*)d_in[15];
    const float* bni  = (const float*)d_in[16];
    const float* Wc1  = (const float*)d_in[17];
    const float* bc1  = (const float*)d_in[18];
    const float* Wc2  = (const float*)d_in[19];
    const float* bc2  = (const float*)d_in[20];
    const float* gc   = (const float*)d_in[21];
    const float* bnc  = (const float*)d_in[22];
    const float* Wm   = (const float*)d_in[23];
    const float* bm   = (const float*)d_in[24];
    const float* gm   = (const float*)d_in[25];
    const float* bnm  = (const float*)d_in[26];
    const float* Wk1  = (const float*)d_in[27];
    const float* bk1  = (const float*)d_in[28];
    const float* Wk2  = (const float*)d_in[29];
    const float* bk2  = (const float*)d_in[30];
    float* out = (float*)d_out;

    // 1) QKV + attention core (writes g_edges, g_ao)
    k_qkv_attn<<<NN / 8, 256>>>(evx, evy, exv, eyv, W_in, b_in);
    // 2) out-proj + residual + LN -> g_attln   (M = 4N)
    k_lin64_ln<<<(NN * 4) / 64, 256>>>(SRC_AO, 64, W_out, b_out, RES_EDGES,
                                       g_at, b_at, DST_ATTLN, 0);
    // 3) interaction hidden -> g_h1
    k_inter<<<dim3(NN / 64, 2), 256>>>(evx, evy, exv, eyv, Wi1, bi1);
    // 4) Wi2 + LN -> g_iemb
    k_lin64_ln<<<NN / 64, 256>>>(SRC_H1, 128, Wi2, bi2, RES_NONE,
                                 gi, bni, DST_IEMB, 0);
    // 5) ci stage1 -> g_ci1
    k_ci1<<<NN / 16, 256>>>(cif, Wc1, bc1);
    // 6) Wc2 + LN -> g_cemb
    k_lin64_ln<<<NN / 64, 256>>>(SRC_CI1, 64, Wc2, bc2, RES_NONE,
                                 gc, bnc, DST_CEMB, 0);
    // 7) merge linear (A gathered on the fly) + LN + GELU -> g_merged
    k_lin64_ln<<<NN / 64, 256>>>(SRC_MERGE, 192, Wm, bm, RES_NONE,
                                 gm, bnm, DST_MERGED, 1);
    // 8) classifier -> out
    k_cls<<<NN / 64, 256>>>(Wk1, bk1, Wk2, bk2, out);

    (void)in_sizes; (void)n_in; (void)out_size;
}

// round 5
// speedup vs baseline: 1.0253x; 1.0253x over previous
#include <cuda_runtime.h>
#include <math.h>

#define NN 131072
#define SD 68          // smem row stride (floats) for 64-wide tiles; 17 float4
#define SD4 17
#define SQ 132         // smem row stride for 128-wide QK tile; 33 float4

// ---------------- scratch (static device arrays; no allocations) ----------------
__device__ __align__(16) float g_edges[NN * 4 * 64];   // stacked edges, rows (n*4+s)
__device__ __align__(16) float g_ao[NN * 4 * 64];      // attention output (pre out-proj)
__device__ __align__(16) float g_attln[NN * 4 * 64];   // post residual+LN
__device__ __align__(16) float g_h1[NN * 128];         // interaction hidden
__device__ __align__(16) float g_ci1[NN * 64];         // ci hidden
__device__ __align__(16) float g_iemb[NN * 64];
__device__ __align__(16) float g_cemb[NN * 64];
__device__ __align__(16) float g_merged[NN * 64];

__device__ __forceinline__ float gelu_f(float x) {
    return 0.5f * x * (1.0f + erff(x * 0.70710678118654752f));
}

__device__ __forceinline__ void fma4(float& acc, float4 a, float4 b) {
    acc = fmaf(a.x, b.x, acc);
    acc = fmaf(a.y, b.y, acc);
    acc = fmaf(a.z, b.z, acc);
    acc = fmaf(a.w, b.w, acc);
}

#define SRC_AO    0
#define SRC_H1    1
#define SRC_CI1   2
#define SRC_MERGE 3
#define RES_NONE  -1
#define RES_EDGES 0
#define DST_ATTLN 0
#define DST_IEMB  1
#define DST_CEMB  2
#define DST_MERGED 3

__device__ __forceinline__ float loadA(int id, int row, int col) {
    switch (id) {
        case SRC_AO:  return g_ao[row * 64 + col];
        case SRC_H1:  return g_h1[row * 128 + col];
        case SRC_CI1: return g_ci1[row * 64 + col];
        default: {  // SRC_MERGE: [pooled(64) | iemb(64) | cemb(64)]
            if (col < 64) {
                int b = row * 256 + col;
                return 0.25f * (g_attln[b] + g_attln[b + 64] + g_attln[b + 128] + g_attln[b + 192]);
            } else if (col < 128) {
                return g_iemb[row * 64 + (col - 64)];
            } else {
                return g_cemb[row * 64 + (col - 128)];
            }
        }
    }
}

__device__ __forceinline__ float* dstPtr(int id) {
    switch (id) {
        case DST_ATTLN: return g_attln;
        case DST_IEMB:  return g_iemb;
        case DST_CEMB:  return g_cemb;
        default:        return g_merged;
    }
}

// =====================================================================
// Kernel 1: QKV GEMM (8 nodes = 32 rows; W in three 64-col chunks)
//           + fused per-node attention core -> g_ao, also writes g_edges
// =====================================================================
__global__ void k_qkv_attn(const float* __restrict__ evx, const float* __restrict__ evy,
                           const float* __restrict__ exv, const float* __restrict__ eyv,
                           const float* __restrict__ Win, const float* __restrict__ bin)
{
    __shared__ __align__(16) float sW[64 * SD];
    __shared__ __align__(16) float sA[32 * SD];    // edge rows; later reused for V output
    __shared__ __align__(16) float sQK[32 * SQ];   // Q cols 0..63, K cols 64..127
    __shared__ float sb[192];

    const int tid = threadIdx.x;
    const int node0 = blockIdx.x * 8;

    if (tid < 192) sb[tid] = bin[tid];
    for (int i4 = tid; i4 < 32 * 16; i4 += 256) {
        int r = i4 >> 4, kq = i4 & 15;
        int node = node0 + (r >> 2), s = r & 3;
        const float* base = (s == 0) ? evx : (s == 1) ? evy : (s == 2) ? exv : eyv;
        float4 v = ((const float4*)(base + node * 64))[kq];
        ((float4*)(sA + r * SD))[kq] = v;
        ((float4*)(g_edges + (node0 * 4 + r) * 64))[kq] = v;
    }

    const int ty = tid >> 5, tx = tid & 31;
    const int r0 = ty * 4;
    float acc[4][2];
    const float4* sA4 = (const float4*)sA;
    const float4* sW4 = (const float4*)sW;

    for (int wc = 0; wc < 3; wc++) {
        __syncthreads();   // sA ready (wc=0) / prev-iter reads of sW complete
        for (int i4 = tid; i4 < 64 * 16; i4 += 256) {
            int c = i4 >> 4, kq = i4 & 15;
            ((float4*)(sW + c * SD))[kq] = ((const float4*)(Win + (wc * 64 + c) * 64))[kq];
        }
        __syncthreads();

#pragma unroll
        for (int j = 0; j < 4; j++) { acc[j][0] = 0.0f; acc[j][1] = 0.0f; }
#pragma unroll 4
        for (int k4 = 0; k4 < 16; k4++) {
            float4 a0 = sA4[(r0 + 0) * SD4 + k4];
            float4 a1 = sA4[(r0 + 1) * SD4 + k4];
            float4 a2 = sA4[(r0 + 2) * SD4 + k4];
            float4 a3 = sA4[(r0 + 3) * SD4 + k4];
            float4 w0 = sW4[tx * SD4 + k4];
            float4 w1 = sW4[(tx + 32) * SD4 + k4];
            fma4(acc[0][0], a0, w0); fma4(acc[0][1], a0, w1);
            fma4(acc[1][0], a1, w0); fma4(acc[1][1], a1, w1);
            fma4(acc[2][0], a2, w0); fma4(acc[2][1], a2, w1);
            fma4(acc[3][0], a3, w0); fma4(acc[3][1], a3, w1);
        }
        if (wc < 2) {
#pragma unroll
            for (int j = 0; j < 4; j++) {
                sQK[(r0 + j) * SQ + wc * 64 + tx]      = acc[j][0] + sb[wc * 64 + tx];
                sQK[(r0 + j) * SQ + wc * 64 + tx + 32] = acc[j][1] + sb[wc * 64 + tx + 32];
            }
        }
    }

    __syncthreads();   // all V-GEMM reads of sA complete
#pragma unroll
    for (int j = 0; j < 4; j++) {        // V output into sA
        sA[(r0 + j) * SD + tx]      = acc[j][0] + sb[128 + tx];
        sA[(r0 + j) * SD + tx + 32] = acc[j][1] + sb[128 + tx + 32];
    }
    __syncthreads();

    // attention core: warp ty handles node (node0+ty); lanes 0..15 = (head h, query qs)
    if (tx < 16) {
        int h = tx >> 2, qs = tx & 3;
        const float* qrow = &sQK[(ty * 4 + qs) * SQ + h * 16];
        float sc[4];
#pragma unroll
        for (int ks = 0; ks < 4; ks++) {
            const float* krow = &sQK[(ty * 4 + ks) * SQ + 64 + h * 16];
            float d = 0.0f;
#pragma unroll
            for (int e = 0; e < 16; e++) d += qrow[e] * krow[e];
            sc[ks] = d * 0.25f;   // 1/sqrt(16)
        }
        float m = fmaxf(fmaxf(sc[0], sc[1]), fmaxf(sc[2], sc[3]));
        float ssum = 0.0f;
#pragma unroll
        for (int ks = 0; ks < 4; ks++) { sc[ks] = expf(sc[ks] - m); ssum += sc[ks]; }
        float inv = 1.0f / ssum;

        int obase = ((node0 + ty) * 4 + qs) * 64 + h * 16;
#pragma unroll
        for (int e = 0; e < 16; e++) {
            float o = 0.0f;
#pragma unroll
            for (int ks = 0; ks < 4; ks++)
                o += sc[ks] * sA[(ty * 4 + ks) * SD + h * 16 + e];
            g_ao[obase + e] = o * inv;
        }
    }
}

// =====================================================================
// Generic: dst(M,64) = LN( A(M,K) @ W(64,K)^T + b (+ res) ) * gamma + beta, opt GELU
// 64 rows per block, 256 threads, thread tile 4x4, K in 64-chunks (vectorized)
// =====================================================================
__global__ void k_lin64_ln(int srcId, int K,
                           const float* __restrict__ W, const float* __restrict__ b,
                           int resId,
                           const float* __restrict__ gamma, const float* __restrict__ beta,
                           int dstId, int doGelu)
{
    __shared__ __align__(16) float sA[64 * SD];
    __shared__ __align__(16) float sW[64 * SD];
    const int tid = threadIdx.x;
    const int row0 = blockIdx.x * 64;
    const int rty = tid >> 4, rtx = tid & 15;
    const float4* sA4 = (const float4*)sA;
    const float4* sW4 = (const float4*)sW;

    float acc[4][4];
#pragma unroll
    for (int j = 0; j < 4; j++)
#pragma unroll
        for (int i = 0; i < 4; i++) acc[j][i] = 0.0f;

    for (int kc = 0; kc < K; kc += 64) {
        __syncthreads();
        for (int i = tid; i < 64 * 64; i += 256) {
            int r = i >> 6, k = i & 63;
            sA[r * SD + k] = loadA(srcId, row0 + r, kc + k);
        }
        for (int i4 = tid; i4 < 64 * 16; i4 += 256) {
            int r = i4 >> 4, kq = i4 & 15;
            ((float4*)(sW + r * SD))[kq] = ((const float4*)(W + r * K + kc))[kq];
        }
        __syncthreads();
#pragma unroll 4
        for (int k4 = 0; k4 < 16; k4++) {
            float4 a[4], w[4];
#pragma unroll
            for (int j = 0; j < 4; j++) a[j] = sA4[(rty * 4 + j) * SD4 + k4];
#pragma unroll
            for (int i = 0; i < 4; i++) w[i] = sW4[(rtx + 16 * i) * SD4 + k4];
#pragma unroll
            for (int j = 0; j < 4; j++)
#pragma unroll
                for (int i = 0; i < 4; i++) fma4(acc[j][i], a[j], w[i]);
        }
    }
    __syncthreads();

    // C (+bias, +residual) back into sA
#pragma unroll
    for (int j = 0; j < 4; j++)
#pragma unroll
        for (int i = 0; i < 4; i++) {
            int r = rty * 4 + j, c = rtx + 16 * i;
            float v = acc[j][i] + b[c];
            if (resId == RES_EDGES) v += g_edges[(row0 + r) * 64 + c];
            sA[r * SD + c] = v;
        }
    __syncthreads();

    // LayerNorm per row: warp handles 8 rows, 4 lanes per row
    float* out = dstPtr(dstId);
    const int wid = tid >> 5, lane = tid & 31;
    const int row = wid * 8 + (lane >> 2), part = lane & 3;
    float x[16];
    float s = 0.0f, ss = 0.0f;
#pragma unroll
    for (int e = 0; e < 16; e++) {
        x[e] = sA[row * SD + part * 16 + e];
        s += x[e]; ss += x[e] * x[e];
    }
    s += __shfl_xor_sync(0xffffffffu, s, 1, 4);
    s += __shfl_xor_sync(0xffffffffu, s, 2, 4);
    ss += __shfl_xor_sync(0xffffffffu, ss, 1, 4);
    ss += __shfl_xor_sync(0xffffffffu, ss, 2, 4);
    float mean = s * (1.0f / 64.0f);
    float var = ss * (1.0f / 64.0f) - mean * mean;
    float rstd = rsqrtf(var + 1e-5f);
#pragma unroll
    for (int e = 0; e < 16; e++) {
        int c = part * 16 + e;
        float y = (x[e] - mean) * rstd * gamma[c] + beta[c];
        if (doGelu) y = gelu_f(y);
        out[(row0 + row) * 64 + c] = y;
    }
}

// =====================================================================
// Interaction GEMM: g_h1(N,128) = GELU( inter(N,384) @ Wi1^T + bi1 )
// 64 rows x 64 cols per block (gridDim.y selects col half); K = 6 chunks of 64
// =====================================================================
__global__ void k_inter(const float* __restrict__ evx, const float* __restrict__ evy,
                        const float* __restrict__ exv, const float* __restrict__ eyv,
                        const float* __restrict__ Wi1, const float* __restrict__ bi1)
{
    __shared__ __align__(16) float sA[64 * SD];
    __shared__ __align__(16) float sW[64 * SD];
    const int tid = threadIdx.x;
    const int n0 = blockIdx.x * 64;
    const int c0 = blockIdx.y * 64;
    const int rty = tid >> 4, rtx = tid & 15;
    const float4* sA4 = (const float4*)sA;
    const float4* sW4 = (const float4*)sW;

    float acc[4][4];
#pragma unroll
    for (int j = 0; j < 4; j++)
#pragma unroll
        for (int i = 0; i < 4; i++) acc[j][i] = 0.0f;

#pragma unroll 1
    for (int p = 0; p < 6; p++) {
        const float* Ea; const float* Eb;
        switch (p) {
            case 0: Ea = evx; Eb = evy; break;
            case 1: Ea = evx; Eb = exv; break;
            case 2: Ea = evx; Eb = eyv; break;
            case 3: Ea = evy; Eb = exv; break;
            case 4: Ea = evy; Eb = eyv; break;
            default: Ea = exv; Eb = eyv; break;
        }
        __syncthreads();
        for (int i4 = tid; i4 < 64 * 16; i4 += 256) {
            int r = i4 >> 4, kq = i4 & 15;
            float4 x = ((const float4*)(Ea + (n0 + r) * 64))[kq];
            float4 y = ((const float4*)(Eb + (n0 + r) * 64))[kq];
            float4 v; v.x = x.x * y.x; v.y = x.y * y.y; v.z = x.z * y.z; v.w = x.w * y.w;
            ((float4*)(sA + r * SD))[kq] = v;
        }
        for (int i4 = tid; i4 < 64 * 16; i4 += 256) {
            int c = i4 >> 4, kq = i4 & 15;
            ((float4*)(sW + c * SD))[kq] = ((const float4*)(Wi1 + (c0 + c) * 384 + p * 64))[kq];
        }
        __syncthreads();
#pragma unroll 4
        for (int k4 = 0; k4 < 16; k4++) {
            float4 a[4], w[4];
#pragma unroll
            for (int j = 0; j < 4; j++) a[j] = sA4[(rty * 4 + j) * SD4 + k4];
#pragma unroll
            for (int i = 0; i < 4; i++) w[i] = sW4[(rtx + 16 * i) * SD4 + k4];
#pragma unroll
            for (int j = 0; j < 4; j++)
#pragma unroll
                for (int i = 0; i < 4; i++) fma4(acc[j][i], a[j], w[i]);
        }
    }
#pragma unroll
    for (int j = 0; j < 4; j++)
#pragma unroll
        for (int i = 0; i < 4; i++) {
            int r = rty * 4 + j, c = rtx + 16 * i;
            g_h1[(n0 + r) * 128 + c0 + c] = gelu_f(acc[j][i] + bi1[c0 + c]);
        }
}

// =====================================================================
// ci stage 1: g_ci1(N,64) = GELU( ci(N,10) @ Wc1^T + bc1 ), 16 nodes/block
// =====================================================================
__global__ void k_ci1(const float* __restrict__ ci, const float* __restrict__ Wc1,
                      const float* __restrict__ bc1)
{
    __shared__ float sW[64 * 10];
    __shared__ float sC[16 * 10];
    const int tid = threadIdx.x;
    const int n0 = blockIdx.x * 16;
    for (int i = tid; i < 640; i += 256) sW[i] = Wc1[i];
    if (tid < 160) sC[tid] = ci[n0 * 10 + tid];
    __syncthreads();
    for (int o = tid; o < 1024; o += 256) {
        int nl = o >> 6, c = o & 63;
        float a = bc1[c];
#pragma unroll
        for (int k = 0; k < 10; k++) a += sC[nl * 10 + k] * sW[c * 10 + k];
        g_ci1[(n0 + nl) * 64 + c] = gelu_f(a);
    }
}

// =====================================================================
// classifier: out(N,8) = GELU(merged @ Wk1^T + bk1) @ Wk2^T + bk2 ; 64 nodes/block
// =====================================================================
__global__ void k_cls(const float* __restrict__ Wk1, const float* __restrict__ bk1,
                      const float* __restrict__ Wk2, const float* __restrict__ bk2,
                      float* __restrict__ out)
{
    __shared__ __align__(16) float sA[64 * SD];
    __shared__ __align__(16) float sW[64 * SD];
    __shared__ float sW2[8 * 65];
    const int tid = threadIdx.x;
    const int n0 = blockIdx.x * 64;
    const int rty = tid >> 4, rtx = tid & 15;
    const float4* sA4 = (const float4*)sA;
    const float4* sW4 = (const float4*)sW;

    for (int i4 = tid; i4 < 64 * 16; i4 += 256) {
        int r = i4 >> 4, kq = i4 & 15;
        ((float4*)(sA + r * SD))[kq] = ((const float4*)(g_merged + (n0 + r) * 64))[kq];
        ((float4*)(sW + r * SD))[kq] = ((const float4*)(Wk1 + r * 64))[kq];
    }
    for (int i = tid; i < 512; i += 256) {
        int c = i >> 6, k = i & 63;
        sW2[c * 65 + k] = Wk2[i];
    }
    __syncthreads();

    float acc[4][4];
#pragma unroll
    for (int j = 0; j < 4; j++)
#pragma unroll
        for (int i = 0; i < 4; i++) acc[j][i] = 0.0f;
#pragma unroll 4
    for (int k4 = 0; k4 < 16; k4++) {
        float4 a[4], w[4];
#pragma unroll
        for (int j = 0; j < 4; j++) a[j] = sA4[(rty * 4 + j) * SD4 + k4];
#pragma unroll
        for (int i = 0; i < 4; i++) w[i] = sW4[(rtx + 16 * i) * SD4 + k4];
#pragma unroll
        for (int j = 0; j < 4; j++)
#pragma unroll
            for (int i = 0; i < 4; i++) fma4(acc[j][i], a[j], w[i]);
    }
    __syncthreads();
#pragma unroll
    for (int j = 0; j < 4; j++)
#pragma unroll
        for (int i = 0; i < 4; i++) {
            int r = rty * 4 + j, c = rtx + 16 * i;
            sA[r * SD + c] = gelu_f(acc[j][i] + bk1[c]);
        }
    __syncthreads();

    // stage 2: 64x8 out, 2 outputs per thread
    int r = tid & 63, oc0 = (tid >> 6) * 2;
    float o0 = bk2[oc0], o1 = bk2[oc0 + 1];
#pragma unroll 8
    for (int k = 0; k < 64; k++) {
        float h = sA[r * SD + k];
        o0 += h * sW2[oc0 * 65 + k];
        o1 += h * sW2[(oc0 + 1) * 65 + k];
    }
    out[(n0 + r) * 8 + oc0] = o0;
    out[(n0 + r) * 8 + oc0 + 1] = o1;
}

// =====================================================================
extern "C" void kernel_launch(void* const* d_in, const int* in_sizes, int n_in,
                              void* d_out, int out_size)
{
    const float* evx  = (const float*)d_in[0];
    const float* evy  = (const float*)d_in[1];
    const float* exv  = (const float*)d_in[2];
    const float* eyv  = (const float*)d_in[3];
    const float* cif  = (const float*)d_in[4];
    const float* W_in = (const float*)d_in[5];
    const float* b_in = (const float*)d_in[6];
    const float* W_out= (const float*)d_in[7];
    const float* b_out= (const float*)d_in[8];
    const float* g_at = (const float*)d_in[9];
    const float* b_at = (const float*)d_in[10];
    const float* Wi1  = (const float*)d_in[11];
    const float* bi1  = (const float*)d_in[12];
    const float* Wi2  = (const float*)d_in[13];
    const float* bi2  = (const float*)d_in[14];
    const float* gi   = (const float*)d_in[15];
    const float* bni  = (const float*)d_in[16];
    const float* Wc1  = (const float*)d_in[17];
    const float* bc1  = (const float*)d_in[18];
    const float* Wc2  = (const float*)d_in[19];
    const float* bc2  = (const float*)d_in[20];
    const float* gc   = (const float*)d_in[21];
    const float* bnc  = (const float*)d_in[22];
    const float* Wm   = (const float*)d_in[23];
    const float* bm   = (const float*)d_in[24];
    const float* gm   = (const float*)d_in[25];
    const float* bnm  = (const float*)d_in[26];
    const float* Wk1  = (const float*)d_in[27];
    const float* bk1  = (const float*)d_in[28];
    const float* Wk2  = (const float*)d_in[29];
    const float* bk2  = (const float*)d_in[30];
    float* out = (float*)d_out;

    // 1) QKV + attention core (writes g_edges, g_ao)
    k_qkv_attn<<<NN / 8, 256>>>(evx, evy, exv, eyv, W_in, b_in);
    // 2) out-proj + residual + LN -> g_attln   (M = 4N)
    k_lin64_ln<<<(NN * 4) / 64, 256>>>(SRC_AO, 64, W_out, b_out, RES_EDGES,
                                       g_at, b_at, DST_ATTLN, 0);
    // 3) interaction hidden -> g_h1
    k_inter<<<dim3(NN / 64, 2), 256>>>(evx, evy, exv, eyv, Wi1, bi1);
    // 4) Wi2 + LN -> g_iemb
    k_lin64_ln<<<NN / 64, 256>>>(SRC_H1, 128, Wi2, bi2, RES_NONE,
                                 gi, bni, DST_IEMB, 0);
    // 5) ci stage1 -> g_ci1
    k_ci1<<<NN / 16, 256>>>(cif, Wc1, bc1);
    // 6) Wc2 + LN -> g_cemb
    k_lin64_ln<<<NN / 64, 256>>>(SRC_CI1, 64, Wc2, bc2, RES_NONE,
                                 gc, bnc, DST_CEMB, 0);
    // 7) merge linear (A gathered on the fly) + LN + GELU -> g_merged
    k_lin64_ln<<<NN / 64, 256>>>(SRC_MERGE, 192, Wm, bm, RES_NONE,
                                 gm, bnm, DST_MERGED, 1);
    // 8) classifier -> out
    k_cls<<<NN / 64, 256>>>(Wk1, bk1, Wk2, bk2, out);

    (void)in_sizes; (void)n_in; (void)out_size;
}

// round 7
// speedup vs baseline: 1.0951x; 1.0680x over previous
#include <cuda_runtime.h>
#include <math.h>

#define NN 131072
#define SD 68
#define SD4 17
typedef unsigned long long ull;

// ---------------- scratch (static device arrays; no allocations) ----------------
__device__ __align__(16) float g_edges[NN * 4 * 64];
__device__ __align__(16) float g_ao[NN * 4 * 64];
__device__ __align__(16) float g_attln[NN * 4 * 64];
__device__ __align__(16) float g_h1[NN * 128];
__device__ __align__(16) float g_ci1[NN * 64];
__device__ __align__(16) float g_iemb[NN * 64];
__device__ __align__(16) float g_cemb[NN * 64];
__device__ __align__(16) float g_merged[NN * 64];

__device__ __forceinline__ float gelu_f(float x) {
    return 0.5f * x * (1.0f + erff(x * 0.70710678118654752f));
}

// packed fp32x2 FMA: acc.{lo,hi} += a.{lo,hi} * b.{lo,hi}
__device__ __forceinline__ void fma2(ull& acc, ull a, ull b) {
    asm("fma.rn.f32x2 %0, %1, %2, %0;" : "+l"(acc) : "l"(a), "l"(b));
}
__device__ __forceinline__ float2 upk(ull v) {
    float2 r; asm("mov.b64 {%0, %1}, %2;" : "=f"(r.x), "=f"(r.y) : "l"(v)); return r;
}
// view a float4 register quad as two 64-bit lanes {x,y} and {z,w}
union F4U { float4 f4; struct { ull a, b; } p; };

#define SRC_AO    0
#define SRC_H1    1
#define SRC_CI1   2
#define SRC_MERGE 3
#define RES_NONE  -1
#define RES_EDGES 0
#define DST_ATTLN 0
#define DST_IEMB  1
#define DST_CEMB  2
#define DST_MERGED 3

__device__ __forceinline__ float4 loadA4(int id, int row, int col) {
    switch (id) {
        case SRC_AO:  return *(const float4*)(g_ao + row * 64 + col);
        case SRC_H1:  return *(const float4*)(g_h1 + row * 128 + col);
        case SRC_CI1: return *(const float4*)(g_ci1 + row * 64 + col);
        default: {
            if (col < 64) {
                const float* base = g_attln + row * 256 + col;
                float4 a = *(const float4*)(base);
                float4 b = *(const float4*)(base + 64);
                float4 c = *(const float4*)(base + 128);
                float4 d = *(const float4*)(base + 192);
                float4 r;
                r.x = 0.25f * (a.x + b.x + c.x + d.x);
                r.y = 0.25f * (a.y + b.y + c.y + d.y);
                r.z = 0.25f * (a.z + b.z + c.z + d.z);
                r.w = 0.25f * (a.w + b.w + c.w + d.w);
                return r;
            } else if (col < 128) {
                return *(const float4*)(g_iemb + row * 64 + (col - 64));
            } else {
                return *(const float4*)(g_cemb + row * 64 + (col - 128));
            }
        }
    }
}

__device__ __forceinline__ float* dstPtr(int id) {
    switch (id) {
        case DST_ATTLN: return g_attln;
        case DST_IEMB:  return g_iemb;
        case DST_CEMB:  return g_cemb;
        default:        return g_merged;
    }
}

// =====================================================================
// lin128: dst(M,64) = LN(A(M,K) @ W(64,K)^T + b (+res)) * gamma + beta, opt GELU
// 128 rows/block, 128 threads, 8x8 thread tile, packed f32x2 FMA
// smem: sA 128x64 unpadded (broadcast reads), sW 64x64 XOR-swizzled
// =====================================================================
__global__ void __launch_bounds__(128, 2)
k_lin128(int srcId, int K,
         const float* __restrict__ W, const float* __restrict__ b,
         int resId,
         const float* __restrict__ gamma, const float* __restrict__ beta,
         int dstId, int doGelu)
{
    __shared__ __align__(16) float sA[128 * 64];
    __shared__ __align__(16) float sW[64 * 64];
    float4* sA4 = (float4*)sA;
    float4* sW4 = (float4*)sW;

    const int tid = threadIdx.x;
    const int row0 = blockIdx.x * 128;
    const int rty = tid >> 3;      // 0..15 -> rows rty*8..+7
    const int rtx = tid & 7;       // 0..7  -> cols rtx*8..+7

    ull acc[8][8];
#pragma unroll
    for (int j = 0; j < 8; j++)
#pragma unroll
        for (int i = 0; i < 8; i++) acc[j][i] = 0ULL;

    for (int kc = 0; kc < K; kc += 64) {
        __syncthreads();
        for (int i4 = tid; i4 < 128 * 16; i4 += 128) {
            int r = i4 >> 4, k4 = i4 & 15;
            sA4[r * 16 + k4] = loadA4(srcId, row0 + r, kc + k4 * 4);
        }
        for (int i4 = tid; i4 < 64 * 16; i4 += 128) {
            int c = i4 >> 4, k4 = i4 & 15;
            sW4[c * 16 + (k4 ^ (c >> 3))] = *(const float4*)(W + c * K + kc + k4 * 4);
        }
        __syncthreads();
#pragma unroll 2
        for (int k4 = 0; k4 < 16; k4++) {
            F4U w[8];
#pragma unroll
            for (int i = 0; i < 8; i++)
                w[i].f4 = sW4[(rtx * 8 + i) * 16 + (k4 ^ rtx)];
#pragma unroll
            for (int j = 0; j < 8; j++) {
                F4U a; a.f4 = sA4[(rty * 8 + j) * 16 + k4];
#pragma unroll
                for (int i = 0; i < 8; i++) {
                    fma2(acc[j][i], a.p.a, w[i].p.a);
                    fma2(acc[j][i], a.p.b, w[i].p.b);
                }
            }
        }
    }

    // epilogue in registers
    float4 bq0 = *(const float4*)(b + rtx * 8);
    float4 bq1 = *(const float4*)(b + rtx * 8 + 4);
    float bias[8] = {bq0.x, bq0.y, bq0.z, bq0.w, bq1.x, bq1.y, bq1.z, bq1.w};
    float4 gq0 = *(const float4*)(gamma + rtx * 8);
    float4 gq1 = *(const float4*)(gamma + rtx * 8 + 4);
    float gam[8] = {gq0.x, gq0.y, gq0.z, gq0.w, gq1.x, gq1.y, gq1.z, gq1.w};
    float4 eq0 = *(const float4*)(beta + rtx * 8);
    float4 eq1 = *(const float4*)(beta + rtx * 8 + 4);
    float bet[8] = {eq0.x, eq0.y, eq0.z, eq0.w, eq1.x, eq1.y, eq1.z, eq1.w};

    float* out = dstPtr(dstId);
#pragma unroll
    for (int j = 0; j < 8; j++) {
        int row = row0 + rty * 8 + j;
        float c[8];
#pragma unroll
        for (int i = 0; i < 8; i++) {
            float2 v = upk(acc[j][i]);
            c[i] = v.x + v.y + bias[i];
        }
        if (resId == RES_EDGES) {
            float4 r0 = *(const float4*)(g_edges + row * 64 + rtx * 8);
            float4 r1 = *(const float4*)(g_edges + row * 64 + rtx * 8 + 4);
            c[0] += r0.x; c[1] += r0.y; c[2] += r0.z; c[3] += r0.w;
            c[4] += r1.x; c[5] += r1.y; c[6] += r1.z; c[7] += r1.w;
        }
        float s = 0.0f, ss = 0.0f;
#pragma unroll
        for (int i = 0; i < 8; i++) { s += c[i]; ss += c[i] * c[i]; }
        s  += __shfl_xor_sync(0xffffffffu, s, 1, 8);
        s  += __shfl_xor_sync(0xffffffffu, s, 2, 8);
        s  += __shfl_xor_sync(0xffffffffu, s, 4, 8);
        ss += __shfl_xor_sync(0xffffffffu, ss, 1, 8);
        ss += __shfl_xor_sync(0xffffffffu, ss, 2, 8);
        ss += __shfl_xor_sync(0xffffffffu, ss, 4, 8);
        float mean = s * (1.0f / 64.0f);
        float var = ss * (1.0f / 64.0f) - mean * mean;
        float rstd = rsqrtf(var + 1e-5f);
        float y[8];
#pragma unroll
        for (int i = 0; i < 8; i++) {
            float v = (c[i] - mean) * rstd * gam[i] + bet[i];
            y[i] = doGelu ? gelu_f(v) : v;
        }
        float4 o0 = {y[0], y[1], y[2], y[3]};
        float4 o1 = {y[4], y[5], y[6], y[7]};
        *(float4*)(out + (size_t)row * 64 + rtx * 8)     = o0;
        *(float4*)(out + (size_t)row * 64 + rtx * 8 + 4) = o1;
    }
}

// =====================================================================
// Interaction: g_h1(N,128) = GELU(inter(N,384) @ Wi1^T + bi1)
// 128 rows x 64 cols per block (blockIdx.y = col half), 6 K-chunks
// =====================================================================
__global__ void __launch_bounds__(128, 2)
k_inter(const float* __restrict__ evx, const float* __restrict__ evy,
        const float* __restrict__ exv, const float* __restrict__ eyv,
        const float* __restrict__ Wi1, const float* __restrict__ bi1)
{
    __shared__ __align__(16) float sA[128 * 64];
    __shared__ __align__(16) float sW[64 * 64];
    float4* sA4 = (float4*)sA;
    float4* sW4 = (float4*)sW;

    const int tid = threadIdx.x;
    const int n0 = blockIdx.x * 128;
    const int c0 = blockIdx.y * 64;
    const int rty = tid >> 3, rtx = tid & 7;

    ull acc[8][8];
#pragma unroll
    for (int j = 0; j < 8; j++)
#pragma unroll
        for (int i = 0; i < 8; i++) acc[j][i] = 0ULL;

#pragma unroll 1
    for (int p = 0; p < 6; p++) {
        const float* Ea; const float* Eb;
        switch (p) {
            case 0: Ea = evx; Eb = evy; break;
            case 1: Ea = evx; Eb = exv; break;
            case 2: Ea = evx; Eb = eyv; break;
            case 3: Ea = evy; Eb = exv; break;
            case 4: Ea = evy; Eb = eyv; break;
            default: Ea = exv; Eb = eyv; break;
        }
        __syncthreads();
        for (int i4 = tid; i4 < 128 * 16; i4 += 128) {
            int r = i4 >> 4, k4 = i4 & 15;
            float4 x = ((const float4*)(Ea + (n0 + r) * 64))[k4];
            float4 y = ((const float4*)(Eb + (n0 + r) * 64))[k4];
            float4 v; v.x = x.x * y.x; v.y = x.y * y.y; v.z = x.z * y.z; v.w = x.w * y.w;
            sA4[r * 16 + k4] = v;
        }
        for (int i4 = tid; i4 < 64 * 16; i4 += 128) {
            int c = i4 >> 4, k4 = i4 & 15;
            sW4[c * 16 + (k4 ^ (c >> 3))] = *(const float4*)(Wi1 + (c0 + c) * 384 + p * 64 + k4 * 4);
        }
        __syncthreads();
#pragma unroll 2
        for (int k4 = 0; k4 < 16; k4++) {
            F4U w[8];
#pragma unroll
            for (int i = 0; i < 8; i++)
                w[i].f4 = sW4[(rtx * 8 + i) * 16 + (k4 ^ rtx)];
#pragma unroll
            for (int j = 0; j < 8; j++) {
                F4U a; a.f4 = sA4[(rty * 8 + j) * 16 + k4];
#pragma unroll
                for (int i = 0; i < 8; i++) {
                    fma2(acc[j][i], a.p.a, w[i].p.a);
                    fma2(acc[j][i], a.p.b, w[i].p.b);
                }
            }
        }
    }

    float4 bq0 = *(const float4*)(bi1 + c0 + rtx * 8);
    float4 bq1 = *(const float4*)(bi1 + c0 + rtx * 8 + 4);
    float bias[8] = {bq0.x, bq0.y, bq0.z, bq0.w, bq1.x, bq1.y, bq1.z, bq1.w};
#pragma unroll
    for (int j = 0; j < 8; j++) {
        int row = n0 + rty * 8 + j;
        float y[8];
#pragma unroll
        for (int i = 0; i < 8; i++) {
            float2 v = upk(acc[j][i]);
            y[i] = gelu_f(v.x + v.y + bias[i]);
        }
        float4 o0 = {y[0], y[1], y[2], y[3]};
        float4 o1 = {y[4], y[5], y[6], y[7]};
        *(float4*)(g_h1 + (size_t)row * 128 + c0 + rtx * 8)     = o0;
        *(float4*)(g_h1 + (size_t)row * 128 + c0 + rtx * 8 + 4) = o1;
    }
}

// =====================================================================
// QKV GEMM (8 nodes = 32 rows, W in 3 chunks) + fused attention -> g_ao
// 128 threads, 2x8 thread tile, packed FMA
// =====================================================================
__global__ void __launch_bounds__(128, 4)
k_qkv_attn(const float* __restrict__ evx, const float* __restrict__ evy,
           const float* __restrict__ exv, const float* __restrict__ eyv,
           const float* __restrict__ Win, const float* __restrict__ bin)
{
    __shared__ __align__(16) float sW[64 * 64];
    __shared__ __align__(16) float sE[32 * 64];     // edges; later reused for V
    __shared__ __align__(16) float sQK[32 * 128];   // Q cols 0..63, K cols 64..127
    __shared__ float sb[192];
    float4* sE4 = (float4*)sE;
    float4* sW4 = (float4*)sW;

    const int tid = threadIdx.x;
    const int node0 = blockIdx.x * 8;
    const int rty = tid >> 3, rtx = tid & 7;

    for (int i = tid; i < 192; i += 128) sb[i] = bin[i];
    for (int i4 = tid; i4 < 32 * 16; i4 += 128) {
        int r = i4 >> 4, k4 = i4 & 15;
        int node = node0 + (r >> 2), s = r & 3;
        const float* base = (s == 0) ? evx : (s == 1) ? evy : (s == 2) ? exv : eyv;
        float4 v = ((const float4*)(base + node * 64))[k4];
        sE4[r * 16 + k4] = v;
        ((float4*)(g_edges + (node0 * 4 + r) * 64))[k4] = v;
    }

    for (int wc = 0; wc < 3; wc++) {
        __syncthreads();
        for (int i4 = tid; i4 < 64 * 16; i4 += 128) {
            int c = i4 >> 4, k4 = i4 & 15;
            sW4[c * 16 + (k4 ^ (c >> 3))] = *(const float4*)(Win + (wc * 64 + c) * 64 + k4 * 4);
        }
        __syncthreads();

        ull acc[2][8];
#pragma unroll
        for (int j = 0; j < 2; j++)
#pragma unroll
            for (int i = 0; i < 8; i++) acc[j][i] = 0ULL;
#pragma unroll 4
        for (int k4 = 0; k4 < 16; k4++) {
            F4U w[8];
#pragma unroll
            for (int i = 0; i < 8; i++)
                w[i].f4 = sW4[(rtx * 8 + i) * 16 + (k4 ^ rtx)];
#pragma unroll
            for (int j = 0; j < 2; j++) {
                F4U a; a.f4 = sE4[(rty * 2 + j) * 16 + k4];
#pragma unroll
                for (int i = 0; i < 8; i++) {
                    fma2(acc[j][i], a.p.a, w[i].p.a);
                    fma2(acc[j][i], a.p.b, w[i].p.b);
                }
            }
        }
        if (wc < 2) {
#pragma unroll
            for (int j = 0; j < 2; j++)
#pragma unroll
                for (int i = 0; i < 8; i++) {
                    int col = rtx * 8 + i;
                    float2 v = upk(acc[j][i]);
                    sQK[(rty * 2 + j) * 128 + wc * 64 + col] = v.x + v.y + sb[wc * 64 + col];
                }
        } else {
            __syncthreads();   // all V-GEMM reads of sE done before overwrite
#pragma unroll
            for (int j = 0; j < 2; j++)
#pragma unroll
                for (int i = 0; i < 8; i++) {
                    int col = rtx * 8 + i;
                    float2 v = upk(acc[j][i]);
                    sE[(rty * 2 + j) * 64 + col] = v.x + v.y + sb[128 + col];
                }
        }
    }
    __syncthreads();

    // attention: warp w handles 2 nodes; 16 lanes per node = (head, query)
    {
        int w = tid >> 5, lane = tid & 31;
        int nl = w * 2 + (lane >> 4);          // local node 0..7
        int l = lane & 15;
        int h = l >> 2, qs = l & 3;
        const float* qrow = &sQK[(nl * 4 + qs) * 128 + h * 16];
        float sc[4];
#pragma unroll
        for (int ks = 0; ks < 4; ks++) {
            const float* krow = &sQK[(nl * 4 + ks) * 128 + 64 + h * 16];
            float d = 0.0f;
#pragma unroll
            for (int e = 0; e < 16; e++) d += qrow[e] * krow[e];
            sc[ks] = d * 0.25f;
        }
        float m = fmaxf(fmaxf(sc[0], sc[1]), fmaxf(sc[2], sc[3]));
        float ssum = 0.0f;
#pragma unroll
        for (int ks = 0; ks < 4; ks++) { sc[ks] = expf(sc[ks] - m); ssum += sc[ks]; }
        float inv = 1.0f / ssum;
        int obase = ((node0 + nl) * 4 + qs) * 64 + h * 16;
#pragma unroll
        for (int e = 0; e < 16; e++) {
            float o = 0.0f;
#pragma unroll
            for (int ks = 0; ks < 4; ks++)
                o += sc[ks] * sE[(nl * 4 + ks) * 64 + h * 16 + e];
            g_ao[obase + e] = o * inv;
        }
    }
}

// =====================================================================
// ci stage 1: g_ci1(N,64) = GELU( ci(N,10) @ Wc1^T + bc1 ), 16 nodes/block
// =====================================================================
__global__ void k_ci1(const float* __restrict__ ci, const float* __restrict__ Wc1,
                      const float* __restrict__ bc1)
{
    __shared__ float sW[64 * 10];
    __shared__ float sC[16 * 10];
    const int tid = threadIdx.x;
    const int n0 = blockIdx.x * 16;
    for (int i = tid; i < 640; i += 256) sW[i] = Wc1[i];
    if (tid < 160) sC[tid] = ci[n0 * 10 + tid];
    __syncthreads();
    for (int o = tid; o < 1024; o += 256) {
        int nl = o >> 6, c = o & 63;
        float a = bc1[c];
#pragma unroll
        for (int k = 0; k < 10; k++) a += sC[nl * 10 + k] * sW[c * 10 + k];
        g_ci1[(n0 + nl) * 64 + c] = gelu_f(a);
    }
}

// =====================================================================
// classifier: out(N,8) = GELU(merged @ Wk1^T + bk1) @ Wk2^T + bk2 ; 64 nodes/block
// =====================================================================
__global__ void k_cls(const float* __restrict__ Wk1, const float* __restrict__ bk1,
                      const float* __restrict__ Wk2, const float* __restrict__ bk2,
                      float* __restrict__ out)
{
    __shared__ __align__(16) float sA[64 * SD];
    __shared__ __align__(16) float sW[64 * SD];
    __shared__ float sW2[8 * 65];
    const int tid = threadIdx.x;
    const int n0 = blockIdx.x * 64;
    const int rty = tid >> 4, rtx = tid & 15;
    const float4* sA4 = (const float4*)sA;
    const float4* sW4 = (const float4*)sW;

    for (int i4 = tid; i4 < 64 * 16; i4 += 256) {
        int r = i4 >> 4, kq = i4 & 15;
        ((float4*)(sA + r * SD))[kq] = ((const float4*)(g_merged + (n0 + r) * 64))[kq];
        ((float4*)(sW + r * SD))[kq] = ((const float4*)(Wk1 + r * 64))[kq];
    }
    for (int i = tid; i < 512; i += 256) {
        int c = i >> 6, k = i & 63;
        sW2[c * 65 + k] = Wk2[i];
    }
    __syncthreads();

    float acc[4][4];
#pragma unroll
    for (int j = 0; j < 4; j++)
#pragma unroll
        for (int i = 0; i < 4; i++) acc[j][i] = 0.0f;
#pragma unroll 4
    for (int k4 = 0; k4 < 16; k4++) {
        float4 a[4], w[4];
#pragma unroll
        for (int j = 0; j < 4; j++) a[j] = sA4[(rty * 4 + j) * SD4 + k4];
#pragma unroll
        for (int i = 0; i < 4; i++) w[i] = sW4[(rtx + 16 * i) * SD4 + k4];
#pragma unroll
        for (int j = 0; j < 4; j++)
#pragma unroll
            for (int i = 0; i < 4; i++) {
                acc[j][i] = fmaf(a[j].x, w[i].x, acc[j][i]);
                acc[j][i] = fmaf(a[j].y, w[i].y, acc[j][i]);
                acc[j][i] = fmaf(a[j].z, w[i].z, acc[j][i]);
                acc[j][i] = fmaf(a[j].w, w[i].w, acc[j][i]);
            }
    }
    __syncthreads();
#pragma unroll
    for (int j = 0; j < 4; j++)
#pragma unroll
        for (int i = 0; i < 4; i++) {
            int r = rty * 4 + j, c = rtx + 16 * i;
            sA[r * SD + c] = gelu_f(acc[j][i] + bk1[c]);
        }
    __syncthreads();

    int r = tid & 63, oc0 = (tid >> 6) * 2;
    float o0 = bk2[oc0], o1 = bk2[oc0 + 1];
#pragma unroll 8
    for (int k = 0; k < 64; k++) {
        float h = sA[r * SD + k];
        o0 += h * sW2[oc0 * 65 + k];
        o1 += h * sW2[(oc0 + 1) * 65 + k];
    }
    out[(n0 + r) * 8 + oc0] = o0;
    out[(n0 + r) * 8 + oc0 + 1] = o1;
}

// =====================================================================
extern "C" void kernel_launch(void* const* d_in, const int* in_sizes, int n_in,
                              void* d_out, int out_size)
{
    const float* evx  = (const float*)d_in[0];
    const float* evy  = (const float*)d_in[1];
    const float* exv  = (const float*)d_in[2];
    const float* eyv  = (const float*)d_in[3];
    const float* cif  = (const float*)d_in[4];
    const float* W_in = (const float*)d_in[5];
    const float* b_in = (const float*)d_in[6];
    const float* W_out= (const float*)d_in[7];
    const float* b_out= (const float*)d_in[8];
    const float* g_at = (const float*)d_in[9];
    const float* b_at = (const float*)d_in[10];
    const float* Wi1  = (const float*)d_in[11];
    const float* bi1  = (const float*)d_in[12];
    const float* Wi2  = (const float*)d_in[13];
    const float* bi2  = (const float*)d_in[14];
    const float* gi   = (const float*)d_in[15];
    const float* bni  = (const float*)d_in[16];
    const float* Wc1  = (const float*)d_in[17];
    const float* bc1  = (const float*)d_in[18];
    const float* Wc2  = (const float*)d_in[19];
    const float* bc2  = (const float*)d_in[20];
    const float* gc   = (const float*)d_in[21];
    const float* bnc  = (const float*)d_in[22];
    const float* Wm   = (const float*)d_in[23];
    const float* bm   = (const float*)d_in[24];
    const float* gm   = (const float*)d_in[25];
    const float* bnm  = (const float*)d_in[26];
    const float* Wk1  = (const float*)d_in[27];
    const float* bk1  = (const float*)d_in[28];
    const float* Wk2  = (const float*)d_in[29];
    const float* bk2  = (const float*)d_in[30];
    float* out = (float*)d_out;

    // 1) QKV + attention core (writes g_edges, g_ao)
    k_qkv_attn<<<NN / 8, 128>>>(evx, evy, exv, eyv, W_in, b_in);
    // 2) out-proj + residual + LN -> g_attln (M = 4N)
    k_lin128<<<(NN * 4) / 128, 128>>>(SRC_AO, 64, W_out, b_out, RES_EDGES,
                                      g_at, b_at, DST_ATTLN, 0);
    // 3) interaction hidden -> g_h1
    k_inter<<<dim3(NN / 128, 2), 128>>>(evx, evy, exv, eyv, Wi1, bi1);
    // 4) Wi2 + LN -> g_iemb
    k_lin128<<<NN / 128, 128>>>(SRC_H1, 128, Wi2, bi2, RES_NONE,
                                gi, bni, DST_IEMB, 0);
    // 5) ci stage1 -> g_ci1
    k_ci1<<<NN / 16, 256>>>(cif, Wc1, bc1);
    // 6) Wc2 + LN -> g_cemb
    k_lin128<<<NN / 128, 128>>>(SRC_CI1, 64, Wc2, bc2, RES_NONE,
                                gc, bnc, DST_CEMB, 0);
    // 7) merge (A gathered on the fly) + LN + GELU -> g_merged
    k_lin128<<<NN / 128, 128>>>(SRC_MERGE, 192, Wm, bm, RES_NONE,
                                gm, bnm, DST_MERGED, 1);
    // 8) classifier -> out
    k_cls<<<NN / 64, 256>>>(Wk1, bk1, Wk2, bk2, out);

    (void)in_sizes; (void)n_in; (void)out_size;
}

// round 9
// speedup vs baseline: 1.6275x; 1.4862x over previous
#include <cuda_runtime.h>
#include <math.h>

#define NN 131072
#define SD 68
#define SD4 17

// ---------------- scratch (static device arrays; no allocations) ----------------
__device__ __align__(16) float g_edges[NN * 4 * 64];
__device__ __align__(16) float g_ao[NN * 4 * 64];
__device__ __align__(16) float g_attln[NN * 4 * 64];
__device__ __align__(16) float g_h1[NN * 128];
__device__ __align__(16) float g_ci1[NN * 64];
__device__ __align__(16) float g_iemb[NN * 64];
__device__ __align__(16) float g_cemb[NN * 64];
__device__ __align__(16) float g_merged[NN * 64];

__device__ __forceinline__ float gelu_f(float x) {
    return 0.5f * x * (1.0f + erff(x * 0.70710678118654752f));
}
__device__ __forceinline__ float to_tf32(float x) {
    unsigned r;
    asm("cvt.rna.tf32.f32 %0, %1;" : "=r"(r) : "f"(x));
    return __uint_as_float(r);
}
__device__ __forceinline__ float4 tf32x4(float4 v) {
    v.x = to_tf32(v.x); v.y = to_tf32(v.y); v.z = to_tf32(v.z); v.w = to_tf32(v.w);
    return v;
}
// D(16x8) += A(16x8,row) * B(8x8,col) in tf32, fp32 accum
__device__ __forceinline__ void mma8(float* c, const unsigned* a, const unsigned* b) {
    asm("mma.sync.aligned.m16n8k8.row.col.f32.tf32.tf32.f32 "
        "{%0,%1,%2,%3}, {%4,%5,%6,%7}, {%8,%9}, {%0,%1,%2,%3};"
        : "+f"(c[0]), "+f"(c[1]), "+f"(c[2]), "+f"(c[3])
        : "r"(a[0]), "r"(a[1]), "r"(a[2]), "r"(a[3]), "r"(b[0]), "r"(b[1]));
}

#define SRC_AO    0
#define SRC_H1    1
#define SRC_CI1   2
#define SRC_MERGE 3
#define RES_NONE  -1
#define RES_EDGES 0
#define DST_ATTLN 0
#define DST_IEMB  1
#define DST_CEMB  2
#define DST_MERGED 3

__device__ __forceinline__ float4 loadA4(int id, int row, int col) {
    switch (id) {
        case SRC_AO:  return *(const float4*)(g_ao + (size_t)row * 64 + col);
        case SRC_H1:  return *(const float4*)(g_h1 + (size_t)row * 128 + col);
        case SRC_CI1: return *(const float4*)(g_ci1 + (size_t)row * 64 + col);
        default: {
            if (col < 64) {
                const float* base = g_attln + (size_t)row * 256 + col;
                float4 a = *(const float4*)(base);
                float4 b = *(const float4*)(base + 64);
                float4 c = *(const float4*)(base + 128);
                float4 d = *(const float4*)(base + 192);
                float4 r;
                r.x = 0.25f * (a.x + b.x + c.x + d.x);
                r.y = 0.25f * (a.y + b.y + c.y + d.y);
                r.z = 0.25f * (a.z + b.z + c.z + d.z);
                r.w = 0.25f * (a.w + b.w + c.w + d.w);
                return r;
            } else if (col < 128) {
                return *(const float4*)(g_iemb + (size_t)row * 64 + (col - 64));
            } else {
                return *(const float4*)(g_cemb + (size_t)row * 64 + (col - 128));
            }
        }
    }
}
__device__ __forceinline__ float* dstPtr(int id) {
    switch (id) {
        case DST_ATTLN: return g_attln;
        case DST_IEMB:  return g_iemb;
        case DST_CEMB:  return g_cemb;
        default:        return g_merged;
    }
}

// =====================================================================
// k_lin_mma: dst(M,64) = LN(A(M,K)@W^T + b (+res))*gamma+beta, opt GELU
// 128 rows/block, 128 threads (4 warps), tf32 mma, row-per-thread epilogue
// dyn smem: sA 128x68 | sW 64x68   (52224 B)
// =====================================================================
extern __shared__ float dsm[];

__global__ void __launch_bounds__(128)
k_lin_mma(int srcId, int K, const float* __restrict__ W, const float* __restrict__ b,
          int resId, const float* __restrict__ gamma, const float* __restrict__ beta,
          int dstId, int doGelu)
{
    float* sA = dsm;              // 128*68
    float* sW = dsm + 128 * 68;   // 64*68
    const int tid = threadIdx.x;
    const int lane = tid & 31, wp = tid >> 5;
    const int g = lane >> 2, t = lane & 3;
    const int row0 = blockIdx.x * 128;

    float acc[2][8][4];
#pragma unroll
    for (int m = 0; m < 2; m++)
#pragma unroll
        for (int n = 0; n < 8; n++)
#pragma unroll
            for (int i = 0; i < 4; i++) acc[m][n][i] = 0.0f;

    for (int kc = 0; kc < K; kc += 64) {
        __syncthreads();
        for (int i4 = tid; i4 < 128 * 16; i4 += 128) {
            int r = i4 >> 4, k4 = i4 & 15;
            *(float4*)(sA + r * 68 + k4 * 4) = tf32x4(loadA4(srcId, row0 + r, kc + k4 * 4));
        }
        for (int i4 = tid; i4 < 64 * 16; i4 += 128) {
            int c = i4 >> 4, k4 = i4 & 15;
            *(float4*)(sW + c * 68 + k4 * 4) = tf32x4(*(const float4*)(W + c * K + kc + k4 * 4));
        }
        __syncthreads();
#pragma unroll
        for (int k8 = 0; k8 < 8; k8++) {
            int kb = k8 * 8;
            unsigned a[2][4], bb[8][2];
#pragma unroll
            for (int m = 0; m < 2; m++) {
                int R = wp * 32 + m * 16;
                a[m][0] = __float_as_uint(sA[(R + g) * 68 + kb + t]);
                a[m][1] = __float_as_uint(sA[(R + g + 8) * 68 + kb + t]);
                a[m][2] = __float_as_uint(sA[(R + g) * 68 + kb + t + 4]);
                a[m][3] = __float_as_uint(sA[(R + g + 8) * 68 + kb + t + 4]);
            }
#pragma unroll
            for (int n = 0; n < 8; n++) {
                bb[n][0] = __float_as_uint(sW[(n * 8 + g) * 68 + kb + t]);
                bb[n][1] = __float_as_uint(sW[(n * 8 + g) * 68 + kb + t + 4]);
            }
#pragma unroll
            for (int m = 0; m < 2; m++)
#pragma unroll
                for (int n = 0; n < 8; n++) mma8(acc[m][n], a[m], bb[n]);
        }
    }

    // scatter C into sA (each warp owns rows [32wp,32wp+32) — no cross-warp hazard)
#pragma unroll
    for (int m = 0; m < 2; m++)
#pragma unroll
        for (int n = 0; n < 8; n++) {
            int R = wp * 32 + m * 16;
            *(float2*)(sA + (R + g) * 68 + n * 8 + 2 * t)     = make_float2(acc[m][n][0], acc[m][n][1]);
            *(float2*)(sA + (R + g + 8) * 68 + n * 8 + 2 * t) = make_float2(acc[m][n][2], acc[m][n][3]);
        }
    __syncthreads();
    // params into sW (free now): b | gamma | beta
    if (tid < 64) {
        sW[tid] = b[tid];
        sW[64 + tid] = gamma[tid];
        sW[128 + tid] = beta[tid];
    }
    __syncthreads();

    // row-per-thread epilogue
    int row = row0 + tid;
    float4 cv[16];
#pragma unroll
    for (int k4 = 0; k4 < 16; k4++) cv[k4] = *(float4*)(sA + tid * 68 + k4 * 4);
#pragma unroll
    for (int k4 = 0; k4 < 16; k4++) {
        cv[k4].x += sW[k4 * 4 + 0];
        cv[k4].y += sW[k4 * 4 + 1];
        cv[k4].z += sW[k4 * 4 + 2];
        cv[k4].w += sW[k4 * 4 + 3];
    }
    if (resId == RES_EDGES) {
#pragma unroll
        for (int k4 = 0; k4 < 16; k4++) {
            float4 r = *(const float4*)(g_edges + (size_t)row * 64 + k4 * 4);
            cv[k4].x += r.x; cv[k4].y += r.y; cv[k4].z += r.z; cv[k4].w += r.w;
        }
    }
    float s = 0.0f, ss = 0.0f;
#pragma unroll
    for (int k4 = 0; k4 < 16; k4++) {
        s += cv[k4].x + cv[k4].y + cv[k4].z + cv[k4].w;
        ss += cv[k4].x * cv[k4].x + cv[k4].y * cv[k4].y + cv[k4].z * cv[k4].z + cv[k4].w * cv[k4].w;
    }
    float mean = s * (1.0f / 64.0f);
    float var = ss * (1.0f / 64.0f) - mean * mean;
    float rstd = rsqrtf(var + 1e-5f);
    float* out = dstPtr(dstId);
#pragma unroll
    for (int k4 = 0; k4 < 16; k4++) {
        float4 o;
        o.x = (cv[k4].x - mean) * rstd * sW[64 + k4 * 4 + 0] + sW[128 + k4 * 4 + 0];
        o.y = (cv[k4].y - mean) * rstd * sW[64 + k4 * 4 + 1] + sW[128 + k4 * 4 + 1];
        o.z = (cv[k4].z - mean) * rstd * sW[64 + k4 * 4 + 2] + sW[128 + k4 * 4 + 2];
        o.w = (cv[k4].w - mean) * rstd * sW[64 + k4 * 4 + 3] + sW[128 + k4 * 4 + 3];
        if (doGelu) { o.x = gelu_f(o.x); o.y = gelu_f(o.y); o.z = gelu_f(o.z); o.w = gelu_f(o.w); }
        *(float4*)(out + (size_t)row * 64 + k4 * 4) = o;
    }
}

// =====================================================================
// k_inter_mma: g_h1(N,128) = GELU(inter(N,384)@Wi1^T + bi1); col half via blockIdx.y
// =====================================================================
__global__ void __launch_bounds__(128)
k_inter_mma(const float* __restrict__ evx, const float* __restrict__ evy,
            const float* __restrict__ exv, const float* __restrict__ eyv,
            const float* __restrict__ Wi1, const float* __restrict__ bi1)
{
    float* sA = dsm;
    float* sW = dsm + 128 * 68;
    const int tid = threadIdx.x;
    const int lane = tid & 31, wp = tid >> 5;
    const int g = lane >> 2, t = lane & 3;
    const int n0 = blockIdx.x * 128;
    const int c0 = blockIdx.y * 64;

    float acc[2][8][4];
#pragma unroll
    for (int m = 0; m < 2; m++)
#pragma unroll
        for (int n = 0; n < 8; n++)
#pragma unroll
            for (int i = 0; i < 4; i++) acc[m][n][i] = 0.0f;

#pragma unroll 1
    for (int p = 0; p < 6; p++) {
        const float* Ea; const float* Eb;
        switch (p) {
            case 0: Ea = evx; Eb = evy; break;
            case 1: Ea = evx; Eb = exv; break;
            case 2: Ea = evx; Eb = eyv; break;
            case 3: Ea = evy; Eb = exv; break;
            case 4: Ea = evy; Eb = eyv; break;
            default: Ea = exv; Eb = eyv; break;
        }
        __syncthreads();
        for (int i4 = tid; i4 < 128 * 16; i4 += 128) {
            int r = i4 >> 4, k4 = i4 & 15;
            float4 x = ((const float4*)(Ea + (size_t)(n0 + r) * 64))[k4];
            float4 y = ((const float4*)(Eb + (size_t)(n0 + r) * 64))[k4];
            float4 v; v.x = x.x * y.x; v.y = x.y * y.y; v.z = x.z * y.z; v.w = x.w * y.w;
            *(float4*)(sA + r * 68 + k4 * 4) = tf32x4(v);
        }
        for (int i4 = tid; i4 < 64 * 16; i4 += 128) {
            int c = i4 >> 4, k4 = i4 & 15;
            *(float4*)(sW + c * 68 + k4 * 4) =
                tf32x4(*(const float4*)(Wi1 + (size_t)(c0 + c) * 384 + p * 64 + k4 * 4));
        }
        __syncthreads();
#pragma unroll
        for (int k8 = 0; k8 < 8; k8++) {
            int kb = k8 * 8;
            unsigned a[2][4], bb[8][2];
#pragma unroll
            for (int m = 0; m < 2; m++) {
                int R = wp * 32 + m * 16;
                a[m][0] = __float_as_uint(sA[(R + g) * 68 + kb + t]);
                a[m][1] = __float_as_uint(sA[(R + g + 8) * 68 + kb + t]);
                a[m][2] = __float_as_uint(sA[(R + g) * 68 + kb + t + 4]);
                a[m][3] = __float_as_uint(sA[(R + g + 8) * 68 + kb + t + 4]);
            }
#pragma unroll
            for (int n = 0; n < 8; n++) {
                bb[n][0] = __float_as_uint(sW[(n * 8 + g) * 68 + kb + t]);
                bb[n][1] = __float_as_uint(sW[(n * 8 + g) * 68 + kb + t + 4]);
            }
#pragma unroll
            for (int m = 0; m < 2; m++)
#pragma unroll
                for (int n = 0; n < 8; n++) mma8(acc[m][n], a[m], bb[n]);
        }
    }

#pragma unroll
    for (int m = 0; m < 2; m++)
#pragma unroll
        for (int n = 0; n < 8; n++) {
            int R = wp * 32 + m * 16;
            *(float2*)(sA + (R + g) * 68 + n * 8 + 2 * t)     = make_float2(acc[m][n][0], acc[m][n][1]);
            *(float2*)(sA + (R + g + 8) * 68 + n * 8 + 2 * t) = make_float2(acc[m][n][2], acc[m][n][3]);
        }
    __syncthreads();
    if (tid < 64) sW[tid] = bi1[c0 + tid];
    __syncthreads();

    int row = n0 + tid;
#pragma unroll
    for (int k4 = 0; k4 < 16; k4++) {
        float4 c = *(float4*)(sA + tid * 68 + k4 * 4);
        float4 o;
        o.x = gelu_f(c.x + sW[k4 * 4 + 0]);
        o.y = gelu_f(c.y + sW[k4 * 4 + 1]);
        o.z = gelu_f(c.z + sW[k4 * 4 + 2]);
        o.w = gelu_f(c.w + sW[k4 * 4 + 3]);
        *(float4*)(g_h1 + (size_t)row * 128 + c0 + k4 * 4) = o;
    }
}

// =====================================================================
// k_qkv_attn_mma: 32 nodes (128 edge rows)/block. QKV GEMM (tf32 mma, 3 W-chunks)
// + attention (thread = (node, query)) -> g_ao. Writes g_edges.
// dyn smem: sE 128x68 | sW 64x68 | sQKV 128x196   (152576 B)
// =====================================================================
__global__ void __launch_bounds__(128)
k_qkv_attn_mma(const float* __restrict__ evx, const float* __restrict__ evy,
               const float* __restrict__ exv, const float* __restrict__ eyv,
               const float* __restrict__ Win, const float* __restrict__ bin)
{
    float* sE = dsm;                    // 128*68
    float* sW = dsm + 128 * 68;         // 64*68
    float* sQKV = sW + 64 * 68;         // 128*196
    const int tid = threadIdx.x;
    const int lane = tid & 31, wp = tid >> 5;
    const int g = lane >> 2, t = lane & 3;
    const int node0 = blockIdx.x * 32;

    // edges: exact fp32 to gmem, tf32 to smem
    for (int i4 = tid; i4 < 128 * 16; i4 += 128) {
        int r = i4 >> 4, k4 = i4 & 15;
        int node = node0 + (r >> 2), s = r & 3;
        const float* base = (s == 0) ? evx : (s == 1) ? evy : (s == 2) ? exv : eyv;
        float4 v = ((const float4*)(base + (size_t)node * 64))[k4];
        ((float4*)(g_edges + (size_t)(node0 * 4 + r) * 64))[k4] = v;
        *(float4*)(sE + r * 68 + k4 * 4) = tf32x4(v);
    }

#pragma unroll 1
    for (int wc = 0; wc < 3; wc++) {
        __syncthreads();
        for (int i4 = tid; i4 < 64 * 16; i4 += 128) {
            int c = i4 >> 4, k4 = i4 & 15;
            *(float4*)(sW + c * 68 + k4 * 4) =
                tf32x4(*(const float4*)(Win + (size_t)(wc * 64 + c) * 64 + k4 * 4));
        }
        __syncthreads();

        float acc[2][8][4];
#pragma unroll
        for (int m = 0; m < 2; m++)
#pragma unroll
            for (int n = 0; n < 8; n++)
#pragma unroll
                for (int i = 0; i < 4; i++) acc[m][n][i] = 0.0f;
#pragma unroll
        for (int k8 = 0; k8 < 8; k8++) {
            int kb = k8 * 8;
            unsigned a[2][4], bb[8][2];
#pragma unroll
            for (int m = 0; m < 2; m++) {
                int R = wp * 32 + m * 16;
                a[m][0] = __float_as_uint(sE[(R + g) * 68 + kb + t]);
                a[m][1] = __float_as_uint(sE[(R + g + 8) * 68 + kb + t]);
                a[m][2] = __float_as_uint(sE[(R + g) * 68 + kb + t + 4]);
                a[m][3] = __float_as_uint(sE[(R + g + 8) * 68 + kb + t + 4]);
            }
#pragma unroll
            for (int n = 0; n < 8; n++) {
                bb[n][0] = __float_as_uint(sW[(n * 8 + g) * 68 + kb + t]);
                bb[n][1] = __float_as_uint(sW[(n * 8 + g) * 68 + kb + t + 4]);
            }
#pragma unroll
            for (int m = 0; m < 2; m++)
#pragma unroll
                for (int n = 0; n < 8; n++) mma8(acc[m][n], a[m], bb[n]);
        }
        // scatter (+bias) into sQKV at col offset wc*64
#pragma unroll
        for (int m = 0; m < 2; m++)
#pragma unroll
            for (int n = 0; n < 8; n++) {
                int R = wp * 32 + m * 16;
                int col = n * 8 + 2 * t;
                float b0 = __ldg(bin + wc * 64 + col);
                float b1 = __ldg(bin + wc * 64 + col + 1);
                *(float2*)(sQKV + (R + g) * 196 + wc * 64 + col) =
                    make_float2(acc[m][n][0] + b0, acc[m][n][1] + b1);
                *(float2*)(sQKV + (R + g + 8) * 196 + wc * 64 + col) =
                    make_float2(acc[m][n][2] + b0, acc[m][n][3] + b1);
            }
    }
    __syncthreads();

    // attention: thread = (node nl, query qs)
    {
        int nl = tid >> 2, qs = tid & 3;
        const float* qrow = sQKV + (nl * 4 + qs) * 196;
        float p[4][4];  // [ks][h]
#pragma unroll
        for (int ks = 0; ks < 4; ks++) {
            const float* krow = sQKV + (nl * 4 + ks) * 196 + 64;
#pragma unroll
            for (int h = 0; h < 4; h++) {
                float d = 0.0f;
#pragma unroll
                for (int e4 = 0; e4 < 4; e4++) {
                    float4 qv = *(const float4*)(qrow + h * 16 + e4 * 4);
                    float4 kv = *(const float4*)(krow + h * 16 + e4 * 4);
                    d += qv.x * kv.x + qv.y * kv.y + qv.z * kv.z + qv.w * kv.w;
                }
                p[ks][h] = d * 0.25f;
            }
        }
#pragma unroll
        for (int h = 0; h < 4; h++) {
            float m = fmaxf(fmaxf(p[0][h], p[1][h]), fmaxf(p[2][h], p[3][h]));
            float s = 0.0f;
#pragma unroll
            for (int ks = 0; ks < 4; ks++) { p[ks][h] = expf(p[ks][h] - m); s += p[ks][h]; }
            float inv = 1.0f / s;
#pragma unroll
            for (int ks = 0; ks < 4; ks++) p[ks][h] *= inv;
        }
        float* orow = g_ao + ((size_t)(node0 + nl) * 4 + qs) * 64;
#pragma unroll
        for (int e4 = 0; e4 < 16; e4++) {
            int h = e4 >> 2;
            float4 o = {0.0f, 0.0f, 0.0f, 0.0f};
#pragma unroll
            for (int ks = 0; ks < 4; ks++) {
                float4 v = *(const float4*)(sQKV + (nl * 4 + ks) * 196 + 128 + e4 * 4);
                float pk = p[ks][h];
                o.x += pk * v.x; o.y += pk * v.y; o.z += pk * v.z; o.w += pk * v.w;
            }
            *(float4*)(orow + e4 * 4) = o;
        }
    }
}

// =====================================================================
// ci stage 1 (scalar, tiny K=10)
// =====================================================================
__global__ void k_ci1(const float* __restrict__ ci, const float* __restrict__ Wc1,
                      const float* __restrict__ bc1)
{
    __shared__ float sW[64 * 10];
    __shared__ float sC[16 * 10];
    const int tid = threadIdx.x;
    const int n0 = blockIdx.x * 16;
    for (int i = tid; i < 640; i += 256) sW[i] = Wc1[i];
    if (tid < 160) sC[tid] = ci[n0 * 10 + tid];
    __syncthreads();
    for (int o = tid; o < 1024; o += 256) {
        int nl = o >> 6, c = o & 63;
        float a = bc1[c];
#pragma unroll
        for (int k = 0; k < 10; k++) a += sC[nl * 10 + k] * sW[c * 10 + k];
        g_ci1[(n0 + nl) * 64 + c] = gelu_f(a);
    }
}

// =====================================================================
// classifier (unchanged, known-good scalar)
// =====================================================================
__global__ void k_cls(const float* __restrict__ Wk1, const float* __restrict__ bk1,
                      const float* __restrict__ Wk2, const float* __restrict__ bk2,
                      float* __restrict__ out)
{
    __shared__ __align__(16) float sA[64 * SD];
    __shared__ __align__(16) float sW[64 * SD];
    __shared__ float sW2[8 * 65];
    const int tid = threadIdx.x;
    const int n0 = blockIdx.x * 64;
    const int rty = tid >> 4, rtx = tid & 15;
    const float4* sA4 = (const float4*)sA;
    const float4* sW4 = (const float4*)sW;

    for (int i4 = tid; i4 < 64 * 16; i4 += 256) {
        int r = i4 >> 4, kq = i4 & 15;
        ((float4*)(sA + r * SD))[kq] = ((const float4*)(g_merged + (size_t)(n0 + r) * 64))[kq];
        ((float4*)(sW + r * SD))[kq] = ((const float4*)(Wk1 + r * 64))[kq];
    }
    for (int i = tid; i < 512; i += 256) {
        int c = i >> 6, k = i & 63;
        sW2[c * 65 + k] = Wk2[i];
    }
    __syncthreads();

    float acc[4][4];
#pragma unroll
    for (int j = 0; j < 4; j++)
#pragma unroll
        for (int i = 0; i < 4; i++) acc[j][i] = 0.0f;
#pragma unroll 4
    for (int k4 = 0; k4 < 16; k4++) {
        float4 a[4], w[4];
#pragma unroll
        for (int j = 0; j < 4; j++) a[j] = sA4[(rty * 4 + j) * SD4 + k4];
#pragma unroll
        for (int i = 0; i < 4; i++) w[i] = sW4[(rtx + 16 * i) * SD4 + k4];
#pragma unroll
        for (int j = 0; j < 4; j++)
#pragma unroll
            for (int i = 0; i < 4; i++) {
                acc[j][i] = fmaf(a[j].x, w[i].x, acc[j][i]);
                acc[j][i] = fmaf(a[j].y, w[i].y, acc[j][i]);
                acc[j][i] = fmaf(a[j].z, w[i].z, acc[j][i]);
                acc[j][i] = fmaf(a[j].w, w[i].w, acc[j][i]);
            }
    }
    __syncthreads();
#pragma unroll
    for (int j = 0; j < 4; j++)
#pragma unroll
        for (int i = 0; i < 4; i++) {
            int r = rty * 4 + j, c = rtx + 16 * i;
            sA[r * SD + c] = gelu_f(acc[j][i] + bk1[c]);
        }
    __syncthreads();

    int r = tid & 63, oc0 = (tid >> 6) * 2;
    float o0 = bk2[oc0], o1 = bk2[oc0 + 1];
#pragma unroll 8
    for (int k = 0; k < 64; k++) {
        float h = sA[r * SD + k];
        o0 += h * sW2[oc0 * 65 + k];
        o1 += h * sW2[(oc0 + 1) * 65 + k];
    }
    out[(n0 + r) * 8 + oc0] = o0;
    out[(n0 + r) * 8 + oc0 + 1] = o1;
}

// =====================================================================
extern "C" void kernel_launch(void* const* d_in, const int* in_sizes, int n_in,
                              void* d_out, int out_size)
{
    const float* evx  = (const float*)d_in[0];
    const float* evy  = (const float*)d_in[1];
    const float* exv  = (const float*)d_in[2];
    const float* eyv  = (const float*)d_in[3];
    const float* cif  = (const float*)d_in[4];
    const float* W_in = (const float*)d_in[5];
    const float* b_in = (const float*)d_in[6];
    const float* W_out= (const float*)d_in[7];
    const float* b_out= (const float*)d_in[8];
    const float* g_at = (const float*)d_in[9];
    const float* b_at = (const float*)d_in[10];
    const float* Wi1  = (const float*)d_in[11];
    const float* bi1  = (const float*)d_in[12];
    const float* Wi2  = (const float*)d_in[13];
    const float* bi2  = (const float*)d_in[14];
    const float* gi   = (const float*)d_in[15];
    const float* bni  = (const float*)d_in[16];
    const float* Wc1  = (const float*)d_in[17];
    const float* bc1  = (const float*)d_in[18];
    const float* Wc2  = (const float*)d_in[19];
    const float* bc2  = (const float*)d_in[20];
    const float* gc   = (const float*)d_in[21];
    const float* bnc  = (const float*)d_in[22];
    const float* Wm   = (const float*)d_in[23];
    const float* bm   = (const float*)d_in[24];
    const float* gm   = (const float*)d_in[25];
    const float* bnm  = (const float*)d_in[26];
    const float* Wk1  = (const float*)d_in[27];
    const float* bk1  = (const float*)d_in[28];
    const float* Wk2  = (const float*)d_in[29];
    const float* bk2  = (const float*)d_in[30];
    float* out = (float*)d_out;

    const int LIN_SMEM = (128 * 68 + 64 * 68) * 4;                 // 52224
    const int QKV_SMEM = (128 * 68 + 64 * 68 + 128 * 196) * 4;     // 152576
    cudaFuncSetAttribute(k_lin_mma,      cudaFuncAttributeMaxDynamicSharedMemorySize, LIN_SMEM);
    cudaFuncSetAttribute(k_inter_mma,    cudaFuncAttributeMaxDynamicSharedMemorySize, LIN_SMEM);
    cudaFuncSetAttribute(k_qkv_attn_mma, cudaFuncAttributeMaxDynamicSharedMemorySize, QKV_SMEM);

    // 1) QKV + attention (writes g_edges, g_ao)
    k_qkv_attn_mma<<<NN / 32, 128, QKV_SMEM>>>(evx, evy, exv, eyv, W_in, b_in);
    // 2) out-proj + residual + LN -> g_attln (M = 4N)
    k_lin_mma<<<(NN * 4) / 128, 128, LIN_SMEM>>>(SRC_AO, 64, W_out, b_out, RES_EDGES,
                                                 g_at, b_at, DST_ATTLN, 0);
    // 3) interaction hidden -> g_h1
    k_inter_mma<<<dim3(NN / 128, 2), 128, LIN_SMEM>>>(evx, evy, exv, eyv, Wi1, bi1);
    // 4) Wi2 + LN -> g_iemb
    k_lin_mma<<<NN / 128, 128, LIN_SMEM>>>(SRC_H1, 128, Wi2, bi2, RES_NONE,
                                           gi, bni, DST_IEMB, 0);
    // 5) ci stage1 -> g_ci1
    k_ci1<<<NN / 16, 256>>>(cif, Wc1, bc1);
    // 6) Wc2 + LN -> g_cemb
    k_lin_mma<<<NN / 128, 128, LIN_SMEM>>>(SRC_CI1, 64, Wc2, bc2, RES_NONE,
                                           gc, bnc, DST_CEMB, 0);
    // 7) merge (A gathered on the fly) + LN + GELU -> g_merged
    k_lin_mma<<<NN / 128, 128, LIN_SMEM>>>(SRC_MERGE, 192, Wm, bm, RES_NONE,
                                           gm, bnm, DST_MERGED, 1);
    // 8) classifier -> out
    k_cls<<<NN / 64, 256>>>(Wk1, bk1, Wk2, bk2, out);

    (void)in_sizes; (void)n_in; (void)out_size;
}

// round 10
// speedup vs baseline: 1.6649x; 1.0230x over previous
#include <cuda_runtime.h>
#include <math.h>

#define NN 131072
#define SD 68
#define SD4 17

// ---------------- scratch (static device arrays; no allocations) ----------------
__device__ __align__(16) float g_pooled[NN * 64];      // mean over 4 attn rows
__device__ __align__(16) float g_h1[NN * 128];
__device__ __align__(16) float g_ci1[NN * 64];
__device__ __align__(16) float g_iemb[NN * 64];
__device__ __align__(16) float g_cemb[NN * 64];
__device__ __align__(16) float g_merged[NN * 64];

__device__ __forceinline__ float gelu_f(float x) {
    return 0.5f * x * (1.0f + erff(x * 0.70710678118654752f));
}
__device__ __forceinline__ float to_tf32(float x) {
    unsigned r;
    asm("cvt.rna.tf32.f32 %0, %1;" : "=r"(r) : "f"(x));
    return __uint_as_float(r);
}
__device__ __forceinline__ float4 tf32x4(float4 v) {
    v.x = to_tf32(v.x); v.y = to_tf32(v.y); v.z = to_tf32(v.z); v.w = to_tf32(v.w);
    return v;
}
// D(16x8) += A(16x8,row) * B(8x8,col) in tf32, fp32 accum
__device__ __forceinline__ void mma8(float* c, const unsigned* a, const unsigned* b) {
    asm("mma.sync.aligned.m16n8k8.row.col.f32.tf32.tf32.f32 "
        "{%0,%1,%2,%3}, {%4,%5,%6,%7}, {%8,%9}, {%0,%1,%2,%3};"
        : "+f"(c[0]), "+f"(c[1]), "+f"(c[2]), "+f"(c[3])
        : "r"(a[0]), "r"(a[1]), "r"(a[2]), "r"(a[3]), "r"(b[0]), "r"(b[1]));
}

#define SRC_H1    1
#define SRC_CI1   2
#define SRC_MERGE 3
#define DST_IEMB  1
#define DST_CEMB  2
#define DST_MERGED 3

__device__ __forceinline__ float4 loadA4(int id, int row, int col) {
    switch (id) {
        case SRC_H1:  return *(const float4*)(g_h1 + (size_t)row * 128 + col);
        case SRC_CI1: return *(const float4*)(g_ci1 + (size_t)row * 64 + col);
        default: {  // SRC_MERGE: [pooled | iemb | cemb]
            if (col < 64)       return *(const float4*)(g_pooled + (size_t)row * 64 + col);
            else if (col < 128) return *(const float4*)(g_iemb + (size_t)row * 64 + (col - 64));
            else                return *(const float4*)(g_cemb + (size_t)row * 64 + (col - 128));
        }
    }
}
__device__ __forceinline__ float* dstPtr(int id) {
    switch (id) {
        case DST_IEMB:  return g_iemb;
        case DST_CEMB:  return g_cemb;
        default:        return g_merged;
    }
}

extern __shared__ float dsm[];

// =====================================================================
// k_attn_fused: 32 nodes (128 edge rows)/block, 128 threads.
// QKV GEMM (tf32 mma, 3 W-chunks) -> attention -> out-proj GEMM
// -> +bias +residual -> LN -> mean over 4 slots -> g_pooled (N,64).
// dyn smem: sE 128x68 | sW 64x68 | sQKV 128x196   (152576 B)
// =====================================================================
__global__ void __launch_bounds__(128)
k_attn_fused(const float* __restrict__ evx, const float* __restrict__ evy,
             const float* __restrict__ exv, const float* __restrict__ eyv,
             const float* __restrict__ Win, const float* __restrict__ bin,
             const float* __restrict__ Wout, const float* __restrict__ bout,
             const float* __restrict__ g_at, const float* __restrict__ b_at)
{
    float* sE = dsm;                    // 128*68 (tf32 edges)
    float* sW = dsm + 128 * 68;         // 64*68
    float* sQKV = sW + 64 * 68;         // 128*196
    const int tid = threadIdx.x;
    const int lane = tid & 31, wp = tid >> 5;
    const int g = lane >> 2, t = lane & 3;
    const int node0 = blockIdx.x * 32;

    // edges -> tf32 smem (no gmem scratch)
    for (int i4 = tid; i4 < 128 * 16; i4 += 128) {
        int r = i4 >> 4, k4 = i4 & 15;
        int node = node0 + (r >> 2), s = r & 3;
        const float* base = (s == 0) ? evx : (s == 1) ? evy : (s == 2) ? exv : eyv;
        float4 v = ((const float4*)(base + (size_t)node * 64))[k4];
        *(float4*)(sE + r * 68 + k4 * 4) = tf32x4(v);
    }

    // ---- QKV: 3 chunks of W_in ----
#pragma unroll 1
    for (int wc = 0; wc < 3; wc++) {
        __syncthreads();
        for (int i4 = tid; i4 < 64 * 16; i4 += 128) {
            int c = i4 >> 4, k4 = i4 & 15;
            *(float4*)(sW + c * 68 + k4 * 4) =
                tf32x4(*(const float4*)(Win + (size_t)(wc * 64 + c) * 64 + k4 * 4));
        }
        __syncthreads();

        float acc[2][8][4];
#pragma unroll
        for (int m = 0; m < 2; m++)
#pragma unroll
            for (int n = 0; n < 8; n++)
#pragma unroll
                for (int i = 0; i < 4; i++) acc[m][n][i] = 0.0f;
#pragma unroll
        for (int k8 = 0; k8 < 8; k8++) {
            int kb = k8 * 8;
            unsigned a[2][4], bb[8][2];
#pragma unroll
            for (int m = 0; m < 2; m++) {
                int R = wp * 32 + m * 16;
                a[m][0] = __float_as_uint(sE[(R + g) * 68 + kb + t]);
                a[m][1] = __float_as_uint(sE[(R + g + 8) * 68 + kb + t]);
                a[m][2] = __float_as_uint(sE[(R + g) * 68 + kb + t + 4]);
                a[m][3] = __float_as_uint(sE[(R + g + 8) * 68 + kb + t + 4]);
            }
#pragma unroll
            for (int n = 0; n < 8; n++) {
                bb[n][0] = __float_as_uint(sW[(n * 8 + g) * 68 + kb + t]);
                bb[n][1] = __float_as_uint(sW[(n * 8 + g) * 68 + kb + t + 4]);
            }
#pragma unroll
            for (int m = 0; m < 2; m++)
#pragma unroll
                for (int n = 0; n < 8; n++) mma8(acc[m][n], a[m], bb[n]);
        }
        // scatter (+bias) into sQKV at col offset wc*64 (own warp rows only)
#pragma unroll
        for (int m = 0; m < 2; m++)
#pragma unroll
            for (int n = 0; n < 8; n++) {
                int R = wp * 32 + m * 16;
                int col = n * 8 + 2 * t;
                float b0 = __ldg(bin + wc * 64 + col);
                float b1 = __ldg(bin + wc * 64 + col + 1);
                *(float2*)(sQKV + (R + g) * 196 + wc * 64 + col) =
                    make_float2(acc[m][n][0] + b0, acc[m][n][1] + b1);
                *(float2*)(sQKV + (R + g + 8) * 196 + wc * 64 + col) =
                    make_float2(acc[m][n][2] + b0, acc[m][n][3] + b1);
            }
    }
    __syncthreads();

    // ---- attention: thread = (node nl, query qs); writes ao into own Q row ----
    {
        int nl = tid >> 2, qs = tid & 3;
        float* qrow = sQKV + (nl * 4 + qs) * 196;
        float p[4][4];  // [ks][h]
#pragma unroll
        for (int ks = 0; ks < 4; ks++) {
            const float* krow = sQKV + (nl * 4 + ks) * 196 + 64;
#pragma unroll
            for (int h = 0; h < 4; h++) {
                float d = 0.0f;
#pragma unroll
                for (int e4 = 0; e4 < 4; e4++) {
                    float4 qv = *(const float4*)(qrow + h * 16 + e4 * 4);
                    float4 kv = *(const float4*)(krow + h * 16 + e4 * 4);
                    d += qv.x * kv.x + qv.y * kv.y + qv.z * kv.z + qv.w * kv.w;
                }
                p[ks][h] = d * 0.25f;
            }
        }
#pragma unroll
        for (int h = 0; h < 4; h++) {
            float m = fmaxf(fmaxf(p[0][h], p[1][h]), fmaxf(p[2][h], p[3][h]));
            float s = 0.0f;
#pragma unroll
            for (int ks = 0; ks < 4; ks++) { p[ks][h] = expf(p[ks][h] - m); s += p[ks][h]; }
            float inv = 1.0f / s;
#pragma unroll
            for (int ks = 0; ks < 4; ks++) p[ks][h] *= inv;
        }
        // ao -> own Q row (cols 0..63); only this thread ever reads that Q row
#pragma unroll
        for (int e4 = 0; e4 < 16; e4++) {
            int h = e4 >> 2;
            float4 o = {0.0f, 0.0f, 0.0f, 0.0f};
#pragma unroll
            for (int ks = 0; ks < 4; ks++) {
                float4 v = *(const float4*)(sQKV + (nl * 4 + ks) * 196 + 128 + e4 * 4);
                float pk = p[ks][h];
                o.x += pk * v.x; o.y += pk * v.y; o.z += pk * v.z; o.w += pk * v.w;
            }
            *(float4*)(qrow + e4 * 4) = o;
        }
    }
    __syncthreads();

    // ---- out-proj GEMM: A = ao (sQKV cols 0..63, cvt on load), B = Wout ----
    for (int i4 = tid; i4 < 64 * 16; i4 += 128) {
        int c = i4 >> 4, k4 = i4 & 15;
        *(float4*)(sW + c * 68 + k4 * 4) =
            tf32x4(*(const float4*)(Wout + (size_t)c * 64 + k4 * 4));
    }
    __syncthreads();
    {
        float acc[2][8][4];
#pragma unroll
        for (int m = 0; m < 2; m++)
#pragma unroll
            for (int n = 0; n < 8; n++)
#pragma unroll
                for (int i = 0; i < 4; i++) acc[m][n][i] = 0.0f;
#pragma unroll
        for (int k8 = 0; k8 < 8; k8++) {
            int kb = k8 * 8;
            unsigned a[2][4], bb[8][2];
#pragma unroll
            for (int m = 0; m < 2; m++) {
                int R = wp * 32 + m * 16;
                a[m][0] = __float_as_uint(to_tf32(sQKV[(R + g) * 196 + kb + t]));
                a[m][1] = __float_as_uint(to_tf32(sQKV[(R + g + 8) * 196 + kb + t]));
                a[m][2] = __float_as_uint(to_tf32(sQKV[(R + g) * 196 + kb + t + 4]));
                a[m][3] = __float_as_uint(to_tf32(sQKV[(R + g + 8) * 196 + kb + t + 4]));
            }
#pragma unroll
            for (int n = 0; n < 8; n++) {
                bb[n][0] = __float_as_uint(sW[(n * 8 + g) * 68 + kb + t]);
                bb[n][1] = __float_as_uint(sW[(n * 8 + g) * 68 + kb + t + 4]);
            }
#pragma unroll
            for (int m = 0; m < 2; m++)
#pragma unroll
                for (int n = 0; n < 8; n++) mma8(acc[m][n], a[m], bb[n]);
        }
        // scatter into dead K region (cols 64..127) of own warp rows
#pragma unroll
        for (int m = 0; m < 2; m++)
#pragma unroll
            for (int n = 0; n < 8; n++) {
                int R = wp * 32 + m * 16;
                int col = n * 8 + 2 * t;
                *(float2*)(sQKV + (R + g) * 196 + 64 + col) =
                    make_float2(acc[m][n][0], acc[m][n][1]);
                *(float2*)(sQKV + (R + g + 8) * 196 + 64 + col) =
                    make_float2(acc[m][n][2], acc[m][n][3]);
            }
    }
    __syncthreads();

    // params into sW (free now): bout | gamma | beta
    if (tid < 64) {
        sW[tid] = bout[tid];
        sW[64 + tid] = g_at[tid];
        sW[128 + tid] = b_at[tid];
    }
    __syncthreads();

    // ---- epilogue: +bias +residual(edge) -> LN -> store LN row into cols 0..63 ----
    {
        int r = tid;
        int node = node0 + (r >> 2), s = r & 3;
        const float* ebase = ((s == 0) ? evx : (s == 1) ? evy : (s == 2) ? exv : eyv)
                             + (size_t)node * 64;
        float4 cv[16];
#pragma unroll
        for (int k4 = 0; k4 < 16; k4++) {
            float4 c = *(float4*)(sQKV + r * 196 + 64 + k4 * 4);
            float4 e = *(const float4*)(ebase + k4 * 4);
            c.x += sW[k4 * 4 + 0] + e.x;
            c.y += sW[k4 * 4 + 1] + e.y;
            c.z += sW[k4 * 4 + 2] + e.z;
            c.w += sW[k4 * 4 + 3] + e.w;
            cv[k4] = c;
        }
        float s1 = 0.0f, s2 = 0.0f;
#pragma unroll
        for (int k4 = 0; k4 < 16; k4++) {
            s1 += cv[k4].x + cv[k4].y + cv[k4].z + cv[k4].w;
            s2 += cv[k4].x * cv[k4].x + cv[k4].y * cv[k4].y + cv[k4].z * cv[k4].z + cv[k4].w * cv[k4].w;
        }
        float mean = s1 * (1.0f / 64.0f);
        float var = s2 * (1.0f / 64.0f) - mean * mean;
        float rstd = rsqrtf(var + 1e-5f);
#pragma unroll
        for (int k4 = 0; k4 < 16; k4++) {
            float4 o;
            o.x = (cv[k4].x - mean) * rstd * sW[64 + k4 * 4 + 0] + sW[128 + k4 * 4 + 0];
            o.y = (cv[k4].y - mean) * rstd * sW[64 + k4 * 4 + 1] + sW[128 + k4 * 4 + 1];
            o.z = (cv[k4].z - mean) * rstd * sW[64 + k4 * 4 + 2] + sW[128 + k4 * 4 + 2];
            o.w = (cv[k4].w - mean) * rstd * sW[64 + k4 * 4 + 3] + sW[128 + k4 * 4 + 3];
            *(float4*)(sQKV + r * 196 + k4 * 4) = o;   // own row, cols 0..63
        }
    }
    __syncthreads();

    // ---- pooled mean over 4 slots -> g_pooled ----
    if (tid < 32) {
        int nl = tid;
#pragma unroll
        for (int k4 = 0; k4 < 16; k4++) {
            float4 a = *(float4*)(sQKV + (nl * 4 + 0) * 196 + k4 * 4);
            float4 b = *(float4*)(sQKV + (nl * 4 + 1) * 196 + k4 * 4);
            float4 c = *(float4*)(sQKV + (nl * 4 + 2) * 196 + k4 * 4);
            float4 d = *(float4*)(sQKV + (nl * 4 + 3) * 196 + k4 * 4);
            float4 o;
            o.x = 0.25f * (a.x + b.x + c.x + d.x);
            o.y = 0.25f * (a.y + b.y + c.y + d.y);
            o.z = 0.25f * (a.z + b.z + c.z + d.z);
            o.w = 0.25f * (a.w + b.w + c.w + d.w);
            *(float4*)(g_pooled + (size_t)(node0 + nl) * 64 + k4 * 4) = o;
        }
    }
}

// =====================================================================
// k_lin_mma: dst(M,64) = LN(A(M,K)@W^T + b)*gamma+beta, opt GELU
// 128 rows/block, 128 threads, tf32 mma, row-per-thread epilogue
// dyn smem: sA 128x68 | sW 64x68  (52224 B)
// =====================================================================
__global__ void __launch_bounds__(128)
k_lin_mma(int srcId, int K, const float* __restrict__ W, const float* __restrict__ b,
          const float* __restrict__ gamma, const float* __restrict__ beta,
          int dstId, int doGelu)
{
    float* sA = dsm;              // 128*68
    float* sW = dsm + 128 * 68;   // 64*68
    const int tid = threadIdx.x;
    const int lane = tid & 31, wp = tid >> 5;
    const int g = lane >> 2, t = lane & 3;
    const int row0 = blockIdx.x * 128;

    float acc[2][8][4];
#pragma unroll
    for (int m = 0; m < 2; m++)
#pragma unroll
        for (int n = 0; n < 8; n++)
#pragma unroll
            for (int i = 0; i < 4; i++) acc[m][n][i] = 0.0f;

    for (int kc = 0; kc < K; kc += 64) {
        __syncthreads();
        for (int i4 = tid; i4 < 128 * 16; i4 += 128) {
            int r = i4 >> 4, k4 = i4 & 15;
            *(float4*)(sA + r * 68 + k4 * 4) = tf32x4(loadA4(srcId, row0 + r, kc + k4 * 4));
        }
        for (int i4 = tid; i4 < 64 * 16; i4 += 128) {
            int c = i4 >> 4, k4 = i4 & 15;
            *(float4*)(sW + c * 68 + k4 * 4) = tf32x4(*(const float4*)(W + c * K + kc + k4 * 4));
        }
        __syncthreads();
#pragma unroll
        for (int k8 = 0; k8 < 8; k8++) {
            int kb = k8 * 8;
            unsigned a[2][4], bb[8][2];
#pragma unroll
            for (int m = 0; m < 2; m++) {
                int R = wp * 32 + m * 16;
                a[m][0] = __float_as_uint(sA[(R + g) * 68 + kb + t]);
                a[m][1] = __float_as_uint(sA[(R + g + 8) * 68 + kb + t]);
                a[m][2] = __float_as_uint(sA[(R + g) * 68 + kb + t + 4]);
                a[m][3] = __float_as_uint(sA[(R + g + 8) * 68 + kb + t + 4]);
            }
#pragma unroll
            for (int n = 0; n < 8; n++) {
                bb[n][0] = __float_as_uint(sW[(n * 8 + g) * 68 + kb + t]);
                bb[n][1] = __float_as_uint(sW[(n * 8 + g) * 68 + kb + t + 4]);
            }
#pragma unroll
            for (int m = 0; m < 2; m++)
#pragma unroll
                for (int n = 0; n < 8; n++) mma8(acc[m][n], a[m], bb[n]);
        }
    }

#pragma unroll
    for (int m = 0; m < 2; m++)
#pragma unroll
        for (int n = 0; n < 8; n++) {
            int R = wp * 32 + m * 16;
            *(float2*)(sA + (R + g) * 68 + n * 8 + 2 * t)     = make_float2(acc[m][n][0], acc[m][n][1]);
            *(float2*)(sA + (R + g + 8) * 68 + n * 8 + 2 * t) = make_float2(acc[m][n][2], acc[m][n][3]);
        }
    __syncthreads();
    if (tid < 64) {
        sW[tid] = b[tid];
        sW[64 + tid] = gamma[tid];
        sW[128 + tid] = beta[tid];
    }
    __syncthreads();

    int row = row0 + tid;
    float4 cv[16];
#pragma unroll
    for (int k4 = 0; k4 < 16; k4++) {
        cv[k4] = *(float4*)(sA + tid * 68 + k4 * 4);
        cv[k4].x += sW[k4 * 4 + 0];
        cv[k4].y += sW[k4 * 4 + 1];
        cv[k4].z += sW[k4 * 4 + 2];
        cv[k4].w += sW[k4 * 4 + 3];
    }
    float s = 0.0f, ss = 0.0f;
#pragma unroll
    for (int k4 = 0; k4 < 16; k4++) {
        s += cv[k4].x + cv[k4].y + cv[k4].z + cv[k4].w;
        ss += cv[k4].x * cv[k4].x + cv[k4].y * cv[k4].y + cv[k4].z * cv[k4].z + cv[k4].w * cv[k4].w;
    }
    float mean = s * (1.0f / 64.0f);
    float var = ss * (1.0f / 64.0f) - mean * mean;
    float rstd = rsqrtf(var + 1e-5f);
    float* out = dstPtr(dstId);
#pragma unroll
    for (int k4 = 0; k4 < 16; k4++) {
        float4 o;
        o.x = (cv[k4].x - mean) * rstd * sW[64 + k4 * 4 + 0] + sW[128 + k4 * 4 + 0];
        o.y = (cv[k4].y - mean) * rstd * sW[64 + k4 * 4 + 1] + sW[128 + k4 * 4 + 1];
        o.z = (cv[k4].z - mean) * rstd * sW[64 + k4 * 4 + 2] + sW[128 + k4 * 4 + 2];
        o.w = (cv[k4].w - mean) * rstd * sW[64 + k4 * 4 + 3] + sW[128 + k4 * 4 + 3];
        if (doGelu) { o.x = gelu_f(o.x); o.y = gelu_f(o.y); o.z = gelu_f(o.z); o.w = gelu_f(o.w); }
        *(float4*)(out + (size_t)row * 64 + k4 * 4) = o;
    }
}

// =====================================================================
// k_inter_mma: g_h1(N,128) = GELU(inter(N,384)@Wi1^T + bi1); col half via blockIdx.y
// =====================================================================
__global__ void __launch_bounds__(128)
k_inter_mma(const float* __restrict__ evx, const float* __restrict__ evy,
            const float* __restrict__ exv, const float* __restrict__ eyv,
            const float* __restrict__ Wi1, const float* __restrict__ bi1)
{
    float* sA = dsm;
    float* sW = dsm + 128 * 68;
    const int tid = threadIdx.x;
    const int lane = tid & 31, wp = tid >> 5;
    const int g = lane >> 2, t = lane & 3;
    const int n0 = blockIdx.x * 128;
    const int c0 = blockIdx.y * 64;

    float acc[2][8][4];
#pragma unroll
    for (int m = 0; m < 2; m++)
#pragma unroll
        for (int n = 0; n < 8; n++)
#pragma unroll
            for (int i = 0; i < 4; i++) acc[m][n][i] = 0.0f;

#pragma unroll 1
    for (int p = 0; p < 6; p++) {
        const float* Ea; const float* Eb;
        switch (p) {
            case 0: Ea = evx; Eb = evy; break;
            case 1: Ea = evx; Eb = exv; break;
            case 2: Ea = evx; Eb = eyv; break;
            case 3: Ea = evy; Eb = exv; break;
            case 4: Ea = evy; Eb = eyv; break;
            default: Ea = exv; Eb = eyv; break;
        }
        __syncthreads();
        for (int i4 = tid; i4 < 128 * 16; i4 += 128) {
            int r = i4 >> 4, k4 = i4 & 15;
            float4 x = ((const float4*)(Ea + (size_t)(n0 + r) * 64))[k4];
            float4 y = ((const float4*)(Eb + (size_t)(n0 + r) * 64))[k4];
            float4 v; v.x = x.x * y.x; v.y = x.y * y.y; v.z = x.z * y.z; v.w = x.w * y.w;
            *(float4*)(sA + r * 68 + k4 * 4) = tf32x4(v);
        }
        for (int i4 = tid; i4 < 64 * 16; i4 += 128) {
            int c = i4 >> 4, k4 = i4 & 15;
            *(float4*)(sW + c * 68 + k4 * 4) =
                tf32x4(*(const float4*)(Wi1 + (size_t)(c0 + c) * 384 + p * 64 + k4 * 4));
        }
        __syncthreads();
#pragma unroll
        for (int k8 = 0; k8 < 8; k8++) {
            int kb = k8 * 8;
            unsigned a[2][4], bb[8][2];
#pragma unroll
            for (int m = 0; m < 2; m++) {
                int R = wp * 32 + m * 16;
                a[m][0] = __float_as_uint(sA[(R + g) * 68 + kb + t]);
                a[m][1] = __float_as_uint(sA[(R + g + 8) * 68 + kb + t]);
                a[m][2] = __float_as_uint(sA[(R + g) * 68 + kb + t + 4]);
                a[m][3] = __float_as_uint(sA[(R + g + 8) * 68 + kb + t + 4]);
            }
#pragma unroll
            for (int n = 0; n < 8; n++) {
                bb[n][0] = __float_as_uint(sW[(n * 8 + g) * 68 + kb + t]);
                bb[n][1] = __float_as_uint(sW[(n * 8 + g) * 68 + kb + t + 4]);
            }
#pragma unroll
            for (int m = 0; m < 2; m++)
#pragma unroll
                for (int n = 0; n < 8; n++) mma8(acc[m][n], a[m], bb[n]);
        }
    }

#pragma unroll
    for (int m = 0; m < 2; m++)
#pragma unroll
        for (int n = 0; n < 8; n++) {
            int R = wp * 32 + m * 16;
            *(float2*)(sA + (R + g) * 68 + n * 8 + 2 * t)     = make_float2(acc[m][n][0], acc[m][n][1]);
            *(float2*)(sA + (R + g + 8) * 68 + n * 8 + 2 * t) = make_float2(acc[m][n][2], acc[m][n][3]);
        }
    __syncthreads();
    if (tid < 64) sW[tid] = bi1[c0 + tid];
    __syncthreads();

    int row = n0 + tid;
#pragma unroll
    for (int k4 = 0; k4 < 16; k4++) {
        float4 c = *(float4*)(sA + tid * 68 + k4 * 4);
        float4 o;
        o.x = gelu_f(c.x + sW[k4 * 4 + 0]);
        o.y = gelu_f(c.y + sW[k4 * 4 + 1]);
        o.z = gelu_f(c.z + sW[k4 * 4 + 2]);
        o.w = gelu_f(c.w + sW[k4 * 4 + 3]);
        *(float4*)(g_h1 + (size_t)row * 128 + c0 + k4 * 4) = o;
    }
}

// =====================================================================
// ci stage 1 (scalar, tiny K=10)
// =====================================================================
__global__ void k_ci1(const float* __restrict__ ci, const float* __restrict__ Wc1,
                      const float* __restrict__ bc1)
{
    __shared__ float sW[64 * 10];
    __shared__ float sC[16 * 10];
    const int tid = threadIdx.x;
    const int n0 = blockIdx.x * 16;
    for (int i = tid; i < 640; i += 256) sW[i] = Wc1[i];
    if (tid < 160) sC[tid] = ci[n0 * 10 + tid];
    __syncthreads();
    for (int o = tid; o < 1024; o += 256) {
        int nl = o >> 6, c = o & 63;
        float a = bc1[c];
#pragma unroll
        for (int k = 0; k < 10; k++) a += sC[nl * 10 + k] * sW[c * 10 + k];
        g_ci1[(n0 + nl) * 64 + c] = gelu_f(a);
    }
}

// =====================================================================
// classifier (scalar, known-good)
// =====================================================================
__global__ void k_cls(const float* __restrict__ Wk1, const float* __restrict__ bk1,
                      const float* __restrict__ Wk2, const float* __restrict__ bk2,
                      float* __restrict__ out)
{
    __shared__ __align__(16) float sA[64 * SD];
    __shared__ __align__(16) float sW[64 * SD];
    __shared__ float sW2[8 * 65];
    const int tid = threadIdx.x;
    const int n0 = blockIdx.x * 64;
    const int rty = tid >> 4, rtx = tid & 15;
    const float4* sA4 = (const float4*)sA;
    const float4* sW4 = (const float4*)sW;

    for (int i4 = tid; i4 < 64 * 16; i4 += 256) {
        int r = i4 >> 4, kq = i4 & 15;
        ((float4*)(sA + r * SD))[kq] = ((const float4*)(g_merged + (size_t)(n0 + r) * 64))[kq];
        ((float4*)(sW + r * SD))[kq] = ((const float4*)(Wk1 + r * 64))[kq];
    }
    for (int i = tid; i < 512; i += 256) {
        int c = i >> 6, k = i & 63;
        sW2[c * 65 + k] = Wk2[i];
    }
    __syncthreads();

    float acc[4][4];
#pragma unroll
    for (int j = 0; j < 4; j++)
#pragma unroll
        for (int i = 0; i < 4; i++) acc[j][i] = 0.0f;
#pragma unroll 4
    for (int k4 = 0; k4 < 16; k4++) {
        float4 a[4], w[4];
#pragma unroll
        for (int j = 0; j < 4; j++) a[j] = sA4[(rty * 4 + j) * SD4 + k4];
#pragma unroll
        for (int i = 0; i < 4; i++) w[i] = sW4[(rtx + 16 * i) * SD4 + k4];
#pragma unroll
        for (int j = 0; j < 4; j++)
#pragma unroll
            for (int i = 0; i < 4; i++) {
                acc[j][i] = fmaf(a[j].x, w[i].x, acc[j][i]);
                acc[j][i] = fmaf(a[j].y, w[i].y, acc[j][i]);
                acc[j][i] = fmaf(a[j].z, w[i].z, acc[j][i]);
                acc[j][i] = fmaf(a[j].w, w[i].w, acc[j][i]);
            }
    }
    __syncthreads();
#pragma unroll
    for (int j = 0; j < 4; j++)
#pragma unroll
        for (int i = 0; i < 4; i++) {
            int r = rty * 4 + j, c = rtx + 16 * i;
            sA[r * SD + c] = gelu_f(acc[j][i] + bk1[c]);
        }
    __syncthreads();

    int r = tid & 63, oc0 = (tid >> 6) * 2;
    float o0 = bk2[oc0], o1 = bk2[oc0 + 1];
#pragma unroll 8
    for (int k = 0; k < 64; k++) {
        float h = sA[r * SD + k];
        o0 += h * sW2[oc0 * 65 + k];
        o1 += h * sW2[(oc0 + 1) * 65 + k];
    }
    out[(n0 + r) * 8 + oc0] = o0;
    out[(n0 + r) * 8 + oc0 + 1] = o1;
}

// =====================================================================
extern "C" void kernel_launch(void* const* d_in, const int* in_sizes, int n_in,
                              void* d_out, int out_size)
{
    const float* evx  = (const float*)d_in[0];
    const float* evy  = (const float*)d_in[1];
    const float* exv  = (const float*)d_in[2];
    const float* eyv  = (const float*)d_in[3];
    const float* cif  = (const float*)d_in[4];
    const float* W_in = (const float*)d_in[5];
    const float* b_in = (const float*)d_in[6];
    const float* W_out= (const float*)d_in[7];
    const float* b_out= (const float*)d_in[8];
    const float* g_at = (const float*)d_in[9];
    const float* b_at = (const float*)d_in[10];
    const float* Wi1  = (const float*)d_in[11];
    const float* bi1  = (const float*)d_in[12];
    const float* Wi2  = (const float*)d_in[13];
    const float* bi2  = (const float*)d_in[14];
    const float* gi   = (const float*)d_in[15];
    const float* bni  = (const float*)d_in[16];
    const float* Wc1  = (const float*)d_in[17];
    const float* bc1  = (const float*)d_in[18];
    const float* Wc2  = (const float*)d_in[19];
    const float* bc2  = (const float*)d_in[20];
    const float* gc   = (const float*)d_in[21];
    const float* bnc  = (const float*)d_in[22];
    const float* Wm   = (const float*)d_in[23];
    const float* bm   = (const float*)d_in[24];
    const float* gm   = (const float*)d_in[25];
    const float* bnm  = (const float*)d_in[26];
    const float* Wk1  = (const float*)d_in[27];
    const float* bk1  = (const float*)d_in[28];
    const float* Wk2  = (const float*)d_in[29];
    const float* bk2  = (const float*)d_in[30];
    float* out = (float*)d_out;

    const int LIN_SMEM = (128 * 68 + 64 * 68) * 4;                 // 52224
    const int ATT_SMEM = (128 * 68 + 64 * 68 + 128 * 196) * 4;     // 152576
    cudaFuncSetAttribute(k_lin_mma,    cudaFuncAttributeMaxDynamicSharedMemorySize, LIN_SMEM);
    cudaFuncSetAttribute(k_inter_mma,  cudaFuncAttributeMaxDynamicSharedMemorySize, LIN_SMEM);
    cudaFuncSetAttribute(k_attn_fused, cudaFuncAttributeMaxDynamicSharedMemorySize, ATT_SMEM);

    // 1) full attention block -> g_pooled
    k_attn_fused<<<NN / 32, 128, ATT_SMEM>>>(evx, evy, exv, eyv, W_in, b_in,
                                             W_out, b_out, g_at, b_at);
    // 2) interaction hidden -> g_h1
    k_inter_mma<<<dim3(NN / 128, 2), 128, LIN_SMEM>>>(evx, evy, exv, eyv, Wi1, bi1);
    // 3) Wi2 + LN -> g_iemb
    k_lin_mma<<<NN / 128, 128, LIN_SMEM>>>(SRC_H1, 128, Wi2, bi2, gi, bni, DST_IEMB, 0);
    // 4) ci stage1 -> g_ci1
    k_ci1<<<NN / 16, 256>>>(cif, Wc1, bc1);
    // 5) Wc2 + LN -> g_cemb
    k_lin_mma<<<NN / 128, 128, LIN_SMEM>>>(SRC_CI1, 64, Wc2, bc2, gc, bnc, DST_CEMB, 0);
    // 6) merge + LN + GELU -> g_merged
    k_lin_mma<<<NN / 128, 128, LIN_SMEM>>>(SRC_MERGE, 192, Wm, bm, gm, bnm, DST_MERGED, 1);
    // 7) classifier -> out
    k_cls<<<NN / 64, 256>>>(Wk1, bk1, Wk2, bk2, out);

    (void)in_sizes; (void)n_in; (void)out_size;
}

// round 11
// speedup vs baseline: 2.2677x; 1.3621x over previous
#include <cuda_runtime.h>
#include <math.h>

#define NN 131072
#define SD 68
#define SD4 17

// ---------------- scratch (static device arrays; no allocations) ----------------
__device__ __align__(16) float g_pooled[NN * 64];      // mean over 4 attn rows
__device__ __align__(16) float g_h1[NN * 128];
__device__ __align__(16) float g_ci1[NN * 64];
__device__ __align__(16) float g_iemb[NN * 64];
__device__ __align__(16) float g_cemb[NN * 64];
__device__ __align__(16) float g_merged[NN * 64];

__device__ __forceinline__ float gelu_f(float x) {
    return 0.5f * x * (1.0f + erff(x * 0.70710678118654752f));
}
__device__ __forceinline__ float to_tf32(float x) {
    unsigned r;
    asm("cvt.rna.tf32.f32 %0, %1;" : "=r"(r) : "f"(x));
    return __uint_as_float(r);
}
__device__ __forceinline__ float4 tf32x4(float4 v) {
    v.x = to_tf32(v.x); v.y = to_tf32(v.y); v.z = to_tf32(v.z); v.w = to_tf32(v.w);
    return v;
}
// D(16x8) += A(16x8,row) * B(8x8,col) in tf32, fp32 accum
__device__ __forceinline__ void mma8(float* c, const unsigned* a, const unsigned* b) {
    asm("mma.sync.aligned.m16n8k8.row.col.f32.tf32.tf32.f32 "
        "{%0,%1,%2,%3}, {%4,%5,%6,%7}, {%8,%9}, {%0,%1,%2,%3};"
        : "+f"(c[0]), "+f"(c[1]), "+f"(c[2]), "+f"(c[3])
        : "r"(a[0]), "r"(a[1]), "r"(a[2]), "r"(a[3]), "r"(b[0]), "r"(b[1]));
}

#define SRC_H1    1
#define SRC_CI1   2
#define SRC_MERGE 3
#define DST_IEMB  1
#define DST_CEMB  2
#define DST_MERGED 3

__device__ __forceinline__ float4 loadA4(int id, int row, int col) {
    switch (id) {
        case SRC_H1:  return *(const float4*)(g_h1 + (size_t)row * 128 + col);
        case SRC_CI1: return *(const float4*)(g_ci1 + (size_t)row * 64 + col);
        default: {  // SRC_MERGE: [pooled | iemb | cemb]
            if (col < 64)       return *(const float4*)(g_pooled + (size_t)row * 64 + col);
            else if (col < 128) return *(const float4*)(g_iemb + (size_t)row * 64 + (col - 64));
            else                return *(const float4*)(g_cemb + (size_t)row * 64 + (col - 128));
        }
    }
}
__device__ __forceinline__ float* dstPtr(int id) {
    switch (id) {
        case DST_IEMB:  return g_iemb;
        case DST_CEMB:  return g_cemb;
        default:        return g_merged;
    }
}

extern __shared__ float dsm[];

// =====================================================================
// k_attn_fused: 16 nodes (64 edge rows)/block, 128 threads, 3 CTAs/SM.
// tf32 edges staged in sQKV cols 128..191 (V region); QKV GEMM (3 W-chunks,
// V scatter overwrites edges intra-warp) -> attention -> out-proj GEMM
// -> +bias +residual(gmem edges) -> LN -> mean over 4 slots -> g_pooled.
// dyn smem: sW 64x68 | sQKV 64x196   (67584 B)
// =====================================================================
__global__ void __launch_bounds__(128, 3)
k_attn_fused(const float* __restrict__ evx, const float* __restrict__ evy,
             const float* __restrict__ exv, const float* __restrict__ eyv,
             const float* __restrict__ Win, const float* __restrict__ bin,
             const float* __restrict__ Wout, const float* __restrict__ bout,
             const float* __restrict__ g_at, const float* __restrict__ b_at)
{
    float* sW = dsm;                // 64*68
    float* sQKV = dsm + 64 * 68;    // 64*196
    const int tid = threadIdx.x;
    const int lane = tid & 31, wp = tid >> 5;
    const int g = lane >> 2, t = lane & 3;
    const int node0 = blockIdx.x * 16;
    const int R = wp * 16;          // warp's 16-row range

    // edges -> tf32 into sQKV cols 128..191
    for (int i4 = tid; i4 < 64 * 16; i4 += 128) {
        int r = i4 >> 4, k4 = i4 & 15;
        int node = node0 + (r >> 2), s = r & 3;
        const float* base = (s == 0) ? evx : (s == 1) ? evy : (s == 2) ? exv : eyv;
        float4 v = ((const float4*)(base + (size_t)node * 64))[k4];
        *(float4*)(sQKV + r * 196 + 128 + k4 * 4) = tf32x4(v);
    }

    // ---- QKV: 3 chunks of W_in; A = edges in cols 128..191 ----
#pragma unroll 1
    for (int wc = 0; wc < 3; wc++) {
        __syncthreads();
        for (int i4 = tid; i4 < 64 * 16; i4 += 128) {
            int c = i4 >> 4, k4 = i4 & 15;
            *(float4*)(sW + c * 68 + k4 * 4) =
                tf32x4(*(const float4*)(Win + (size_t)(wc * 64 + c) * 64 + k4 * 4));
        }
        __syncthreads();

        float acc[8][4];
#pragma unroll
        for (int n = 0; n < 8; n++)
#pragma unroll
            for (int i = 0; i < 4; i++) acc[n][i] = 0.0f;
#pragma unroll
        for (int k8 = 0; k8 < 8; k8++) {
            int kb = k8 * 8;
            unsigned a[4], bb[8][2];
            a[0] = __float_as_uint(sQKV[(R + g) * 196 + 128 + kb + t]);
            a[1] = __float_as_uint(sQKV[(R + g + 8) * 196 + 128 + kb + t]);
            a[2] = __float_as_uint(sQKV[(R + g) * 196 + 128 + kb + t + 4]);
            a[3] = __float_as_uint(sQKV[(R + g + 8) * 196 + 128 + kb + t + 4]);
#pragma unroll
            for (int n = 0; n < 8; n++) {
                bb[n][0] = __float_as_uint(sW[(n * 8 + g) * 68 + kb + t]);
                bb[n][1] = __float_as_uint(sW[(n * 8 + g) * 68 + kb + t + 4]);
            }
#pragma unroll
            for (int n = 0; n < 8; n++) mma8(acc[n], a, bb[n]);
        }
        // scatter (+bias): wc<2 -> cols wc*64 ; wc==2 -> V overwrites edges
        // (own warp rows only; V region reads by this warp already complete)
        int cbase = (wc < 2) ? wc * 64 : 128;
#pragma unroll
        for (int n = 0; n < 8; n++) {
            int col = n * 8 + 2 * t;
            float b0 = __ldg(bin + wc * 64 + col);
            float b1 = __ldg(bin + wc * 64 + col + 1);
            *(float2*)(sQKV + (R + g) * 196 + cbase + col) =
                make_float2(acc[n][0] + b0, acc[n][1] + b1);
            *(float2*)(sQKV + (R + g + 8) * 196 + cbase + col) =
                make_float2(acc[n][2] + b0, acc[n][3] + b1);
        }
    }
    __syncthreads();

    // ---- attention: 64 threads, thread = (node nl, query qs); ao -> own Q row ----
    if (tid < 64) {
        int nl = tid >> 2, qs = tid & 3;
        float* qrow = sQKV + (nl * 4 + qs) * 196;
        float p[4][4];  // [ks][h]
#pragma unroll
        for (int ks = 0; ks < 4; ks++) {
            const float* krow = sQKV + (nl * 4 + ks) * 196 + 64;
#pragma unroll
            for (int h = 0; h < 4; h++) {
                float d = 0.0f;
#pragma unroll
                for (int e4 = 0; e4 < 4; e4++) {
                    float4 qv = *(const float4*)(qrow + h * 16 + e4 * 4);
                    float4 kv = *(const float4*)(krow + h * 16 + e4 * 4);
                    d += qv.x * kv.x + qv.y * kv.y + qv.z * kv.z + qv.w * kv.w;
                }
                p[ks][h] = d * 0.25f;
            }
        }
#pragma unroll
        for (int h = 0; h < 4; h++) {
            float m = fmaxf(fmaxf(p[0][h], p[1][h]), fmaxf(p[2][h], p[3][h]));
            float s = 0.0f;
#pragma unroll
            for (int ks = 0; ks < 4; ks++) { p[ks][h] = expf(p[ks][h] - m); s += p[ks][h]; }
            float inv = 1.0f / s;
#pragma unroll
            for (int ks = 0; ks < 4; ks++) p[ks][h] *= inv;
        }
#pragma unroll
        for (int e4 = 0; e4 < 16; e4++) {
            int h = e4 >> 2;
            float4 o = {0.0f, 0.0f, 0.0f, 0.0f};
#pragma unroll
            for (int ks = 0; ks < 4; ks++) {
                float4 v = *(const float4*)(sQKV + (nl * 4 + ks) * 196 + 128 + e4 * 4);
                float pk = p[ks][h];
                o.x += pk * v.x; o.y += pk * v.y; o.z += pk * v.z; o.w += pk * v.w;
            }
            *(float4*)(qrow + e4 * 4) = o;
        }
    }
    __syncthreads();

    // ---- out-proj GEMM: A = ao (cols 0..63, cvt on load), B = Wout ----
    for (int i4 = tid; i4 < 64 * 16; i4 += 128) {
        int c = i4 >> 4, k4 = i4 & 15;
        *(float4*)(sW + c * 68 + k4 * 4) =
            tf32x4(*(const float4*)(Wout + (size_t)c * 64 + k4 * 4));
    }
    __syncthreads();
    {
        float acc[8][4];
#pragma unroll
        for (int n = 0; n < 8; n++)
#pragma unroll
            for (int i = 0; i < 4; i++) acc[n][i] = 0.0f;
#pragma unroll
        for (int k8 = 0; k8 < 8; k8++) {
            int kb = k8 * 8;
            unsigned a[4], bb[8][2];
            a[0] = __float_as_uint(to_tf32(sQKV[(R + g) * 196 + kb + t]));
            a[1] = __float_as_uint(to_tf32(sQKV[(R + g + 8) * 196 + kb + t]));
            a[2] = __float_as_uint(to_tf32(sQKV[(R + g) * 196 + kb + t + 4]));
            a[3] = __float_as_uint(to_tf32(sQKV[(R + g + 8) * 196 + kb + t + 4]));
#pragma unroll
            for (int n = 0; n < 8; n++) {
                bb[n][0] = __float_as_uint(sW[(n * 8 + g) * 68 + kb + t]);
                bb[n][1] = __float_as_uint(sW[(n * 8 + g) * 68 + kb + t + 4]);
            }
#pragma unroll
            for (int n = 0; n < 8; n++) mma8(acc[n], a, bb[n]);
        }
        // scatter into dead K region (cols 64..127), own warp rows
#pragma unroll
        for (int n = 0; n < 8; n++) {
            int col = n * 8 + 2 * t;
            *(float2*)(sQKV + (R + g) * 196 + 64 + col) = make_float2(acc[n][0], acc[n][1]);
            *(float2*)(sQKV + (R + g + 8) * 196 + 64 + col) = make_float2(acc[n][2], acc[n][3]);
        }
    }
    __syncthreads();

    // params into sW (free now): bout | gamma | beta
    if (tid < 64) {
        sW[tid] = bout[tid];
        sW[64 + tid] = g_at[tid];
        sW[128 + tid] = b_at[tid];
    }
    __syncthreads();

    // ---- epilogue: +bias +residual(gmem edge) -> LN -> cols 0..63 ----
    if (tid < 64) {
        int r = tid;
        int node = node0 + (r >> 2), s = r & 3;
        const float* ebase = ((s == 0) ? evx : (s == 1) ? evy : (s == 2) ? exv : eyv)
                             + (size_t)node * 64;
        float4 cv[16];
#pragma unroll
        for (int k4 = 0; k4 < 16; k4++) {
            float4 c = *(float4*)(sQKV + r * 196 + 64 + k4 * 4);
            float4 e = *(const float4*)(ebase + k4 * 4);
            c.x += sW[k4 * 4 + 0] + e.x;
            c.y += sW[k4 * 4 + 1] + e.y;
            c.z += sW[k4 * 4 + 2] + e.z;
            c.w += sW[k4 * 4 + 3] + e.w;
            cv[k4] = c;
        }
        float s1 = 0.0f, s2 = 0.0f;
#pragma unroll
        for (int k4 = 0; k4 < 16; k4++) {
            s1 += cv[k4].x + cv[k4].y + cv[k4].z + cv[k4].w;
            s2 += cv[k4].x * cv[k4].x + cv[k4].y * cv[k4].y + cv[k4].z * cv[k4].z + cv[k4].w * cv[k4].w;
        }
        float mean = s1 * (1.0f / 64.0f);
        float var = s2 * (1.0f / 64.0f) - mean * mean;
        float rstd = rsqrtf(var + 1e-5f);
#pragma unroll
        for (int k4 = 0; k4 < 16; k4++) {
            float4 o;
            o.x = (cv[k4].x - mean) * rstd * sW[64 + k4 * 4 + 0] + sW[128 + k4 * 4 + 0];
            o.y = (cv[k4].y - mean) * rstd * sW[64 + k4 * 4 + 1] + sW[128 + k4 * 4 + 1];
            o.z = (cv[k4].z - mean) * rstd * sW[64 + k4 * 4 + 2] + sW[128 + k4 * 4 + 2];
            o.w = (cv[k4].w - mean) * rstd * sW[64 + k4 * 4 + 3] + sW[128 + k4 * 4 + 3];
            *(float4*)(sQKV + r * 196 + k4 * 4) = o;
        }
    }
    __syncthreads();

    // ---- pooled mean over 4 slots -> g_pooled ----
    if (tid < 16) {
        int nl = tid;
#pragma unroll
        for (int k4 = 0; k4 < 16; k4++) {
            float4 a = *(float4*)(sQKV + (nl * 4 + 0) * 196 + k4 * 4);
            float4 b = *(float4*)(sQKV + (nl * 4 + 1) * 196 + k4 * 4);
            float4 c = *(float4*)(sQKV + (nl * 4 + 2) * 196 + k4 * 4);
            float4 d = *(float4*)(sQKV + (nl * 4 + 3) * 196 + k4 * 4);
            float4 o;
            o.x = 0.25f * (a.x + b.x + c.x + d.x);
            o.y = 0.25f * (a.y + b.y + c.y + d.y);
            o.z = 0.25f * (a.z + b.z + c.z + d.z);
            o.w = 0.25f * (a.w + b.w + c.w + d.w);
            *(float4*)(g_pooled + (size_t)(node0 + nl) * 64 + k4 * 4) = o;
        }
    }
}

// =====================================================================
// k_lin_mma: dst(M,64) = LN(A(M,K)@W^T + b)*gamma+beta, opt GELU
// 128 rows/block, 128 threads, tf32 mma, row-per-thread epilogue
// dyn smem: sA 128x68 | sW 64x68  (52224 B)
// =====================================================================
__global__ void __launch_bounds__(128)
k_lin_mma(int srcId, int K, const float* __restrict__ W, const float* __restrict__ b,
          const float* __restrict__ gamma, const float* __restrict__ beta,
          int dstId, int doGelu)
{
    float* sA = dsm;              // 128*68
    float* sW = dsm + 128 * 68;   // 64*68
    const int tid = threadIdx.x;
    const int lane = tid & 31, wp = tid >> 5;
    const int g = lane >> 2, t = lane & 3;
    const int row0 = blockIdx.x * 128;

    float acc[2][8][4];
#pragma unroll
    for (int m = 0; m < 2; m++)
#pragma unroll
        for (int n = 0; n < 8; n++)
#pragma unroll
            for (int i = 0; i < 4; i++) acc[m][n][i] = 0.0f;

    for (int kc = 0; kc < K; kc += 64) {
        __syncthreads();
        for (int i4 = tid; i4 < 128 * 16; i4 += 128) {
            int r = i4 >> 4, k4 = i4 & 15;
            *(float4*)(sA + r * 68 + k4 * 4) = tf32x4(loadA4(srcId, row0 + r, kc + k4 * 4));
        }
        for (int i4 = tid; i4 < 64 * 16; i4 += 128) {
            int c = i4 >> 4, k4 = i4 & 15;
            *(float4*)(sW + c * 68 + k4 * 4) = tf32x4(*(const float4*)(W + c * K + kc + k4 * 4));
        }
        __syncthreads();
#pragma unroll
        for (int k8 = 0; k8 < 8; k8++) {
            int kb = k8 * 8;
            unsigned a[2][4], bb[8][2];
#pragma unroll
            for (int m = 0; m < 2; m++) {
                int R = wp * 32 + m * 16;
                a[m][0] = __float_as_uint(sA[(R + g) * 68 + kb + t]);
                a[m][1] = __float_as_uint(sA[(R + g + 8) * 68 + kb + t]);
                a[m][2] = __float_as_uint(sA[(R + g) * 68 + kb + t + 4]);
                a[m][3] = __float_as_uint(sA[(R + g + 8) * 68 + kb + t + 4]);
            }
#pragma unroll
            for (int n = 0; n < 8; n++) {
                bb[n][0] = __float_as_uint(sW[(n * 8 + g) * 68 + kb + t]);
                bb[n][1] = __float_as_uint(sW[(n * 8 + g) * 68 + kb + t + 4]);
            }
#pragma unroll
            for (int m = 0; m < 2; m++)
#pragma unroll
                for (int n = 0; n < 8; n++) mma8(acc[m][n], a[m], bb[n]);
        }
    }

#pragma unroll
    for (int m = 0; m < 2; m++)
#pragma unroll
        for (int n = 0; n < 8; n++) {
            int R = wp * 32 + m * 16;
            *(float2*)(sA + (R + g) * 68 + n * 8 + 2 * t)     = make_float2(acc[m][n][0], acc[m][n][1]);
            *(float2*)(sA + (R + g + 8) * 68 + n * 8 + 2 * t) = make_float2(acc[m][n][2], acc[m][n][3]);
        }
    __syncthreads();
    if (tid < 64) {
        sW[tid] = b[tid];
        sW[64 + tid] = gamma[tid];
        sW[128 + tid] = beta[tid];
    }
    __syncthreads();

    int row = row0 + tid;
    float4 cv[16];
#pragma unroll
    for (int k4 = 0; k4 < 16; k4++) {
        cv[k4] = *(float4*)(sA + tid * 68 + k4 * 4);
        cv[k4].x += sW[k4 * 4 + 0];
        cv[k4].y += sW[k4 * 4 + 1];
        cv[k4].z += sW[k4 * 4 + 2];
        cv[k4].w += sW[k4 * 4 + 3];
    }
    float s = 0.0f, ss = 0.0f;
#pragma unroll
    for (int k4 = 0; k4 < 16; k4++) {
        s += cv[k4].x + cv[k4].y + cv[k4].z + cv[k4].w;
        ss += cv[k4].x * cv[k4].x + cv[k4].y * cv[k4].y + cv[k4].z * cv[k4].z + cv[k4].w * cv[k4].w;
    }
    float mean = s * (1.0f / 64.0f);
    float var = ss * (1.0f / 64.0f) - mean * mean;
    float rstd = rsqrtf(var + 1e-5f);
    float* out = dstPtr(dstId);
#pragma unroll
    for (int k4 = 0; k4 < 16; k4++) {
        float4 o;
        o.x = (cv[k4].x - mean) * rstd * sW[64 + k4 * 4 + 0] + sW[128 + k4 * 4 + 0];
        o.y = (cv[k4].y - mean) * rstd * sW[64 + k4 * 4 + 1] + sW[128 + k4 * 4 + 1];
        o.z = (cv[k4].z - mean) * rstd * sW[64 + k4 * 4 + 2] + sW[128 + k4 * 4 + 2];
        o.w = (cv[k4].w - mean) * rstd * sW[64 + k4 * 4 + 3] + sW[128 + k4 * 4 + 3];
        if (doGelu) { o.x = gelu_f(o.x); o.y = gelu_f(o.y); o.z = gelu_f(o.z); o.w = gelu_f(o.w); }
        *(float4*)(out + (size_t)row * 64 + k4 * 4) = o;
    }
}

// =====================================================================
// k_inter_mma: g_h1(N,128) = GELU(inter(N,384)@Wi1^T + bi1); col half via blockIdx.y
// =====================================================================
__global__ void __launch_bounds__(128)
k_inter_mma(const float* __restrict__ evx, const float* __restrict__ evy,
            const float* __restrict__ exv, const float* __restrict__ eyv,
            const float* __restrict__ Wi1, const float* __restrict__ bi1)
{
    float* sA = dsm;
    float* sW = dsm + 128 * 68;
    const int tid = threadIdx.x;
    const int lane = tid & 31, wp = tid >> 5;
    const int g = lane >> 2, t = lane & 3;
    const int n0 = blockIdx.x * 128;
    const int c0 = blockIdx.y * 64;

    float acc[2][8][4];
#pragma unroll
    for (int m = 0; m < 2; m++)
#pragma unroll
        for (int n = 0; n < 8; n++)
#pragma unroll
            for (int i = 0; i < 4; i++) acc[m][n][i] = 0.0f;

#pragma unroll 1
    for (int p = 0; p < 6; p++) {
        const float* Ea; const float* Eb;
        switch (p) {
            case 0: Ea = evx; Eb = evy; break;
            case 1: Ea = evx; Eb = exv; break;
            case 2: Ea = evx; Eb = eyv; break;
            case 3: Ea = evy; Eb = exv; break;
            case 4: Ea = evy; Eb = eyv; break;
            default: Ea = exv; Eb = eyv; break;
        }
        __syncthreads();
        for (int i4 = tid; i4 < 128 * 16; i4 += 128) {
            int r = i4 >> 4, k4 = i4 & 15;
            float4 x = ((const float4*)(Ea + (size_t)(n0 + r) * 64))[k4];
            float4 y = ((const float4*)(Eb + (size_t)(n0 + r) * 64))[k4];
            float4 v; v.x = x.x * y.x; v.y = x.y * y.y; v.z = x.z * y.z; v.w = x.w * y.w;
            *(float4*)(sA + r * 68 + k4 * 4) = tf32x4(v);
        }
        for (int i4 = tid; i4 < 64 * 16; i4 += 128) {
            int c = i4 >> 4, k4 = i4 & 15;
            *(float4*)(sW + c * 68 + k4 * 4) =
                tf32x4(*(const float4*)(Wi1 + (size_t)(c0 + c) * 384 + p * 64 + k4 * 4));
        }
        __syncthreads();
#pragma unroll
        for (int k8 = 0; k8 < 8; k8++) {
            int kb = k8 * 8;
            unsigned a[2][4], bb[8][2];
#pragma unroll
            for (int m = 0; m < 2; m++) {
                int R = wp * 32 + m * 16;
                a[m][0] = __float_as_uint(sA[(R + g) * 68 + kb + t]);
                a[m][1] = __float_as_uint(sA[(R + g + 8) * 68 + kb + t]);
                a[m][2] = __float_as_uint(sA[(R + g) * 68 + kb + t + 4]);
                a[m][3] = __float_as_uint(sA[(R + g + 8) * 68 + kb + t + 4]);
            }
#pragma unroll
            for (int n = 0; n < 8; n++) {
                bb[n][0] = __float_as_uint(sW[(n * 8 + g) * 68 + kb + t]);
                bb[n][1] = __float_as_uint(sW[(n * 8 + g) * 68 + kb + t + 4]);
            }
#pragma unroll
            for (int m = 0; m < 2; m++)
#pragma unroll
                for (int n = 0; n < 8; n++) mma8(acc[m][n], a[m], bb[n]);
        }
    }

#pragma unroll
    for (int m = 0; m < 2; m++)
#pragma unroll
        for (int n = 0; n < 8; n++) {
            int R = wp * 32 + m * 16;
            *(float2*)(sA + (R + g) * 68 + n * 8 + 2 * t)     = make_float2(acc[m][n][0], acc[m][n][1]);
            *(float2*)(sA + (R + g + 8) * 68 + n * 8 + 2 * t) = make_float2(acc[m][n][2], acc[m][n][3]);
        }
    __syncthreads();
    if (tid < 64) sW[tid] = bi1[c0 + tid];
    __syncthreads();

    int row = n0 + tid;
#pragma unroll
    for (int k4 = 0; k4 < 16; k4++) {
        float4 c = *(float4*)(sA + tid * 68 + k4 * 4);
        float4 o;
        o.x = gelu_f(c.x + sW[k4 * 4 + 0]);
        o.y = gelu_f(c.y + sW[k4 * 4 + 1]);
        o.z = gelu_f(c.z + sW[k4 * 4 + 2]);
        o.w = gelu_f(c.w + sW[k4 * 4 + 3]);
        *(float4*)(g_h1 + (size_t)row * 128 + c0 + k4 * 4) = o;
    }
}

// =====================================================================
// ci stage 1 (scalar, tiny K=10)
// =====================================================================
__global__ void k_ci1(const float* __restrict__ ci, const float* __restrict__ Wc1,
                      const float* __restrict__ bc1)
{
    __shared__ float sW[64 * 10];
    __shared__ float sC[16 * 10];
    const int tid = threadIdx.x;
    const int n0 = blockIdx.x * 16;
    for (int i = tid; i < 640; i += 256) sW[i] = Wc1[i];
    if (tid < 160) sC[tid] = ci[n0 * 10 + tid];
    __syncthreads();
    for (int o = tid; o < 1024; o += 256) {
        int nl = o >> 6, c = o & 63;
        float a = bc1[c];
#pragma unroll
        for (int k = 0; k < 10; k++) a += sC[nl * 10 + k] * sW[c * 10 + k];
        g_ci1[(n0 + nl) * 64 + c] = gelu_f(a);
    }
}

// =====================================================================
// classifier (scalar, known-good)
// =====================================================================
__global__ void k_cls(const float* __restrict__ Wk1, const float* __restrict__ bk1,
                      const float* __restrict__ Wk2, const float* __restrict__ bk2,
                      float* __restrict__ out)
{
    __shared__ __align__(16) float sA[64 * SD];
    __shared__ __align__(16) float sW[64 * SD];
    __shared__ float sW2[8 * 65];
    const int tid = threadIdx.x;
    const int n0 = blockIdx.x * 64;
    const int rty = tid >> 4, rtx = tid & 15;
    const float4* sA4 = (const float4*)sA;
    const float4* sW4 = (const float4*)sW;

    for (int i4 = tid; i4 < 64 * 16; i4 += 256) {
        int r = i4 >> 4, kq = i4 & 15;
        ((float4*)(sA + r * SD))[kq] = ((const float4*)(g_merged + (size_t)(n0 + r) * 64))[kq];
        ((float4*)(sW + r * SD))[kq] = ((const float4*)(Wk1 + r * 64))[kq];
    }
    for (int i = tid; i < 512; i += 256) {
        int c = i >> 6, k = i & 63;
        sW2[c * 65 + k] = Wk2[i];
    }
    __syncthreads();

    float acc[4][4];
#pragma unroll
    for (int j = 0; j < 4; j++)
#pragma unroll
        for (int i = 0; i < 4; i++) acc[j][i] = 0.0f;
#pragma unroll 4
    for (int k4 = 0; k4 < 16; k4++) {
        float4 a[4], w[4];
#pragma unroll
        for (int j = 0; j < 4; j++) a[j] = sA4[(rty * 4 + j) * SD4 + k4];
#pragma unroll
        for (int i = 0; i < 4; i++) w[i] = sW4[(rtx + 16 * i) * SD4 + k4];
#pragma unroll
        for (int j = 0; j < 4; j++)
#pragma unroll
            for (int i = 0; i < 4; i++) {
                acc[j][i] = fmaf(a[j].x, w[i].x, acc[j][i]);
                acc[j][i] = fmaf(a[j].y, w[i].y, acc[j][i]);
                acc[j][i] = fmaf(a[j].z, w[i].z, acc[j][i]);
                acc[j][i] = fmaf(a[j].w, w[i].w, acc[j][i]);
            }
    }
    __syncthreads();
#pragma unroll
    for (int j = 0; j < 4; j++)
#pragma unroll
        for (int i = 0; i < 4; i++) {
            int r = rty * 4 + j, c = rtx + 16 * i;
            sA[r * SD + c] = gelu_f(acc[j][i] + bk1[c]);
        }
    __syncthreads();

    int r = tid & 63, oc0 = (tid >> 6) * 2;
    float o0 = bk2[oc0], o1 = bk2[oc0 + 1];
#pragma unroll 8
    for (int k = 0; k < 64; k++) {
        float h = sA[r * SD + k];
        o0 += h * sW2[oc0 * 65 + k];
        o1 += h * sW2[(oc0 + 1) * 65 + k];
    }
    out[(n0 + r) * 8 + oc0] = o0;
    out[(n0 + r) * 8 + oc0 + 1] = o1;
}

// =====================================================================
extern "C" void kernel_launch(void* const* d_in, const int* in_sizes, int n_in,
                              void* d_out, int out_size)
{
    const float* evx  = (const float*)d_in[0];
    const float* evy  = (const float*)d_in[1];
    const float* exv  = (const float*)d_in[2];
    const float* eyv  = (const float*)d_in[3];
    const float* cif  = (const float*)d_in[4];
    const float* W_in = (const float*)d_in[5];
    const float* b_in = (const float*)d_in[6];
    const float* W_out= (const float*)d_in[7];
    const float* b_out= (const float*)d_in[8];
    const float* g_at = (const float*)d_in[9];
    const float* b_at = (const float*)d_in[10];
    const float* Wi1  = (const float*)d_in[11];
    const float* bi1  = (const float*)d_in[12];
    const float* Wi2  = (const float*)d_in[13];
    const float* bi2  = (const float*)d_in[14];
    const float* gi   = (const float*)d_in[15];
    const float* bni  = (const float*)d_in[16];
    const float* Wc1  = (const float*)d_in[17];
    const float* bc1  = (const float*)d_in[18];
    const float* Wc2  = (const float*)d_in[19];
    const float* bc2  = (const float*)d_in[20];
    const float* gc   = (const float*)d_in[21];
    const float* bnc  = (const float*)d_in[22];
    const float* Wm   = (const float*)d_in[23];
    const float* bm   = (const float*)d_in[24];
    const float* gm   = (const float*)d_in[25];
    const float* bnm  = (const float*)d_in[26];
    const float* Wk1  = (const float*)d_in[27];
    const float* bk1  = (const float*)d_in[28];
    const float* Wk2  = (const float*)d_in[29];
    const float* bk2  = (const float*)d_in[30];
    float* out = (float*)d_out;

    const int LIN_SMEM = (128 * 68 + 64 * 68) * 4;        // 52224
    const int ATT_SMEM = (64 * 68 + 64 * 196) * 4;        // 67584
    cudaFuncSetAttribute(k_lin_mma,    cudaFuncAttributeMaxDynamicSharedMemorySize, LIN_SMEM);
    cudaFuncSetAttribute(k_inter_mma,  cudaFuncAttributeMaxDynamicSharedMemorySize, LIN_SMEM);
    cudaFuncSetAttribute(k_attn_fused, cudaFuncAttributeMaxDynamicSharedMemorySize, ATT_SMEM);

    // 1) full attention block -> g_pooled
    k_attn_fused<<<NN / 16, 128, ATT_SMEM>>>(evx, evy, exv, eyv, W_in, b_in,
                                             W_out, b_out, g_at, b_at);
    // 2) interaction hidden -> g_h1
    k_inter_mma<<<dim3(NN / 128, 2), 128, LIN_SMEM>>>(evx, evy, exv, eyv, Wi1, bi1);
    // 3) Wi2 + LN -> g_iemb
    k_lin_mma<<<NN / 128, 128, LIN_SMEM>>>(SRC_H1, 128, Wi2, bi2, gi, bni, DST_IEMB, 0);
    // 4) ci stage1 -> g_ci1
    k_ci1<<<NN / 16, 256>>>(cif, Wc1, bc1);
    // 5) Wc2 + LN -> g_cemb
    k_lin_mma<<<NN / 128, 128, LIN_SMEM>>>(SRC_CI1, 64, Wc2, bc2, gc, bnc, DST_CEMB, 0);
    // 6) merge + LN + GELU -> g_merged
    k_lin_mma<<<NN / 128, 128, LIN_SMEM>>>(SRC_MERGE, 192, Wm, bm, gm, bnm, DST_MERGED, 1);
    // 7) classifier -> out
    k_cls<<<NN / 64, 256>>>(Wk1, bk1, Wk2, bk2, out);

    (void)in_sizes; (void)n_in; (void)out_size;
}

// round 12
// speedup vs baseline: 2.3521x; 1.0372x over previous
#include <cuda_runtime.h>
#include <math.h>

#define NN 131072
#define SD 68
#define SD4 17

// ---------------- scratch (static device arrays; no allocations) ----------------
__device__ __align__(16) float g_pooled[NN * 64];      // mean over 4 attn rows
__device__ __align__(16) float g_h1[NN * 128];
__device__ __align__(16) float g_ci1[NN * 64];
__device__ __align__(16) float g_iemb[NN * 64];
__device__ __align__(16) float g_cemb[NN * 64];
__device__ __align__(16) float g_merged[NN * 64];

__device__ __forceinline__ float gelu_f(float x) {
    return 0.5f * x * (1.0f + erff(x * 0.70710678118654752f));
}
__device__ __forceinline__ float to_tf32(float x) {
    unsigned r;
    asm("cvt.rna.tf32.f32 %0, %1;" : "=r"(r) : "f"(x));
    return __uint_as_float(r);
}
__device__ __forceinline__ float4 tf32x4(float4 v) {
    v.x = to_tf32(v.x); v.y = to_tf32(v.y); v.z = to_tf32(v.z); v.w = to_tf32(v.w);
    return v;
}
// D(16x8) += A(16x8,row) * B(8x8,col) in tf32, fp32 accum
__device__ __forceinline__ void mma8(float* c, const unsigned* a, const unsigned* b) {
    asm("mma.sync.aligned.m16n8k8.row.col.f32.tf32.tf32.f32 "
        "{%0,%1,%2,%3}, {%4,%5,%6,%7}, {%8,%9}, {%0,%1,%2,%3};"
        : "+f"(c[0]), "+f"(c[1]), "+f"(c[2]), "+f"(c[3])
        : "r"(a[0]), "r"(a[1]), "r"(a[2]), "r"(a[3]), "r"(b[0]), "r"(b[1]));
}

#define SRC_H1    1
#define SRC_CI1   2
#define SRC_MERGE 3
#define DST_IEMB  1
#define DST_CEMB  2
#define DST_MERGED 3

__device__ __forceinline__ float4 loadA4(int id, int row, int col) {
    switch (id) {
        case SRC_H1:  return *(const float4*)(g_h1 + (size_t)row * 128 + col);
        case SRC_CI1: return *(const float4*)(g_ci1 + (size_t)row * 64 + col);
        default: {  // SRC_MERGE: [pooled | iemb | cemb]
            if (col < 64)       return *(const float4*)(g_pooled + (size_t)row * 64 + col);
            else if (col < 128) return *(const float4*)(g_iemb + (size_t)row * 64 + (col - 64));
            else                return *(const float4*)(g_cemb + (size_t)row * 64 + (col - 128));
        }
    }
}
__device__ __forceinline__ float* dstPtr(int id) {
    switch (id) {
        case DST_IEMB:  return g_iemb;
        case DST_CEMB:  return g_cemb;
        default:        return g_merged;
    }
}

extern __shared__ float dsm[];

// =====================================================================
// k_attn_fused: 16 nodes (64 edge rows)/block, 128 threads, 3 CTAs/SM.
// A-fragments (tf32 edges) preloaded to registers, reused for 3 QKV chunks.
// QKV GEMM -> attention (128 thr, 2 heads/thr) -> out-proj GEMM
// -> +bias +residual(gmem) -> LN (2 thr/row) -> mean -> g_pooled.
// dyn smem: sW 64x68 | sQKV 64x196   (67584 B)
// =====================================================================
__global__ void __launch_bounds__(128, 3)
k_attn_fused(const float* __restrict__ evx, const float* __restrict__ evy,
             const float* __restrict__ exv, const float* __restrict__ eyv,
             const float* __restrict__ Win, const float* __restrict__ bin,
             const float* __restrict__ Wout, const float* __restrict__ bout,
             const float* __restrict__ g_at, const float* __restrict__ b_at)
{
    float* sW = dsm;                // 64*68
    float* sQKV = dsm + 64 * 68;    // 64*196
    const int tid = threadIdx.x;
    const int lane = tid & 31, wp = tid >> 5;
    const int g = lane >> 2, t = lane & 3;
    const int node0 = blockIdx.x * 16;
    const int R = wp * 16;          // warp's 16-row range

    // ---- preload A fragments (tf32 edges) straight from gmem ----
    float af[8][4];
    {
        int r0 = R + g, r1 = R + g + 8;
        const float* base0 = ((r0 & 3) == 0) ? evx : ((r0 & 3) == 1) ? evy
                           : ((r0 & 3) == 2) ? exv : eyv;
        const float* base1 = ((r1 & 3) == 0) ? evx : ((r1 & 3) == 1) ? evy
                           : ((r1 & 3) == 2) ? exv : eyv;
        const float* p0 = base0 + (size_t)(node0 + (r0 >> 2)) * 64;
        const float* p1 = base1 + (size_t)(node0 + (r1 >> 2)) * 64;
#pragma unroll
        for (int k8 = 0; k8 < 8; k8++) {
            int kb = k8 * 8;
            af[k8][0] = to_tf32(__ldg(p0 + kb + t));
            af[k8][1] = to_tf32(__ldg(p1 + kb + t));
            af[k8][2] = to_tf32(__ldg(p0 + kb + t + 4));
            af[k8][3] = to_tf32(__ldg(p1 + kb + t + 4));
        }
    }

    // ---- QKV: 3 chunks of W_in ----
#pragma unroll 1
    for (int wc = 0; wc < 3; wc++) {
        __syncthreads();   // prior readers of sW done (no-op on wc=0)
        for (int i4 = tid; i4 < 64 * 16; i4 += 128) {
            int c = i4 >> 4, k4 = i4 & 15;
            *(float4*)(sW + c * 68 + k4 * 4) =
                tf32x4(*(const float4*)(Win + (size_t)(wc * 64 + c) * 64 + k4 * 4));
        }
        __syncthreads();

        float acc[8][4];
#pragma unroll
        for (int n = 0; n < 8; n++)
#pragma unroll
            for (int i = 0; i < 4; i++) acc[n][i] = 0.0f;
#pragma unroll
        for (int k8 = 0; k8 < 8; k8++) {
            int kb = k8 * 8;
            unsigned bb[8][2];
#pragma unroll
            for (int n = 0; n < 8; n++) {
                bb[n][0] = __float_as_uint(sW[(n * 8 + g) * 68 + kb + t]);
                bb[n][1] = __float_as_uint(sW[(n * 8 + g) * 68 + kb + t + 4]);
            }
            const unsigned* a = (const unsigned*)af[k8];
#pragma unroll
            for (int n = 0; n < 8; n++) mma8(acc[n], a, bb[n]);
        }
        // scatter (+bias): wc<2 -> cols wc*64 ; wc==2 -> V region (cols 128..191)
        int cbase = (wc < 2) ? wc * 64 : 128;
#pragma unroll
        for (int n = 0; n < 8; n++) {
            int col = n * 8 + 2 * t;
            float b0 = __ldg(bin + wc * 64 + col);
            float b1 = __ldg(bin + wc * 64 + col + 1);
            *(float2*)(sQKV + (R + g) * 196 + cbase + col) =
                make_float2(acc[n][0] + b0, acc[n][1] + b1);
            *(float2*)(sQKV + (R + g + 8) * 196 + cbase + col) =
                make_float2(acc[n][2] + b0, acc[n][3] + b1);
        }
    }
    __syncthreads();

    // ---- attention: 128 threads, thread = (node nl, query qs, head-pair hp) ----
    {
        int nl = tid >> 3, qs = (tid >> 1) & 3, hp = tid & 1;
        float* qrow = sQKV + (nl * 4 + qs) * 196;
        float p[4][2];  // [ks][h within pair]
#pragma unroll
        for (int ks = 0; ks < 4; ks++) {
            const float* krow = sQKV + (nl * 4 + ks) * 196 + 64;
#pragma unroll
            for (int hh = 0; hh < 2; hh++) {
                int h = hp * 2 + hh;
                float d = 0.0f;
#pragma unroll
                for (int e4 = 0; e4 < 4; e4++) {
                    float4 qv = *(const float4*)(qrow + h * 16 + e4 * 4);
                    float4 kv = *(const float4*)(krow + h * 16 + e4 * 4);
                    d += qv.x * kv.x + qv.y * kv.y + qv.z * kv.z + qv.w * kv.w;
                }
                p[ks][hh] = d * 0.25f;
            }
        }
#pragma unroll
        for (int hh = 0; hh < 2; hh++) {
            float m = fmaxf(fmaxf(p[0][hh], p[1][hh]), fmaxf(p[2][hh], p[3][hh]));
            float s = 0.0f;
#pragma unroll
            for (int ks = 0; ks < 4; ks++) { p[ks][hh] = expf(p[ks][hh] - m); s += p[ks][hh]; }
            float inv = 1.0f / s;
#pragma unroll
            for (int ks = 0; ks < 4; ks++) p[ks][hh] *= inv;
        }
        // ao -> own row, cols hp*32..hp*32+31 (e4 = hp*8 .. hp*8+7)
#pragma unroll
        for (int e = 0; e < 8; e++) {
            int e4 = hp * 8 + e;
            int hh = e >> 2;     // h = e4>>2 = hp*2 + (e>>2)
            float4 o = {0.0f, 0.0f, 0.0f, 0.0f};
#pragma unroll
            for (int ks = 0; ks < 4; ks++) {
                float4 v = *(const float4*)(sQKV + (nl * 4 + ks) * 196 + 128 + e4 * 4);
                float pk = p[ks][hh];
                o.x += pk * v.x; o.y += pk * v.y; o.z += pk * v.z; o.w += pk * v.w;
            }
            *(float4*)(qrow + e4 * 4) = o;
        }
    }
    __syncthreads();

    // ---- out-proj GEMM: A = ao (cols 0..63, cvt on load), B = Wout ----
    for (int i4 = tid; i4 < 64 * 16; i4 += 128) {
        int c = i4 >> 4, k4 = i4 & 15;
        *(float4*)(sW + c * 68 + k4 * 4) =
            tf32x4(*(const float4*)(Wout + (size_t)c * 64 + k4 * 4));
    }
    __syncthreads();
    {
        float acc[8][4];
#pragma unroll
        for (int n = 0; n < 8; n++)
#pragma unroll
            for (int i = 0; i < 4; i++) acc[n][i] = 0.0f;
#pragma unroll
        for (int k8 = 0; k8 < 8; k8++) {
            int kb = k8 * 8;
            unsigned a[4], bb[8][2];
            a[0] = __float_as_uint(to_tf32(sQKV[(R + g) * 196 + kb + t]));
            a[1] = __float_as_uint(to_tf32(sQKV[(R + g + 8) * 196 + kb + t]));
            a[2] = __float_as_uint(to_tf32(sQKV[(R + g) * 196 + kb + t + 4]));
            a[3] = __float_as_uint(to_tf32(sQKV[(R + g + 8) * 196 + kb + t + 4]));
#pragma unroll
            for (int n = 0; n < 8; n++) {
                bb[n][0] = __float_as_uint(sW[(n * 8 + g) * 68 + kb + t]);
                bb[n][1] = __float_as_uint(sW[(n * 8 + g) * 68 + kb + t + 4]);
            }
#pragma unroll
            for (int n = 0; n < 8; n++) mma8(acc[n], a, bb[n]);
        }
        // scatter into dead K region (cols 64..127), own warp rows
#pragma unroll
        for (int n = 0; n < 8; n++) {
            int col = n * 8 + 2 * t;
            *(float2*)(sQKV + (R + g) * 196 + 64 + col) = make_float2(acc[n][0], acc[n][1]);
            *(float2*)(sQKV + (R + g + 8) * 196 + 64 + col) = make_float2(acc[n][2], acc[n][3]);
        }
    }
    __syncthreads();

    // params into sW (free now): bout | gamma | beta
    if (tid < 64) {
        sW[tid] = bout[tid];
        sW[64 + tid] = g_at[tid];
        sW[128 + tid] = b_at[tid];
    }
    __syncthreads();

    // ---- epilogue: 2 threads/row; +bias +residual(gmem) -> LN -> cols 0..63 ----
    {
        int r = tid >> 1, ch = tid & 1;
        int c0 = ch * 32;                    // 8 float4 quads
        int node = node0 + (r >> 2), s = r & 3;
        const float* ebase = ((s == 0) ? evx : (s == 1) ? evy : (s == 2) ? exv : eyv)
                             + (size_t)node * 64;
        float4 cv[8];
#pragma unroll
        for (int q = 0; q < 8; q++) {
            int c = c0 + q * 4;
            float4 v = *(float4*)(sQKV + r * 196 + 64 + c);
            float4 e = *(const float4*)(ebase + c);
            v.x += sW[c + 0] + e.x;
            v.y += sW[c + 1] + e.y;
            v.z += sW[c + 2] + e.z;
            v.w += sW[c + 3] + e.w;
            cv[q] = v;
        }
        float s1 = 0.0f, s2 = 0.0f;
#pragma unroll
        for (int q = 0; q < 8; q++) {
            s1 += cv[q].x + cv[q].y + cv[q].z + cv[q].w;
            s2 += cv[q].x * cv[q].x + cv[q].y * cv[q].y + cv[q].z * cv[q].z + cv[q].w * cv[q].w;
        }
        s1 += __shfl_xor_sync(0xffffffffu, s1, 1, 2);
        s2 += __shfl_xor_sync(0xffffffffu, s2, 1, 2);
        float mean = s1 * (1.0f / 64.0f);
        float var = s2 * (1.0f / 64.0f) - mean * mean;
        float rstd = rsqrtf(var + 1e-5f);
#pragma unroll
        for (int q = 0; q < 8; q++) {
            int c = c0 + q * 4;
            float4 o;
            o.x = (cv[q].x - mean) * rstd * sW[64 + c + 0] + sW[128 + c + 0];
            o.y = (cv[q].y - mean) * rstd * sW[64 + c + 1] + sW[128 + c + 1];
            o.z = (cv[q].z - mean) * rstd * sW[64 + c + 2] + sW[128 + c + 2];
            o.w = (cv[q].w - mean) * rstd * sW[64 + c + 3] + sW[128 + c + 3];
            *(float4*)(sQKV + r * 196 + c) = o;
        }
    }
    __syncthreads();

    // ---- pooled mean over 4 slots -> g_pooled (32 threads, half-row each) ----
    if (tid < 32) {
        int nl = tid >> 1, ch = tid & 1;
#pragma unroll
        for (int q = 0; q < 8; q++) {
            int c = ch * 32 + q * 4;
            float4 a = *(float4*)(sQKV + (nl * 4 + 0) * 196 + c);
            float4 b = *(float4*)(sQKV + (nl * 4 + 1) * 196 + c);
            float4 cc = *(float4*)(sQKV + (nl * 4 + 2) * 196 + c);
            float4 d = *(float4*)(sQKV + (nl * 4 + 3) * 196 + c);
            float4 o;
            o.x = 0.25f * (a.x + b.x + cc.x + d.x);
            o.y = 0.25f * (a.y + b.y + cc.y + d.y);
            o.z = 0.25f * (a.z + b.z + cc.z + d.z);
            o.w = 0.25f * (a.w + b.w + cc.w + d.w);
            *(float4*)(g_pooled + (size_t)(node0 + nl) * 64 + c) = o;
        }
    }
}

// =====================================================================
// k_lin_mma: dst(M,64) = LN(A(M,K)@W^T + b)*gamma+beta, opt GELU
// 128 rows/block, 128 threads, tf32 mma, row-per-thread epilogue
// dyn smem: sA 128x68 | sW 64x68  (52224 B)
// =====================================================================
__global__ void __launch_bounds__(128)
k_lin_mma(int srcId, int K, const float* __restrict__ W, const float* __restrict__ b,
          const float* __restrict__ gamma, const float* __restrict__ beta,
          int dstId, int doGelu)
{
    float* sA = dsm;              // 128*68
    float* sW = dsm + 128 * 68;   // 64*68
    const int tid = threadIdx.x;
    const int lane = tid & 31, wp = tid >> 5;
    const int g = lane >> 2, t = lane & 3;
    const int row0 = blockIdx.x * 128;

    float acc[2][8][4];
#pragma unroll
    for (int m = 0; m < 2; m++)
#pragma unroll
        for (int n = 0; n < 8; n++)
#pragma unroll
            for (int i = 0; i < 4; i++) acc[m][n][i] = 0.0f;

    for (int kc = 0; kc < K; kc += 64) {
        __syncthreads();
        for (int i4 = tid; i4 < 128 * 16; i4 += 128) {
            int r = i4 >> 4, k4 = i4 & 15;
            *(float4*)(sA + r * 68 + k4 * 4) = tf32x4(loadA4(srcId, row0 + r, kc + k4 * 4));
        }
        for (int i4 = tid; i4 < 64 * 16; i4 += 128) {
            int c = i4 >> 4, k4 = i4 & 15;
            *(float4*)(sW + c * 68 + k4 * 4) = tf32x4(*(const float4*)(W + c * K + kc + k4 * 4));
        }
        __syncthreads();
#pragma unroll
        for (int k8 = 0; k8 < 8; k8++) {
            int kb = k8 * 8;
            unsigned a[2][4], bb[8][2];
#pragma unroll
            for (int m = 0; m < 2; m++) {
                int R = wp * 32 + m * 16;
                a[m][0] = __float_as_uint(sA[(R + g) * 68 + kb + t]);
                a[m][1] = __float_as_uint(sA[(R + g + 8) * 68 + kb + t]);
                a[m][2] = __float_as_uint(sA[(R + g) * 68 + kb + t + 4]);
                a[m][3] = __float_as_uint(sA[(R + g + 8) * 68 + kb + t + 4]);
            }
#pragma unroll
            for (int n = 0; n < 8; n++) {
                bb[n][0] = __float_as_uint(sW[(n * 8 + g) * 68 + kb + t]);
                bb[n][1] = __float_as_uint(sW[(n * 8 + g) * 68 + kb + t + 4]);
            }
#pragma unroll
            for (int m = 0; m < 2; m++)
#pragma unroll
                for (int n = 0; n < 8; n++) mma8(acc[m][n], a[m], bb[n]);
        }
    }

#pragma unroll
    for (int m = 0; m < 2; m++)
#pragma unroll
        for (int n = 0; n < 8; n++) {
            int R = wp * 32 + m * 16;
            *(float2*)(sA + (R + g) * 68 + n * 8 + 2 * t)     = make_float2(acc[m][n][0], acc[m][n][1]);
            *(float2*)(sA + (R + g + 8) * 68 + n * 8 + 2 * t) = make_float2(acc[m][n][2], acc[m][n][3]);
        }
    __syncthreads();
    if (tid < 64) {
        sW[tid] = b[tid];
        sW[64 + tid] = gamma[tid];
        sW[128 + tid] = beta[tid];
    }
    __syncthreads();

    int row = row0 + tid;
    float4 cv[16];
#pragma unroll
    for (int k4 = 0; k4 < 16; k4++) {
        cv[k4] = *(float4*)(sA + tid * 68 + k4 * 4);
        cv[k4].x += sW[k4 * 4 + 0];
        cv[k4].y += sW[k4 * 4 + 1];
        cv[k4].z += sW[k4 * 4 + 2];
        cv[k4].w += sW[k4 * 4 + 3];
    }
    float s = 0.0f, ss = 0.0f;
#pragma unroll
    for (int k4 = 0; k4 < 16; k4++) {
        s += cv[k4].x + cv[k4].y + cv[k4].z + cv[k4].w;
        ss += cv[k4].x * cv[k4].x + cv[k4].y * cv[k4].y + cv[k4].z * cv[k4].z + cv[k4].w * cv[k4].w;
    }
    float mean = s * (1.0f / 64.0f);
    float var = ss * (1.0f / 64.0f) - mean * mean;
    float rstd = rsqrtf(var + 1e-5f);
    float* out = dstPtr(dstId);
#pragma unroll
    for (int k4 = 0; k4 < 16; k4++) {
        float4 o;
        o.x = (cv[k4].x - mean) * rstd * sW[64 + k4 * 4 + 0] + sW[128 + k4 * 4 + 0];
        o.y = (cv[k4].y - mean) * rstd * sW[64 + k4 * 4 + 1] + sW[128 + k4 * 4 + 1];
        o.z = (cv[k4].z - mean) * rstd * sW[64 + k4 * 4 + 2] + sW[128 + k4 * 4 + 2];
        o.w = (cv[k4].w - mean) * rstd * sW[64 + k4 * 4 + 3] + sW[128 + k4 * 4 + 3];
        if (doGelu) { o.x = gelu_f(o.x); o.y = gelu_f(o.y); o.z = gelu_f(o.z); o.w = gelu_f(o.w); }
        *(float4*)(out + (size_t)row * 64 + k4 * 4) = o;
    }
}

// =====================================================================
// k_inter_mma: g_h1(N,128) = GELU(inter(N,384)@Wi1^T + bi1); col half via blockIdx.y
// =====================================================================
__global__ void __launch_bounds__(128)
k_inter_mma(const float* __restrict__ evx, const float* __restrict__ evy,
            const float* __restrict__ exv, const float* __restrict__ eyv,
            const float* __restrict__ Wi1, const float* __restrict__ bi1)
{
    float* sA = dsm;
    float* sW = dsm + 128 * 68;
    const int tid = threadIdx.x;
    const int lane = tid & 31, wp = tid >> 5;
    const int g = lane >> 2, t = lane & 3;
    const int n0 = blockIdx.x * 128;
    const int c0 = blockIdx.y * 64;

    float acc[2][8][4];
#pragma unroll
    for (int m = 0; m < 2; m++)
#pragma unroll
        for (int n = 0; n < 8; n++)
#pragma unroll
            for (int i = 0; i < 4; i++) acc[m][n][i] = 0.0f;

#pragma unroll 1
    for (int p = 0; p < 6; p++) {
        const float* Ea; const float* Eb;
        switch (p) {
            case 0: Ea = evx; Eb = evy; break;
            case 1: Ea = evx; Eb = exv; break;
            case 2: Ea = evx; Eb = eyv; break;
            case 3: Ea = evy; Eb = exv; break;
            case 4: Ea = evy; Eb = eyv; break;
            default: Ea = exv; Eb = eyv; break;
        }
        __syncthreads();
        for (int i4 = tid; i4 < 128 * 16; i4 += 128) {
            int r = i4 >> 4, k4 = i4 & 15;
            float4 x = ((const float4*)(Ea + (size_t)(n0 + r) * 64))[k4];
            float4 y = ((const float4*)(Eb + (size_t)(n0 + r) * 64))[k4];
            float4 v; v.x = x.x * y.x; v.y = x.y * y.y; v.z = x.z * y.z; v.w = x.w * y.w;
            *(float4*)(sA + r * 68 + k4 * 4) = tf32x4(v);
        }
        for (int i4 = tid; i4 < 64 * 16; i4 += 128) {
            int c = i4 >> 4, k4 = i4 & 15;
            *(float4*)(sW + c * 68 + k4 * 4) =
                tf32x4(*(const float4*)(Wi1 + (size_t)(c0 + c) * 384 + p * 64 + k4 * 4));
        }
        __syncthreads();
#pragma unroll
        for (int k8 = 0; k8 < 8; k8++) {
            int kb = k8 * 8;
            unsigned a[2][4], bb[8][2];
#pragma unroll
            for (int m = 0; m < 2; m++) {
                int R = wp * 32 + m * 16;
                a[m][0] = __float_as_uint(sA[(R + g) * 68 + kb + t]);
                a[m][1] = __float_as_uint(sA[(R + g + 8) * 68 + kb + t]);
                a[m][2] = __float_as_uint(sA[(R + g) * 68 + kb + t + 4]);
                a[m][3] = __float_as_uint(sA[(R + g + 8) * 68 + kb + t + 4]);
            }
#pragma unroll
            for (int n = 0; n < 8; n++) {
                bb[n][0] = __float_as_uint(sW[(n * 8 + g) * 68 + kb + t]);
                bb[n][1] = __float_as_uint(sW[(n * 8 + g) * 68 + kb + t + 4]);
            }
#pragma unroll
            for (int m = 0; m < 2; m++)
#pragma unroll
                for (int n = 0; n < 8; n++) mma8(acc[m][n], a[m], bb[n]);
        }
    }

#pragma unroll
    for (int m = 0; m < 2; m++)
#pragma unroll
        for (int n = 0; n < 8; n++) {
            int R = wp * 32 + m * 16;
            *(float2*)(sA + (R + g) * 68 + n * 8 + 2 * t)     = make_float2(acc[m][n][0], acc[m][n][1]);
            *(float2*)(sA + (R + g + 8) * 68 + n * 8 + 2 * t) = make_float2(acc[m][n][2], acc[m][n][3]);
        }
    __syncthreads();
    if (tid < 64) sW[tid] = bi1[c0 + tid];
    __syncthreads();

    int row = n0 + tid;
#pragma unroll
    for (int k4 = 0; k4 < 16; k4++) {
        float4 c = *(float4*)(sA + tid * 68 + k4 * 4);
        float4 o;
        o.x = gelu_f(c.x + sW[k4 * 4 + 0]);
        o.y = gelu_f(c.y + sW[k4 * 4 + 1]);
        o.z = gelu_f(c.z + sW[k4 * 4 + 2]);
        o.w = gelu_f(c.w + sW[k4 * 4 + 3]);
        *(float4*)(g_h1 + (size_t)row * 128 + c0 + k4 * 4) = o;
    }
}

// =====================================================================
// ci stage 1 (scalar, tiny K=10)
// =====================================================================
__global__ void k_ci1(const float* __restrict__ ci, const float* __restrict__ Wc1,
                      const float* __restrict__ bc1)
{
    __shared__ float sW[64 * 10];
    __shared__ float sC[16 * 10];
    const int tid = threadIdx.x;
    const int n0 = blockIdx.x * 16;
    for (int i = tid; i < 640; i += 256) sW[i] = Wc1[i];
    if (tid < 160) sC[tid] = ci[n0 * 10 + tid];
    __syncthreads();
    for (int o = tid; o < 1024; o += 256) {
        int nl = o >> 6, c = o & 63;
        float a = bc1[c];
#pragma unroll
        for (int k = 0; k < 10; k++) a += sC[nl * 10 + k] * sW[c * 10 + k];
        g_ci1[(n0 + nl) * 64 + c] = gelu_f(a);
    }
}

// =====================================================================
// classifier (scalar, known-good)
// =====================================================================
__global__ void k_cls(const float* __restrict__ Wk1, const float* __restrict__ bk1,
                      const float* __restrict__ Wk2, const float* __restrict__ bk2,
                      float* __restrict__ out)
{
    __shared__ __align__(16) float sA[64 * SD];
    __shared__ __align__(16) float sW[64 * SD];
    __shared__ float sW2[8 * 65];
    const int tid = threadIdx.x;
    const int n0 = blockIdx.x * 64;
    const int rty = tid >> 4, rtx = tid & 15;
    const float4* sA4 = (const float4*)sA;
    const float4* sW4 = (const float4*)sW;

    for (int i4 = tid; i4 < 64 * 16; i4 += 256) {
        int r = i4 >> 4, kq = i4 & 15;
        ((float4*)(sA + r * SD))[kq] = ((const float4*)(g_merged + (size_t)(n0 + r) * 64))[kq];
        ((float4*)(sW + r * SD))[kq] = ((const float4*)(Wk1 + r * 64))[kq];
    }
    for (int i = tid; i < 512; i += 256) {
        int c = i >> 6, k = i & 63;
        sW2[c * 65 + k] = Wk2[i];
    }
    __syncthreads();

    float acc[4][4];
#pragma unroll
    for (int j = 0; j < 4; j++)
#pragma unroll
        for (int i = 0; i < 4; i++) acc[j][i] = 0.0f;
#pragma unroll 4
    for (int k4 = 0; k4 < 16; k4++) {
        float4 a[4], w[4];
#pragma unroll
        for (int j = 0; j < 4; j++) a[j] = sA4[(rty * 4 + j) * SD4 + k4];
#pragma unroll
        for (int i = 0; i < 4; i++) w[i] = sW4[(rtx + 16 * i) * SD4 + k4];
#pragma unroll
        for (int j = 0; j < 4; j++)
#pragma unroll
            for (int i = 0; i < 4; i++) {
                acc[j][i] = fmaf(a[j].x, w[i].x, acc[j][i]);
                acc[j][i] = fmaf(a[j].y, w[i].y, acc[j][i]);
                acc[j][i] = fmaf(a[j].z, w[i].z, acc[j][i]);
                acc[j][i] = fmaf(a[j].w, w[i].w, acc[j][i]);
            }
    }
    __syncthreads();
#pragma unroll
    for (int j = 0; j < 4; j++)
#pragma unroll
        for (int i = 0; i < 4; i++) {
            int r = rty * 4 + j, c = rtx + 16 * i;
            sA[r * SD + c] = gelu_f(acc[j][i] + bk1[c]);
        }
    __syncthreads();

    int r = tid & 63, oc0 = (tid >> 6) * 2;
    float o0 = bk2[oc0], o1 = bk2[oc0 + 1];
#pragma unroll 8
    for (int k = 0; k < 64; k++) {
        float h = sA[r * SD + k];
        o0 += h * sW2[oc0 * 65 + k];
        o1 += h * sW2[(oc0 + 1) * 65 + k];
    }
    out[(n0 + r) * 8 + oc0] = o0;
    out[(n0 + r) * 8 + oc0 + 1] = o1;
}

// =====================================================================
extern "C" void kernel_launch(void* const* d_in, const int* in_sizes, int n_in,
                              void* d_out, int out_size)
{
    const float* evx  = (const float*)d_in[0];
    const float* evy  = (const float*)d_in[1];
    const float* exv  = (const float*)d_in[2];
    const float* eyv  = (const float*)d_in[3];
    const float* cif  = (const float*)d_in[4];
    const float* W_in = (const float*)d_in[5];
    const float* b_in = (const float*)d_in[6];
    const float* W_out= (const float*)d_in[7];
    const float* b_out= (const float*)d_in[8];
    const float* g_at = (const float*)d_in[9];
    const float* b_at = (const float*)d_in[10];
    const float* Wi1  = (const float*)d_in[11];
    const float* bi1  = (const float*)d_in[12];
    const float* Wi2  = (const float*)d_in[13];
    const float* bi2  = (const float*)d_in[14];
    const float* gi   = (const float*)d_in[15];
    const float* bni  = (const float*)d_in[16];
    const float* Wc1  = (const float*)d_in[17];
    const float* bc1  = (const float*)d_in[18];
    const float* Wc2  = (const float*)d_in[19];
    const float* bc2  = (const float*)d_in[20];
    const float* gc   = (const float*)d_in[21];
    const float* bnc  = (const float*)d_in[22];
    const float* Wm   = (const float*)d_in[23];
    const float* bm   = (const float*)d_in[24];
    const float* gm   = (const float*)d_in[25];
    const float* bnm  = (const float*)d_in[26];
    const float* Wk1  = (const float*)d_in[27];
    const float* bk1  = (const float*)d_in[28];
    const float* Wk2  = (const float*)d_in[29];
    const float* bk2  = (const float*)d_in[30];
    float* out = (float*)d_out;

    const int LIN_SMEM = (128 * 68 + 64 * 68) * 4;        // 52224
    const int ATT_SMEM = (64 * 68 + 64 * 196) * 4;        // 67584
    cudaFuncSetAttribute(k_lin_mma,    cudaFuncAttributeMaxDynamicSharedMemorySize, LIN_SMEM);
    cudaFuncSetAttribute(k_inter_mma,  cudaFuncAttributeMaxDynamicSharedMemorySize, LIN_SMEM);
    cudaFuncSetAttribute(k_attn_fused, cudaFuncAttributeMaxDynamicSharedMemorySize, ATT_SMEM);

    // 1) full attention block -> g_pooled
    k_attn_fused<<<NN / 16, 128, ATT_SMEM>>>(evx, evy, exv, eyv, W_in, b_in,
                                             W_out, b_out, g_at, b_at);
    // 2) interaction hidden -> g_h1
    k_inter_mma<<<dim3(NN / 128, 2), 128, LIN_SMEM>>>(evx, evy, exv, eyv, Wi1, bi1);
    // 3) Wi2 + LN -> g_iemb
    k_lin_mma<<<NN / 128, 128, LIN_SMEM>>>(SRC_H1, 128, Wi2, bi2, gi, bni, DST_IEMB, 0);
    // 4) ci stage1 -> g_ci1
    k_ci1<<<NN / 16, 256>>>(cif, Wc1, bc1);
    // 5) Wc2 + LN -> g_cemb
    k_lin_mma<<<NN / 128, 128, LIN_SMEM>>>(SRC_CI1, 64, Wc2, bc2, gc, bnc, DST_CEMB, 0);
    // 6) merge + LN + GELU -> g_merged
    k_lin_mma<<<NN / 128, 128, LIN_SMEM>>>(SRC_MERGE, 192, Wm, bm, gm, bnm, DST_MERGED, 1);
    // 7) classifier -> out
    k_cls<<<NN / 64, 256>>>(Wk1, bk1, Wk2, bk2, out);

    (void)in_sizes; (void)n_in; (void)out_size;
}

// round 13
// speedup vs baseline: 2.4314x; 1.0337x over previous
#include <cuda_runtime.h>
#include <math.h>

#define NN 131072

// ---------------- scratch (static device arrays; no allocations) ----------------
__device__ __align__(16) float g_pooled[NN * 64];      // attention-block output
__device__ __align__(16) float g_h1[NN * 128];         // interaction hidden

__device__ __forceinline__ float gelu_f(float x) {
    return 0.5f * x * (1.0f + erff(x * 0.70710678118654752f));
}
__device__ __forceinline__ float to_tf32(float x) {
    unsigned r;
    asm("cvt.rna.tf32.f32 %0, %1;" : "=r"(r) : "f"(x));
    return __uint_as_float(r);
}
__device__ __forceinline__ float4 tf32x4(float4 v) {
    v.x = to_tf32(v.x); v.y = to_tf32(v.y); v.z = to_tf32(v.z); v.w = to_tf32(v.w);
    return v;
}
// D(16x8) += A(16x8,row) * B(8x8,col) in tf32, fp32 accum
__device__ __forceinline__ void mma8(float* c, const unsigned* a, const unsigned* b) {
    asm("mma.sync.aligned.m16n8k8.row.col.f32.tf32.tf32.f32 "
        "{%0,%1,%2,%3}, {%4,%5,%6,%7}, {%8,%9}, {%0,%1,%2,%3};"
        : "+f"(c[0]), "+f"(c[1]), "+f"(c[2]), "+f"(c[3])
        : "r"(a[0]), "r"(a[1]), "r"(a[2]), "r"(a[3]), "r"(b[0]), "r"(b[1]));
}

extern __shared__ float dsm[];

// ---- shared helpers for 16-rows-per-warp mma stages (tail + attention) ----
// A,W are stride-68 smem regions holding tf32 bit patterns.
__device__ __forceinline__ void mma_stage16(const float* sA, const float* sW,
                                            float acc[8][4], int R, int g, int t) {
#pragma unroll
    for (int k8 = 0; k8 < 8; k8++) {
        int kb = k8 * 8;
        unsigned a[4], bb[8][2];
        a[0] = __float_as_uint(sA[(R + g) * 68 + kb + t]);
        a[1] = __float_as_uint(sA[(R + g + 8) * 68 + kb + t]);
        a[2] = __float_as_uint(sA[(R + g) * 68 + kb + t + 4]);
        a[3] = __float_as_uint(sA[(R + g + 8) * 68 + kb + t + 4]);
#pragma unroll
        for (int n = 0; n < 8; n++) {
            bb[n][0] = __float_as_uint(sW[(n * 8 + g) * 68 + kb + t]);
            bb[n][1] = __float_as_uint(sW[(n * 8 + g) * 68 + kb + t + 4]);
        }
#pragma unroll
        for (int n = 0; n < 8; n++) mma8(acc[n], a, bb[n]);
    }
}
// scatter acc (+bias from gmem) into stride-68 region rows (R+g),(R+g+8)
__device__ __forceinline__ void scatter16(float* dst, const float acc[8][4],
                                          const float* __restrict__ bias,
                                          int R, int g, int t) {
#pragma unroll
    for (int n = 0; n < 8; n++) {
        int col = n * 8 + 2 * t;
        float b0 = __ldg(bias + col);
        float b1 = __ldg(bias + col + 1);
        *(float2*)(dst + (R + g) * 68 + col) = make_float2(acc[n][0] + b0, acc[n][1] + b1);
        *(float2*)(dst + (R + g + 8) * 68 + col) = make_float2(acc[n][2] + b0, acc[n][3] + b1);
    }
}
// LayerNorm over 64 rows of a stride-68 region, 2 threads/row, optional GELU, tf32 store
__device__ __forceinline__ void ln64(float* buf, const float* __restrict__ gamma,
                                     const float* __restrict__ beta, int tid,
                                     int doGelu, int cvt) {
    int r = tid >> 1, c0 = (tid & 1) * 32;
    float4 cv[8];
#pragma unroll
    for (int q = 0; q < 8; q++) cv[q] = *(float4*)(buf + r * 68 + c0 + q * 4);
    float s1 = 0.0f, s2 = 0.0f;
#pragma unroll
    for (int q = 0; q < 8; q++) {
        s1 += cv[q].x + cv[q].y + cv[q].z + cv[q].w;
        s2 += cv[q].x * cv[q].x + cv[q].y * cv[q].y + cv[q].z * cv[q].z + cv[q].w * cv[q].w;
    }
    s1 += __shfl_xor_sync(0xffffffffu, s1, 1, 2);
    s2 += __shfl_xor_sync(0xffffffffu, s2, 1, 2);
    float mean = s1 * (1.0f / 64.0f);
    float var = s2 * (1.0f / 64.0f) - mean * mean;
    float rstd = rsqrtf(var + 1e-5f);
#pragma unroll
    for (int q = 0; q < 8; q++) {
        int c = c0 + q * 4;
        float4 gq = *(const float4*)(gamma + c);
        float4 eq = *(const float4*)(beta + c);
        float4 o;
        o.x = (cv[q].x - mean) * rstd * gq.x + eq.x;
        o.y = (cv[q].y - mean) * rstd * gq.y + eq.y;
        o.z = (cv[q].z - mean) * rstd * gq.z + eq.z;
        o.w = (cv[q].w - mean) * rstd * gq.w + eq.w;
        if (doGelu) { o.x = gelu_f(o.x); o.y = gelu_f(o.y); o.z = gelu_f(o.z); o.w = gelu_f(o.w); }
        if (cvt) o = tf32x4(o);
        *(float4*)(buf + r * 68 + c) = o;
    }
}

// =====================================================================
// k_front: grid-partitioned attention (8192 blocks) + interaction (2048).
// bx % 5 == 0 -> inter block bx/5 ; else attention block bx - bx/5 - 1.
// attention smem: sW 64x68 | sQKV 64x196 (67584 B)
// inter smem:     sA 128x68 | sW 64x68   (52224 B)
// =====================================================================
__global__ void __launch_bounds__(128, 3)
k_front(const float* __restrict__ evx, const float* __restrict__ evy,
        const float* __restrict__ exv, const float* __restrict__ eyv,
        const float* __restrict__ Win, const float* __restrict__ bin,
        const float* __restrict__ Wout, const float* __restrict__ bout,
        const float* __restrict__ g_at, const float* __restrict__ b_at,
        const float* __restrict__ Wi1, const float* __restrict__ bi1)
{
    const int bx = blockIdx.x;
    const int tid = threadIdx.x;
    const int lane = tid & 31, wp = tid >> 5;
    const int g = lane >> 2, t = lane & 3;

    if (bx % 5 != 0) {
        // ================= attention branch =================
        float* sW = dsm;                // 64*68
        float* sQKV = dsm + 64 * 68;    // 64*196
        const int ab = bx - bx / 5 - 1;
        const int node0 = ab * 16;
        const int R = wp * 16;

        // preload A fragments (tf32 edges) from gmem
        float af[8][4];
        {
            int r0 = R + g, r1 = R + g + 8;
            const float* base0 = ((r0 & 3) == 0) ? evx : ((r0 & 3) == 1) ? evy
                               : ((r0 & 3) == 2) ? exv : eyv;
            const float* base1 = ((r1 & 3) == 0) ? evx : ((r1 & 3) == 1) ? evy
                               : ((r1 & 3) == 2) ? exv : eyv;
            const float* p0 = base0 + (size_t)(node0 + (r0 >> 2)) * 64;
            const float* p1 = base1 + (size_t)(node0 + (r1 >> 2)) * 64;
#pragma unroll
            for (int k8 = 0; k8 < 8; k8++) {
                int kb = k8 * 8;
                af[k8][0] = to_tf32(__ldg(p0 + kb + t));
                af[k8][1] = to_tf32(__ldg(p1 + kb + t));
                af[k8][2] = to_tf32(__ldg(p0 + kb + t + 4));
                af[k8][3] = to_tf32(__ldg(p1 + kb + t + 4));
            }
        }

        // QKV: 3 chunks of W_in
#pragma unroll 1
        for (int wc = 0; wc < 3; wc++) {
            __syncthreads();
            for (int i4 = tid; i4 < 64 * 16; i4 += 128) {
                int c = i4 >> 4, k4 = i4 & 15;
                *(float4*)(sW + c * 68 + k4 * 4) =
                    tf32x4(*(const float4*)(Win + (size_t)(wc * 64 + c) * 64 + k4 * 4));
            }
            __syncthreads();

            float acc[8][4];
#pragma unroll
            for (int n = 0; n < 8; n++)
#pragma unroll
                for (int i = 0; i < 4; i++) acc[n][i] = 0.0f;
#pragma unroll
            for (int k8 = 0; k8 < 8; k8++) {
                int kb = k8 * 8;
                unsigned bb[8][2];
#pragma unroll
                for (int n = 0; n < 8; n++) {
                    bb[n][0] = __float_as_uint(sW[(n * 8 + g) * 68 + kb + t]);
                    bb[n][1] = __float_as_uint(sW[(n * 8 + g) * 68 + kb + t + 4]);
                }
                const unsigned* a = (const unsigned*)af[k8];
#pragma unroll
                for (int n = 0; n < 8; n++) mma8(acc[n], a, bb[n]);
            }
            int cbase = (wc < 2) ? wc * 64 : 128;
#pragma unroll
            for (int n = 0; n < 8; n++) {
                int col = n * 8 + 2 * t;
                float b0 = __ldg(bin + wc * 64 + col);
                float b1 = __ldg(bin + wc * 64 + col + 1);
                *(float2*)(sQKV + (R + g) * 196 + cbase + col) =
                    make_float2(acc[n][0] + b0, acc[n][1] + b1);
                *(float2*)(sQKV + (R + g + 8) * 196 + cbase + col) =
                    make_float2(acc[n][2] + b0, acc[n][3] + b1);
            }
        }
        __syncthreads();

        // attention: 128 threads, thread = (node nl, query qs, head-pair hp)
        {
            int nl = tid >> 3, qs = (tid >> 1) & 3, hp = tid & 1;
            float* qrow = sQKV + (nl * 4 + qs) * 196;
            float p[4][2];
#pragma unroll
            for (int ks = 0; ks < 4; ks++) {
                const float* krow = sQKV + (nl * 4 + ks) * 196 + 64;
#pragma unroll
                for (int hh = 0; hh < 2; hh++) {
                    int h = hp * 2 + hh;
                    float d = 0.0f;
#pragma unroll
                    for (int e4 = 0; e4 < 4; e4++) {
                        float4 qv = *(const float4*)(qrow + h * 16 + e4 * 4);
                        float4 kv = *(const float4*)(krow + h * 16 + e4 * 4);
                        d += qv.x * kv.x + qv.y * kv.y + qv.z * kv.z + qv.w * kv.w;
                    }
                    p[ks][hh] = d * 0.25f;
                }
            }
#pragma unroll
            for (int hh = 0; hh < 2; hh++) {
                float m = fmaxf(fmaxf(p[0][hh], p[1][hh]), fmaxf(p[2][hh], p[3][hh]));
                float s = 0.0f;
#pragma unroll
                for (int ks = 0; ks < 4; ks++) { p[ks][hh] = expf(p[ks][hh] - m); s += p[ks][hh]; }
                float inv = 1.0f / s;
#pragma unroll
                for (int ks = 0; ks < 4; ks++) p[ks][hh] *= inv;
            }
#pragma unroll
            for (int e = 0; e < 8; e++) {
                int e4 = hp * 8 + e;
                int hh = e >> 2;
                float4 o = {0.0f, 0.0f, 0.0f, 0.0f};
#pragma unroll
                for (int ks = 0; ks < 4; ks++) {
                    float4 v = *(const float4*)(sQKV + (nl * 4 + ks) * 196 + 128 + e4 * 4);
                    float pk = p[ks][hh];
                    o.x += pk * v.x; o.y += pk * v.y; o.z += pk * v.z; o.w += pk * v.w;
                }
                *(float4*)(qrow + e4 * 4) = o;
            }
        }
        __syncthreads();

        // out-proj GEMM: A = ao (cols 0..63, cvt on load), B = Wout
        for (int i4 = tid; i4 < 64 * 16; i4 += 128) {
            int c = i4 >> 4, k4 = i4 & 15;
            *(float4*)(sW + c * 68 + k4 * 4) =
                tf32x4(*(const float4*)(Wout + (size_t)c * 64 + k4 * 4));
        }
        __syncthreads();
        {
            float acc[8][4];
#pragma unroll
            for (int n = 0; n < 8; n++)
#pragma unroll
                for (int i = 0; i < 4; i++) acc[n][i] = 0.0f;
#pragma unroll
            for (int k8 = 0; k8 < 8; k8++) {
                int kb = k8 * 8;
                unsigned a[4], bb[8][2];
                a[0] = __float_as_uint(to_tf32(sQKV[(R + g) * 196 + kb + t]));
                a[1] = __float_as_uint(to_tf32(sQKV[(R + g + 8) * 196 + kb + t]));
                a[2] = __float_as_uint(to_tf32(sQKV[(R + g) * 196 + kb + t + 4]));
                a[3] = __float_as_uint(to_tf32(sQKV[(R + g + 8) * 196 + kb + t + 4]));
#pragma unroll
                for (int n = 0; n < 8; n++) {
                    bb[n][0] = __float_as_uint(sW[(n * 8 + g) * 68 + kb + t]);
                    bb[n][1] = __float_as_uint(sW[(n * 8 + g) * 68 + kb + t + 4]);
                }
#pragma unroll
                for (int n = 0; n < 8; n++) mma8(acc[n], a, bb[n]);
            }
#pragma unroll
            for (int n = 0; n < 8; n++) {
                int col = n * 8 + 2 * t;
                *(float2*)(sQKV + (R + g) * 196 + 64 + col) = make_float2(acc[n][0], acc[n][1]);
                *(float2*)(sQKV + (R + g + 8) * 196 + 64 + col) = make_float2(acc[n][2], acc[n][3]);
            }
        }
        __syncthreads();

        // epilogue in registers: +bout +edge residual -> LN -> butterfly pooled mean
        {
            int r = tid >> 1, ch = tid & 1;
            int c0 = ch * 32;
            int node = node0 + (r >> 2), s = r & 3;
            const float* ebase = ((s == 0) ? evx : (s == 1) ? evy : (s == 2) ? exv : eyv)
                                 + (size_t)node * 64;
            float4 cv[8];
#pragma unroll
            for (int q = 0; q < 8; q++) {
                int c = c0 + q * 4;
                float4 v = *(float4*)(sQKV + r * 196 + 64 + c);
                float4 e = *(const float4*)(ebase + c);
                float4 bq = *(const float4*)(bout + c);
                v.x += bq.x + e.x; v.y += bq.y + e.y;
                v.z += bq.z + e.z; v.w += bq.w + e.w;
                cv[q] = v;
            }
            float s1 = 0.0f, s2 = 0.0f;
#pragma unroll
            for (int q = 0; q < 8; q++) {
                s1 += cv[q].x + cv[q].y + cv[q].z + cv[q].w;
                s2 += cv[q].x * cv[q].x + cv[q].y * cv[q].y + cv[q].z * cv[q].z + cv[q].w * cv[q].w;
            }
            s1 += __shfl_xor_sync(0xffffffffu, s1, 1, 2);
            s2 += __shfl_xor_sync(0xffffffffu, s2, 1, 2);
            float mean = s1 * (1.0f / 64.0f);
            float var = s2 * (1.0f / 64.0f) - mean * mean;
            float rstd = rsqrtf(var + 1e-5f);
            float4 yv[8];
#pragma unroll
            for (int q = 0; q < 8; q++) {
                int c = c0 + q * 4;
                float4 gq = *(const float4*)(g_at + c);
                float4 eq = *(const float4*)(b_at + c);
                yv[q].x = (cv[q].x - mean) * rstd * gq.x + eq.x;
                yv[q].y = (cv[q].y - mean) * rstd * gq.y + eq.y;
                yv[q].z = (cv[q].z - mean) * rstd * gq.z + eq.z;
                yv[q].w = (cv[q].w - mean) * rstd * gq.w + eq.w;
            }
            // butterfly mean over the 4 query slots (threads 8nl..8nl+7; xor 2, xor 4)
#pragma unroll
            for (int q = 0; q < 8; q++) {
                yv[q].x += __shfl_xor_sync(0xffffffffu, yv[q].x, 2, 8);
                yv[q].y += __shfl_xor_sync(0xffffffffu, yv[q].y, 2, 8);
                yv[q].z += __shfl_xor_sync(0xffffffffu, yv[q].z, 2, 8);
                yv[q].w += __shfl_xor_sync(0xffffffffu, yv[q].w, 2, 8);
                yv[q].x += __shfl_xor_sync(0xffffffffu, yv[q].x, 4, 8);
                yv[q].y += __shfl_xor_sync(0xffffffffu, yv[q].y, 4, 8);
                yv[q].z += __shfl_xor_sync(0xffffffffu, yv[q].z, 4, 8);
                yv[q].w += __shfl_xor_sync(0xffffffffu, yv[q].w, 4, 8);
            }
            if ((tid & 6) == 0) {   // qs == 0: 2 writers per node (ch 0,1)
                int nl = tid >> 3;
#pragma unroll
                for (int q = 0; q < 8; q++) {
                    float4 o;
                    o.x = 0.25f * yv[q].x; o.y = 0.25f * yv[q].y;
                    o.z = 0.25f * yv[q].z; o.w = 0.25f * yv[q].w;
                    *(float4*)(g_pooled + (size_t)(node0 + nl) * 64 + c0 + q * 4) = o;
                }
            }
        }
    } else {
        // ================= interaction branch =================
        float* sA = dsm;              // 128*68
        float* sW = dsm + 128 * 68;   // 64*68
        const int ib = bx / 5;
        const int n0 = (ib & 1023) * 128;
        const int c0 = (ib >> 10) * 64;

        float acc[2][8][4];
#pragma unroll
        for (int m = 0; m < 2; m++)
#pragma unroll
            for (int n = 0; n < 8; n++)
#pragma unroll
                for (int i = 0; i < 4; i++) acc[m][n][i] = 0.0f;

#pragma unroll 1
        for (int p = 0; p < 6; p++) {
            const float* Ea; const float* Eb;
            switch (p) {
                case 0: Ea = evx; Eb = evy; break;
                case 1: Ea = evx; Eb = exv; break;
                case 2: Ea = evx; Eb = eyv; break;
                case 3: Ea = evy; Eb = exv; break;
                case 4: Ea = evy; Eb = eyv; break;
                default: Ea = exv; Eb = eyv; break;
            }
            __syncthreads();
            for (int i4 = tid; i4 < 128 * 16; i4 += 128) {
                int r = i4 >> 4, k4 = i4 & 15;
                float4 x = ((const float4*)(Ea + (size_t)(n0 + r) * 64))[k4];
                float4 y = ((const float4*)(Eb + (size_t)(n0 + r) * 64))[k4];
                float4 v; v.x = x.x * y.x; v.y = x.y * y.y; v.z = x.z * y.z; v.w = x.w * y.w;
                *(float4*)(sA + r * 68 + k4 * 4) = tf32x4(v);
            }
            for (int i4 = tid; i4 < 64 * 16; i4 += 128) {
                int c = i4 >> 4, k4 = i4 & 15;
                *(float4*)(sW + c * 68 + k4 * 4) =
                    tf32x4(*(const float4*)(Wi1 + (size_t)(c0 + c) * 384 + p * 64 + k4 * 4));
            }
            __syncthreads();
#pragma unroll
            for (int k8 = 0; k8 < 8; k8++) {
                int kb = k8 * 8;
                unsigned a[2][4], bb[8][2];
#pragma unroll
                for (int m = 0; m < 2; m++) {
                    int R = wp * 32 + m * 16;
                    a[m][0] = __float_as_uint(sA[(R + g) * 68 + kb + t]);
                    a[m][1] = __float_as_uint(sA[(R + g + 8) * 68 + kb + t]);
                    a[m][2] = __float_as_uint(sA[(R + g) * 68 + kb + t + 4]);
                    a[m][3] = __float_as_uint(sA[(R + g + 8) * 68 + kb + t + 4]);
                }
#pragma unroll
                for (int n = 0; n < 8; n++) {
                    bb[n][0] = __float_as_uint(sW[(n * 8 + g) * 68 + kb + t]);
                    bb[n][1] = __float_as_uint(sW[(n * 8 + g) * 68 + kb + t + 4]);
                }
#pragma unroll
                for (int m = 0; m < 2; m++)
#pragma unroll
                    for (int n = 0; n < 8; n++) mma8(acc[m][n], a[m], bb[n]);
            }
        }

        // epilogue: +bias, GELU, write g_h1 (via register scatter through smem)
#pragma unroll
        for (int m = 0; m < 2; m++)
#pragma unroll
            for (int n = 0; n < 8; n++) {
                int R = wp * 32 + m * 16;
                *(float2*)(sA + (R + g) * 68 + n * 8 + 2 * t) = make_float2(acc[m][n][0], acc[m][n][1]);
                *(float2*)(sA + (R + g + 8) * 68 + n * 8 + 2 * t) = make_float2(acc[m][n][2], acc[m][n][3]);
            }
        __syncthreads();
        {
            int row = n0 + tid;
#pragma unroll
            for (int k4 = 0; k4 < 16; k4++) {
                float4 c = *(float4*)(sA + tid * 68 + k4 * 4);
                float4 bq = *(const float4*)(bi1 + c0 + k4 * 4);
                float4 o;
                o.x = gelu_f(c.x + bq.x);
                o.y = gelu_f(c.y + bq.y);
                o.z = gelu_f(c.z + bq.z);
                o.w = gelu_f(c.w + bq.w);
                *(float4*)(g_h1 + (size_t)row * 128 + c0 + k4 * 4) = o;
            }
        }
    }
}

// =====================================================================
// k_tail: 64 nodes/block, 128 threads, 3 CTAs/SM.
// ci1 -> Wc2+LN(cemb) -> Wi2+LN(iemb) -> merge+LN+GELU -> Wk1+GELU -> Wk2 -> out
// dyn smem: sA | sW | sIem | sCem, each 64x68  (69632 B)
// =====================================================================
__global__ void __launch_bounds__(128, 3)
k_tail(const float* __restrict__ cif,
       const float* __restrict__ Wc1, const float* __restrict__ bc1,
       const float* __restrict__ Wc2, const float* __restrict__ bc2,
       const float* __restrict__ gc, const float* __restrict__ bnc,
       const float* __restrict__ Wi2, const float* __restrict__ bi2,
       const float* __restrict__ gi, const float* __restrict__ bni,
       const float* __restrict__ Wm, const float* __restrict__ bm,
       const float* __restrict__ gm, const float* __restrict__ bnm,
       const float* __restrict__ Wk1, const float* __restrict__ bk1,
       const float* __restrict__ Wk2, const float* __restrict__ bk2,
       float* __restrict__ out)
{
    float* sA = dsm;                // 64*68
    float* sW = sA + 64 * 68;       // 64*68
    float* sIem = sW + 64 * 68;     // 64*68
    float* sCem = sIem + 64 * 68;   // 64*68
    const int tid = threadIdx.x;
    const int lane = tid & 31, wp = tid >> 5;
    const int g = lane >> 2, t = lane & 3;
    const int n0 = blockIdx.x * 64;
    const int R = wp * 16;
    float acc[8][4];

    // ---- S1: ci hidden = gelu(ci @ Wc1^T + bc1) -> sA (tf32) ----
    for (int i = tid; i < 640; i += 128) sW[i] = Wc1[i];          // Wc1 64x10
    if (tid < 64) sW[640 + tid] = bc1[tid];
    for (int i = tid; i < 640; i += 128) {                        // ci rows 64x10 -> sIem
        int r = i / 10, k = i - r * 10;
        sIem[r * 12 + k] = cif[(size_t)(n0 + r) * 10 + k];
    }
    __syncthreads();
    for (int o = tid; o < 4096; o += 128) {
        int nl = o >> 6, c = o & 63;
        float a = sW[640 + c];
#pragma unroll
        for (int k = 0; k < 10; k++) a += sIem[nl * 12 + k] * sW[c * 10 + k];
        sA[nl * 68 + c] = to_tf32(gelu_f(a));
    }
    __syncthreads();

    // ---- S2: cemb = LN(sA @ Wc2^T + bc2) -> sCem (tf32) ----
    for (int i4 = tid; i4 < 64 * 16; i4 += 128) {
        int c = i4 >> 4, k4 = i4 & 15;
        *(float4*)(sW + c * 68 + k4 * 4) = tf32x4(*(const float4*)(Wc2 + (size_t)c * 64 + k4 * 4));
    }
    __syncthreads();
#pragma unroll
    for (int n = 0; n < 8; n++)
#pragma unroll
        for (int i = 0; i < 4; i++) acc[n][i] = 0.0f;
    mma_stage16(sA, sW, acc, R, g, t);
    scatter16(sCem, acc, bc2, R, g, t);
    __syncthreads();
    ln64(sCem, gc, bnc, tid, 0, 1);
    __syncthreads();

    // ---- S3: iemb = LN(h1 @ Wi2^T + bi2) -> sIem (tf32), K=128 in 2 chunks ----
#pragma unroll
    for (int n = 0; n < 8; n++)
#pragma unroll
        for (int i = 0; i < 4; i++) acc[n][i] = 0.0f;
#pragma unroll 1
    for (int kc = 0; kc < 128; kc += 64) {
        for (int i4 = tid; i4 < 64 * 16; i4 += 128) {
            int r = i4 >> 4, k4 = i4 & 15;
            *(float4*)(sA + r * 68 + k4 * 4) =
                tf32x4(*(const float4*)(g_h1 + (size_t)(n0 + r) * 128 + kc + k4 * 4));
        }
        for (int i4 = tid; i4 < 64 * 16; i4 += 128) {
            int c = i4 >> 4, k4 = i4 & 15;
            *(float4*)(sW + c * 68 + k4 * 4) =
                tf32x4(*(const float4*)(Wi2 + (size_t)c * 128 + kc + k4 * 4));
        }
        __syncthreads();
        mma_stage16(sA, sW, acc, R, g, t);
        __syncthreads();
    }
    scatter16(sIem, acc, bi2, R, g, t);
    __syncthreads();
    ln64(sIem, gi, bni, tid, 0, 1);
    __syncthreads();

    // ---- S4: merged = GELU(LN([pooled|iemb|cemb] @ Wm^T + bm)) -> sA (tf32) ----
#pragma unroll
    for (int n = 0; n < 8; n++)
#pragma unroll
        for (int i = 0; i < 4; i++) acc[n][i] = 0.0f;
    // chunk0: pooled
    for (int i4 = tid; i4 < 64 * 16; i4 += 128) {
        int r = i4 >> 4, k4 = i4 & 15;
        *(float4*)(sA + r * 68 + k4 * 4) =
            tf32x4(*(const float4*)(g_pooled + (size_t)(n0 + r) * 64 + k4 * 4));
    }
    for (int i4 = tid; i4 < 64 * 16; i4 += 128) {
        int c = i4 >> 4, k4 = i4 & 15;
        *(float4*)(sW + c * 68 + k4 * 4) = tf32x4(*(const float4*)(Wm + (size_t)c * 192 + k4 * 4));
    }
    __syncthreads();
    mma_stage16(sA, sW, acc, R, g, t);
    __syncthreads();
    // chunk1: iemb (in place)
    for (int i4 = tid; i4 < 64 * 16; i4 += 128) {
        int c = i4 >> 4, k4 = i4 & 15;
        *(float4*)(sW + c * 68 + k4 * 4) =
            tf32x4(*(const float4*)(Wm + (size_t)c * 192 + 64 + k4 * 4));
    }
    __syncthreads();
    mma_stage16(sIem, sW, acc, R, g, t);
    __syncthreads();
    // chunk2: cemb (in place)
    for (int i4 = tid; i4 < 64 * 16; i4 += 128) {
        int c = i4 >> 4, k4 = i4 & 15;
        *(float4*)(sW + c * 68 + k4 * 4) =
            tf32x4(*(const float4*)(Wm + (size_t)c * 192 + 128 + k4 * 4));
    }
    __syncthreads();
    mma_stage16(sCem, sW, acc, R, g, t);
    scatter16(sA, acc, bm, R, g, t);
    __syncthreads();
    ln64(sA, gm, bnm, tid, 1, 1);
    __syncthreads();

    // ---- S5: hidden = GELU(merged @ Wk1^T + bk1) -> sCem (fp32) ----
    for (int i4 = tid; i4 < 64 * 16; i4 += 128) {
        int c = i4 >> 4, k4 = i4 & 15;
        *(float4*)(sW + c * 68 + k4 * 4) = tf32x4(*(const float4*)(Wk1 + (size_t)c * 64 + k4 * 4));
    }
    __syncthreads();
#pragma unroll
    for (int n = 0; n < 8; n++)
#pragma unroll
        for (int i = 0; i < 4; i++) acc[n][i] = 0.0f;
    mma_stage16(sA, sW, acc, R, g, t);
#pragma unroll
    for (int n = 0; n < 8; n++) {
        int col = n * 8 + 2 * t;
        float b0 = __ldg(bk1 + col);
        float b1 = __ldg(bk1 + col + 1);
        *(float2*)(sCem + (R + g) * 68 + col) =
            make_float2(gelu_f(acc[n][0] + b0), gelu_f(acc[n][1] + b1));
        *(float2*)(sCem + (R + g + 8) * 68 + col) =
            make_float2(gelu_f(acc[n][2] + b0), gelu_f(acc[n][3] + b1));
    }
    __syncthreads();

    // ---- S6: out = hidden @ Wk2^T + bk2 (scalar fp32) ----
    for (int i = tid; i < 512; i += 128) {          // Wk2 8x64, stride 68
        int c = i >> 6, k = i & 63;
        sW[c * 68 + k] = Wk2[i];
    }
    if (tid < 8) sW[8 * 68 + tid] = bk2[tid];
    __syncthreads();
    for (int o = tid; o < 512; o += 128) {
        int nl = o >> 3, oc = o & 7;
        float a = sW[8 * 68 + oc];
#pragma unroll 8
        for (int k = 0; k < 64; k++) a += sCem[nl * 68 + k] * sW[oc * 68 + k];
        out[(size_t)(n0 + nl) * 8 + oc] = a;
    }
}

// =====================================================================
extern "C" void kernel_launch(void* const* d_in, const int* in_sizes, int n_in,
                              void* d_out, int out_size)
{
    const float* evx  = (const float*)d_in[0];
    const float* evy  = (const float*)d_in[1];
    const float* exv  = (const float*)d_in[2];
    const float* eyv  = (const float*)d_in[3];
    const float* cif  = (const float*)d_in[4];
    const float* W_in = (const float*)d_in[5];
    const float* b_in = (const float*)d_in[6];
    const float* W_out= (const float*)d_in[7];
    const float* b_out= (const float*)d_in[8];
    const float* g_at = (const float*)d_in[9];
    const float* b_at = (const float*)d_in[10];
    const float* Wi1  = (const float*)d_in[11];
    const float* bi1  = (const float*)d_in[12];
    const float* Wi2  = (const float*)d_in[13];
    const float* bi2  = (const float*)d_in[14];
    const float* gi   = (const float*)d_in[15];
    const float* bni  = (const float*)d_in[16];
    const float* Wc1  = (const float*)d_in[17];
    const float* bc1  = (const float*)d_in[18];
    const float* Wc2  = (const float*)d_in[19];
    const float* bc2  = (const float*)d_in[20];
    const float* gc   = (const float*)d_in[21];
    const float* bnc  = (const float*)d_in[22];
    const float* Wm   = (const float*)d_in[23];
    const float* bm   = (const float*)d_in[24];
    const float* gm   = (const float*)d_in[25];
    const float* bnm  = (const float*)d_in[26];
    const float* Wk1  = (const float*)d_in[27];
    const float* bk1  = (const float*)d_in[28];
    const float* Wk2  = (const float*)d_in[29];
    const float* bk2  = (const float*)d_in[30];
    float* out = (float*)d_out;

    const int FRONT_SMEM = (64 * 68 + 64 * 196) * 4;   // 67584
    const int TAIL_SMEM  = 4 * 64 * 68 * 4;            // 69632
    cudaFuncSetAttribute(k_front, cudaFuncAttributeMaxDynamicSharedMemorySize, FRONT_SMEM);
    cudaFuncSetAttribute(k_tail,  cudaFuncAttributeMaxDynamicSharedMemorySize, TAIL_SMEM);

    // 1) attention (8192 blocks) + interaction (2048 blocks), interleaved 4:1
    k_front<<<10240, 128, FRONT_SMEM>>>(evx, evy, exv, eyv, W_in, b_in,
                                        W_out, b_out, g_at, b_at, Wi1, bi1);
    // 2) everything after: ci/Wc2/Wi2/merge/classifier
    k_tail<<<NN / 64, 128, TAIL_SMEM>>>(cif, Wc1, bc1, Wc2, bc2, gc, bnc,
                                        Wi2, bi2, gi, bni, Wm, bm, gm, bnm,
                                        Wk1, bk1, Wk2, bk2, out);

    (void)in_sizes; (void)n_in; (void)out_size;
}